// round 12
// baseline (speedup 1.0000x reference)
#include <cuda_runtime.h>
#include <math.h>
#include <stdint.h>

// ----------------------------------------------------------------------------
// Problem constants
//   T=32, B=32, TB=1024, NA=5, HID=256, FEAT=512, IN_DIM=517 (pad 544), FLAT=3136
// Output layout (22528 floats): logits[1024*5] | v[1024] | hT[32*256] | cT[32*256]
// ----------------------------------------------------------------------------

#define TBn 1024
#define KPAD 544    // padded IN_DIM for tf32 GEMM (multiple of 32)

// Scratch (device globals; no allocation allowed)
__device__ float g_x1[TBn * 32 * 20 * 20];   // conv1 out
__device__ float g_x2[TBn * 64 * 9 * 9];     // conv2 out
__device__ float g_x3[TBn * 3136];           // conv3 out (flatten, C,H,W)
__device__ float g_xs[TBn * KPAD];           // feat || one-hot || zero pad
__device__ float g_pre[TBn * 1024];          // x @ W_ih^T + b_ih + b_hh
__device__ float g_whhT[256 * 1024];         // W_hh transposed: [k][4*HID]
__device__ float g_wihp[1024 * KPAD];        // W_ih zero-padded to KPAD
__device__ float g_bsum[1024];               // b_ih + b_hh
__device__ float g_wp1T[256 * 64];           // Wp1 transposed [k][64]
__device__ float g_wv1T[256 * 64];           // Wv1 transposed [k][64]
__device__ float g_hs[TBn * 256];            // all h outputs
// im2col LUTs: value = img_s[lutk[k] + lutn[n]]
__device__ int g_lutk1[192], g_lutn1[400];
__device__ int g_lutk2[512], g_lutn2[81];
__device__ int g_lutk3[576], g_lutn3[49];

__device__ __forceinline__ float sigmoidf(float x) { return 1.0f / (1.0f + expf(-x)); }

__device__ __forceinline__ unsigned f2tf(float f) {
    unsigned u;
    asm("cvt.rna.tf32.f32 %0, %1;" : "=r"(u) : "f"(f));
    return u;
}

// ---- cluster / DSMEM helpers ----
__device__ __forceinline__ uint32_t smem_u32(const void* p) {
    uint32_t a;
    asm("{ .reg .u64 t; cvta.to.shared.u64 t, %1; cvt.u32.u64 %0, t; }"
        : "=r"(a) : "l"(p));
    return a;
}
__device__ __forceinline__ uint32_t mapa_rank(uint32_t saddr, uint32_t rank) {
    uint32_t r;
    asm("mapa.shared::cluster.u32 %0, %1, %2;" : "=r"(r) : "r"(saddr), "r"(rank));
    return r;
}
__device__ __forceinline__ void st_cluster_f32(uint32_t addr, float v) {
    asm volatile("st.shared::cluster.f32 [%0], %1;" :: "r"(addr), "f"(v) : "memory");
}
#define CLUSTER_SYNC() do { \
    asm volatile("barrier.cluster.arrive.aligned;" ::: "memory"); \
    asm volatile("barrier.cluster.wait.aligned;" ::: "memory"); \
} while (0)

// ----------------------------------------------------------------------------
// prep: transposes, bias sum, W_ih pad, im2col LUTs
// ----------------------------------------------------------------------------
__global__ void prep_kernel(const float* __restrict__ W_hh,
                            const float* __restrict__ b_ih,
                            const float* __restrict__ b_hh,
                            const float* __restrict__ Wp1,
                            const float* __restrict__ Wv1,
                            const float* __restrict__ W_ih) {
    int idx = blockIdx.x * blockDim.x + threadIdx.x;
    if (idx < 262144) {
        int j = idx >> 8, k = idx & 255;
        g_whhT[k * 1024 + j] = W_hh[idx];
    }
    if (idx < 16384) {
        int j = idx >> 8, k = idx & 255;
        g_wp1T[k * 64 + j] = Wp1[idx];
        g_wv1T[k * 64 + j] = Wv1[idx];
    }
    if (idx < 1024) g_bsum[idx] = b_ih[idx] + b_hh[idx];
    if (idx < 1024 * KPAD) {
        int row = idx / KPAD, col = idx % KPAD;
        g_wihp[idx] = (col < 517) ? W_ih[row * 517 + col] : 0.0f;
    }
    // conv1 LUTs: k = ic*64 + ky*8 + kx ; n = oy*20 + ox (stride 4)
    if (idx < 192) {
        int ic = idx >> 6, ky = (idx >> 3) & 7, kx = idx & 7;
        g_lutk1[idx] = ic * 7056 + ky * 84 + kx;
    }
    if (idx < 400) g_lutn1[idx] = (idx / 20) * 336 + (idx % 20) * 4;
    // conv2 LUTs: k = ic*16 + ky*4 + kx ; n = oy*9 + ox (stride 2)
    if (idx < 512) {
        int ic = idx >> 4, ky = (idx >> 2) & 3, kx = idx & 3;
        g_lutk2[idx] = ic * 400 + ky * 20 + kx;
    }
    if (idx < 81) g_lutn2[idx] = (idx / 9) * 40 + (idx % 9) * 2;
    // conv3 LUTs: k = ic*9 + ky*3 + kx ; n = oy*7 + ox (stride 1)
    if (idx < 576) {
        int ic = idx / 9, r = idx % 9;
        g_lutk3[idx] = ic * 81 + (r / 3) * 9 + (r % 3);
    }
    if (idx < 49) g_lutn3[idx] = (idx / 7) * 9 + (idx % 7);
}

// ----------------------------------------------------------------------------
// one-hot columns of xs (cols 512..516) + zero pad (517..543)
// ----------------------------------------------------------------------------
__global__ void onehot_kernel(const int* __restrict__ la) {
    int r = blockIdx.x * blockDim.x + threadIdx.x;
    if (r < TBn) {
        int a = la[r];
        float* p = g_xs + r * KPAD + 512;
#pragma unroll
        for (int j = 0; j < 5; j++) p[j] = (j == a) ? 1.0f : 0.0f;
#pragma unroll
        for (int j = 5; j < 32; j++) p[j] = 0.0f;
    }
}

// ----------------------------------------------------------------------------
// tf32 m16n8k8 mma helper
// ----------------------------------------------------------------------------
__device__ __forceinline__ void mma_tf32(float* c, const unsigned* a, const unsigned* b) {
    asm volatile(
        "mma.sync.aligned.m16n8k8.row.col.f32.tf32.tf32.f32 "
        "{%0,%1,%2,%3}, {%4,%5,%6,%7}, {%8,%9}, {%0,%1,%2,%3};\n"
        : "+f"(c[0]), "+f"(c[1]), "+f"(c[2]), "+f"(c[3])
        : "r"(a[0]), "r"(a[1]), "r"(a[2]), "r"(a[3]), "r"(b[0]), "r"(b[1]));
}

// ----------------------------------------------------------------------------
// Implicit-GEMM conv via tf32 tensor cores, 3xTF32 precision (hi/lo split).
// Per image: C[OC][NPX] = W[OC][K] * im2col[K][NPX] (+bias, relu).
// Persistent grid 148, 128 threads (4 warps). Weights fp32 in smem (whole
// kernel); B tiles gathered per 32-k chunk via LUTs, stored hi/lo tf32,
// double-buffered. WARPS_M=2 -> 64x64 C tile; WARPS_M=1 -> 32x128.
// ----------------------------------------------------------------------------
template<int OC, int NPX, int K, int IMG, int WARPS_M>
__global__ void __launch_bounds__(128, 1)
conv_mma_kernel(const float* __restrict__ W, const float* __restrict__ bias,
                const float* __restrict__ in_ext, float wscale) {
    constexpr int KS = K + 4;                      // (K+4)%32==4 -> conflict-free frags
    constexpr int BN = (WARPS_M == 2) ? 64 : 128;
    constexpr int NT = (NPX + BN - 1) / BN;
    constexpr int NCH = K / 32;
    constexpr int ELS = BN / 4;                    // B elements per thread per chunk

    const float* in = (K == 192) ? in_ext : ((K == 512) ? (const float*)g_x1 : (const float*)g_x2);
    float* out = (K == 192) ? (float*)g_x1 : ((K == 512) ? (float*)g_x2 : (float*)g_x3);
    const int* lutk = (K == 192) ? g_lutk1 : ((K == 512) ? g_lutk2 : g_lutk3);
    const int* lutn = (K == 192) ? g_lutn1 : ((K == 512) ? g_lutn2 : g_lutn3);

    extern __shared__ char smraw[];
    float* Ws = (float*)smraw;                     // OC*KS
    float* img_s = Ws + OC * KS;                   // IMG
    unsigned* Bh = (unsigned*)(img_s + IMG);       // 2*BN*36
    unsigned* Bl = Bh + 2 * BN * 36;               // 2*BN*36
    int* lutk_s = (int*)(Bl + 2 * BN * 36);        // K
    int* lutn_s = lutk_s + K;                      // NPX

    int tid = threadIdx.x, lane = tid & 31, warp = tid >> 5;
    int wm = (WARPS_M == 2) ? ((warp & 1) * 32) : 0;
    int wn = (WARPS_M == 2) ? ((warp >> 1) * 32) : (warp * 32);

    // stage weights (fp32, scaled) + LUTs once
    for (int i = tid; i < OC * K; i += 128) {
        int rr = i / K, cc = i % K;
        Ws[rr * KS + cc] = __ldg(&W[i]) * wscale;
    }
    for (int i = tid; i < K; i += 128) lutk_s[i] = __ldg(&lutk[i]);
    for (int i = tid; i < NPX; i += 128) lutn_s[i] = __ldg(&lutn[i]);
    __syncthreads();

    int gn = (BN == 128) ? tid : (tid >> 1);
    int gk0 = (BN == 128) ? 0 : ((tid & 1) * 16);

    int s = (blockIdx.x * TBn) / 148;
    int e = ((blockIdx.x + 1) * TBn) / 148;

    for (int n_img = s; n_img < e; n_img++) {
        {
            const float4* g4 = reinterpret_cast<const float4*>(in + n_img * IMG);
            float4* s4 = reinterpret_cast<float4*>(img_s);
            for (int i = tid; i < IMG / 4; i += 128) s4[i] = g4[i];
        }
        __syncthreads();

        for (int ntile = 0; ntile < NT; ntile++) {
            int nbase = ntile * BN;
            bool gvalid = (nbase + gn) < NPX;
            int noff = gvalid ? lutn_s[nbase + gn] : 0;

            float c[2][4][4];
#pragma unroll
            for (int mt = 0; mt < 2; mt++)
#pragma unroll
                for (int nt = 0; nt < 4; nt++)
#pragma unroll
                    for (int i = 0; i < 4; i++) c[mt][nt][i] = 0.0f;

            auto gather = [&](int ch, int buf) {
                unsigned* bh = Bh + buf * (BN * 36) + gn * 36 + gk0;
                unsigned* bl = Bl + buf * (BN * 36) + gn * 36 + gk0;
#pragma unroll
                for (int ii = 0; ii < ELS; ii++) {
                    int k = ch * 32 + gk0 + ii;
                    float v = gvalid ? img_s[lutk_s[k] + noff] : 0.0f;
                    unsigned h = f2tf(v);
                    unsigned l = f2tf(v - __uint_as_float(h));
                    bh[ii] = h;
                    bl[ii] = l;
                }
            };

            gather(0, 0);
            __syncthreads();

            for (int ch = 0; ch < NCH; ch++) {
                int buf = ch & 1;
                if (ch + 1 < NCH) gather(ch + 1, buf ^ 1);

                const unsigned* BhB = Bh + buf * (BN * 36);
                const unsigned* BlB = Bl + buf * (BN * 36);
                int r = lane >> 2, q = lane & 3;
#pragma unroll
                for (int ks = 0; ks < 4; ks++) {
                    int kg = ch * 32 + ks * 8;
                    unsigned ah[2][4], al[2][4];
#pragma unroll
                    for (int mt = 0; mt < 2; mt++) {
                        int mr = wm + mt * 16 + r;
                        float f0 = Ws[mr * KS + kg + q];
                        float f1 = Ws[(mr + 8) * KS + kg + q];
                        float f2 = Ws[mr * KS + kg + q + 4];
                        float f3 = Ws[(mr + 8) * KS + kg + q + 4];
                        ah[mt][0] = f2tf(f0); al[mt][0] = f2tf(f0 - __uint_as_float(ah[mt][0]));
                        ah[mt][1] = f2tf(f1); al[mt][1] = f2tf(f1 - __uint_as_float(ah[mt][1]));
                        ah[mt][2] = f2tf(f2); al[mt][2] = f2tf(f2 - __uint_as_float(ah[mt][2]));
                        ah[mt][3] = f2tf(f3); al[mt][3] = f2tf(f3 - __uint_as_float(ah[mt][3]));
                    }
                    int kc = ks * 8;
#pragma unroll
                    for (int nt = 0; nt < 4; nt++) {
                        int nr = wn + nt * 8 + r;
                        unsigned bhv[2], blv[2];
                        bhv[0] = BhB[nr * 36 + kc + q];
                        bhv[1] = BhB[nr * 36 + kc + q + 4];
                        blv[0] = BlB[nr * 36 + kc + q];
                        blv[1] = BlB[nr * 36 + kc + q + 4];
#pragma unroll
                        for (int mt = 0; mt < 2; mt++) {
                            mma_tf32(c[mt][nt], ah[mt], bhv);
                            mma_tf32(c[mt][nt], ah[mt], blv);
                            mma_tf32(c[mt][nt], al[mt], bhv);
                        }
                    }
                }
                __syncthreads();
            }

            // epilogue: bias (indexed by oc=row) + relu, guarded stores
            float* outimg = out + n_img * (OC * NPX);
#pragma unroll
            for (int mt = 0; mt < 2; mt++) {
                int row = wm + mt * 16 + (lane >> 2);
                float b0 = __ldg(&bias[row]);
                float b2 = __ldg(&bias[row + 8]);
#pragma unroll
                for (int nt = 0; nt < 4; nt++) {
                    int col = nbase + wn + nt * 8 + ((lane & 3) << 1);
                    if (col < NPX) {
                        outimg[row * NPX + col] = fmaxf(c[mt][nt][0] + b0, 0.0f);
                        outimg[(row + 8) * NPX + col] = fmaxf(c[mt][nt][2] + b2, 0.0f);
                        if (col + 1 < NPX) {
                            outimg[row * NPX + col + 1] = fmaxf(c[mt][nt][1] + b0, 0.0f);
                            outimg[(row + 8) * NPX + col + 1] = fmaxf(c[mt][nt][3] + b2, 0.0f);
                        }
                    }
                }
            }
            __syncthreads();
        }
    }
}

// ----------------------------------------------------------------------------
// tf32 tensor-core GEMM: C[M x N] = act(A[M x K] * B[N x K]^T + bias)
// ----------------------------------------------------------------------------
__device__ __forceinline__ void gemm_tf32(const float* __restrict__ A, int lda,
                                          const float* __restrict__ B, int ldb,
                                          const float* __restrict__ bias,
                                          float* __restrict__ C, int ldc,
                                          int K, bool relu) {
    __shared__ unsigned As[2][64][36];
    __shared__ unsigned Bs[2][64][36];
    int tid = threadIdx.x, lane = tid & 31, warp = tid >> 5;
    int bm = blockIdx.y * 64, bn = blockIdx.x * 64;
    int wm = (warp & 1) << 5, wn = (warp >> 1) << 5;

    float c[2][4][4];
#pragma unroll
    for (int mt = 0; mt < 2; mt++)
#pragma unroll
        for (int nt = 0; nt < 4; nt++)
#pragma unroll
            for (int i = 0; i < 4; i++) c[mt][nt][i] = 0.0f;

    int ntiles = K >> 5;
    float4 pa[4], pb[4];

#pragma unroll
    for (int i = 0; i < 4; i++) {
        int idx = tid + (i << 7);
        int row = idx >> 3, c4 = (idx & 7) << 2;
        pa[i] = *reinterpret_cast<const float4*>(A + (bm + row) * lda + c4);
        pb[i] = *reinterpret_cast<const float4*>(B + (bn + row) * ldb + c4);
    }
#pragma unroll
    for (int i = 0; i < 4; i++) {
        int idx = tid + (i << 7);
        int row = idx >> 3, c4 = (idx & 7) << 2;
        uint4 ta = {f2tf(pa[i].x), f2tf(pa[i].y), f2tf(pa[i].z), f2tf(pa[i].w)};
        uint4 tb = {f2tf(pb[i].x), f2tf(pb[i].y), f2tf(pb[i].z), f2tf(pb[i].w)};
        *reinterpret_cast<uint4*>(&As[0][row][c4]) = ta;
        *reinterpret_cast<uint4*>(&Bs[0][row][c4]) = tb;
    }
    __syncthreads();

    for (int t = 0; t < ntiles; t++) {
        int buf = t & 1;
        if (t + 1 < ntiles) {
            int k0 = (t + 1) << 5;
#pragma unroll
            for (int i = 0; i < 4; i++) {
                int idx = tid + (i << 7);
                int row = idx >> 3, c4 = (idx & 7) << 2;
                pa[i] = *reinterpret_cast<const float4*>(A + (bm + row) * lda + k0 + c4);
                pb[i] = *reinterpret_cast<const float4*>(B + (bn + row) * ldb + k0 + c4);
            }
        }
        int r = lane >> 2, q = lane & 3;
#pragma unroll
        for (int ks = 0; ks < 4; ks++) {
            unsigned a[2][4], b[4][2];
            int kc = ks << 3;
#pragma unroll
            for (int mt = 0; mt < 2; mt++) {
                int mr = wm + (mt << 4) + r;
                a[mt][0] = As[buf][mr][kc + q];
                a[mt][1] = As[buf][mr + 8][kc + q];
                a[mt][2] = As[buf][mr][kc + q + 4];
                a[mt][3] = As[buf][mr + 8][kc + q + 4];
            }
#pragma unroll
            for (int nt = 0; nt < 4; nt++) {
                int nr = wn + (nt << 3) + r;
                b[nt][0] = Bs[buf][nr][kc + q];
                b[nt][1] = Bs[buf][nr][kc + q + 4];
            }
#pragma unroll
            for (int mt = 0; mt < 2; mt++)
#pragma unroll
                for (int nt = 0; nt < 4; nt++)
                    mma_tf32(c[mt][nt], a[mt], b[nt]);
        }
        if (t + 1 < ntiles) {
            int nbuf = buf ^ 1;
#pragma unroll
            for (int i = 0; i < 4; i++) {
                int idx = tid + (i << 7);
                int row = idx >> 3, c4 = (idx & 7) << 2;
                uint4 ta = {f2tf(pa[i].x), f2tf(pa[i].y), f2tf(pa[i].z), f2tf(pa[i].w)};
                uint4 tb = {f2tf(pb[i].x), f2tf(pb[i].y), f2tf(pb[i].z), f2tf(pb[i].w)};
                *reinterpret_cast<uint4*>(&As[nbuf][row][c4]) = ta;
                *reinterpret_cast<uint4*>(&Bs[nbuf][row][c4]) = tb;
            }
            __syncthreads();
        }
    }

#pragma unroll
    for (int mt = 0; mt < 2; mt++) {
#pragma unroll
        for (int nt = 0; nt < 4; nt++) {
            int row = bm + wm + (mt << 4) + (lane >> 2);
            int col = bn + wn + (nt << 3) + ((lane & 3) << 1);
            float b0 = bias[col], b1 = bias[col + 1];
            float v0 = c[mt][nt][0] + b0;
            float v1 = c[mt][nt][1] + b1;
            float v2 = c[mt][nt][2] + b0;
            float v3 = c[mt][nt][3] + b1;
            if (relu) {
                v0 = fmaxf(v0, 0.0f); v1 = fmaxf(v1, 0.0f);
                v2 = fmaxf(v2, 0.0f); v3 = fmaxf(v3, 0.0f);
            }
            C[row * ldc + col] = v0;
            C[row * ldc + col + 1] = v1;
            C[(row + 8) * ldc + col] = v2;
            C[(row + 8) * ldc + col + 1] = v3;
        }
    }
}

__global__ void __launch_bounds__(128)
gemm_fc_kernel(const float* __restrict__ Wfc, const float* __restrict__ bfc) {
    gemm_tf32(g_x3, 3136, Wfc, 3136, bfc, g_xs, KPAD, 3136, true);
}

__global__ void __launch_bounds__(128)
gemm_pre_kernel() {
    gemm_tf32(g_xs, KPAD, g_wihp, KPAD, g_bsum, g_pre, 1024, KPAD, false);
}

// ----------------------------------------------------------------------------
// LSTM: 4 clusters x 8 CTAs, W_hh slice SMEM-resident, DSMEM gate exchange.
// ----------------------------------------------------------------------------
__global__ void __launch_bounds__(256, 1) __cluster_dims__(8, 1, 1)
lstm_kernel(const float* __restrict__ done,
            const float* __restrict__ h0,
            const float* __restrict__ c0,
            float* __restrict__ hT,
            float* __restrict__ cT) {
    extern __shared__ float sm[];
    float* wsl = sm;                    // 256*128 = 32768 floats (weight slice)
    float* h_s = sm + 32768;            // 8*260 = 2080 floats (padded h, full copy)
    float* gbuf = h_s + 2080;           // 4*8*32 = 1024 floats (owned gate values)
    float* m_s = gbuf + 1024;           // 8 floats (masks)

    int tid = threadIdx.x;
    unsigned rank;
    asm("mov.u32 %0, %%cluster_ctarank;" : "=r"(rank));
    int cl = blockIdx.x >> 3;
    int bbase = cl * 8;

    {
        const float* src = g_whhT + 128 * (int)rank;
        for (int i = tid; i < 8192; i += 256) {
            int k = i >> 5, j4 = (i & 31) << 2;
            *reinterpret_cast<float4*>(&wsl[k * 128 + j4]) =
                *reinterpret_cast<const float4*>(&src[k * 1024 + j4]);
        }
    }
    for (int i = tid; i < 2048; i += 256) {
        int b = i >> 8, k = i & 255;
        h_s[b * 260 + k] = h0[(bbase + b) * 256 + k];
    }
    int ob = tid >> 5, os = tid & 31;
    int ou = 32 * (int)rank + os;
    float c_reg = c0[(bbase + ob) * 256 + ou];
    float hn = 0.0f;

    int b = tid & 7, jg = tid >> 3;
    int jbase = 4 * jg;
    int gt = (int)rank >> 1;
    int ubase = ((128 * (int)rank) & 255) + jbase;
    uint32_t owner = (uint32_t)(ubase >> 5);
    uint32_t gbuf_a = smem_u32(gbuf);
    uint32_t h_a = smem_u32(h_s);
    uint32_t peer_gbuf = mapa_rank(gbuf_a, owner);
    uint32_t goff = (uint32_t)(((gt * 8 + b) * 32 + (ubase & 31)) * 4);
    uint32_t hpeer[8];
#pragma unroll
    for (int p = 0; p < 8; p++) hpeer[p] = mapa_rank(h_a, (uint32_t)p);
    uint32_t hoff = (uint32_t)((ob * 260 + ou) * 4);

    __syncthreads();
    CLUSTER_SYNC();

    for (int t = 0; t < 32; t++) {
        if (tid < 8) m_s[tid] = 1.0f - __ldg(&done[t * 32 + bbase + tid]);
        __syncthreads();
        for (int i = tid; i < 2048; i += 256) {
            int bb = i >> 8, k = i & 255;
            h_s[bb * 260 + k] *= m_s[bb];
        }
        c_reg *= m_s[ob];
        __syncthreads();

        int row = (t << 5) + bbase + b;
        float4 a = *reinterpret_cast<const float4*>(
            g_pre + row * 1024 + 128 * (int)rank + jbase);
        float acc0 = a.x, acc1 = a.y, acc2 = a.z, acc3 = a.w;
        const float* hb = h_s + b * 260;
#pragma unroll 8
        for (int k = 0; k < 256; k++) {
            float hv = hb[k];
            float4 w = *reinterpret_cast<const float4*>(&wsl[k * 128 + jbase]);
            acc0 = fmaf(hv, w.x, acc0);
            acc1 = fmaf(hv, w.y, acc1);
            acc2 = fmaf(hv, w.z, acc2);
            acc3 = fmaf(hv, w.w, acc3);
        }
        st_cluster_f32(peer_gbuf + goff, acc0);
        st_cluster_f32(peer_gbuf + goff + 4, acc1);
        st_cluster_f32(peer_gbuf + goff + 8, acc2);
        st_cluster_f32(peer_gbuf + goff + 12, acc3);
        CLUSTER_SYNC();

        {
            float gi = sigmoidf(gbuf[(0 * 8 + ob) * 32 + os]);
            float gf = sigmoidf(gbuf[(1 * 8 + ob) * 32 + os]);
            float gg = tanhf(gbuf[(2 * 8 + ob) * 32 + os]);
            float go = sigmoidf(gbuf[(3 * 8 + ob) * 32 + os]);
            c_reg = gf * c_reg + gi * gg;
            hn = go * tanhf(c_reg);
            g_hs[((t << 5) + bbase + ob) * 256 + ou] = hn;
#pragma unroll
            for (int p = 0; p < 8; p++) st_cluster_f32(hpeer[p] + hoff, hn);
        }
        CLUSTER_SYNC();
    }
    hT[(bbase + ob) * 256 + ou] = hn;
    cT[(bbase + ob) * 256 + ou] = c_reg;
}

// ----------------------------------------------------------------------------
// Heads: 8 rows per block; weights loaded once per k, 8 FMAs each.
// ----------------------------------------------------------------------------
__global__ void __launch_bounds__(128)
heads_kernel(const float* __restrict__ bp1,
             const float* __restrict__ Wp2,
             const float* __restrict__ bp2,
             const float* __restrict__ bv1,
             const float* __restrict__ Wv2,
             const float* __restrict__ bv2,
             float* __restrict__ logits,
             float* __restrict__ vout) {
    __shared__ float h_s[8][256];
    __shared__ float hp[8][64];
    __shared__ float hv[8][64];
    int r0 = blockIdx.x * 8, t = threadIdx.x;
    {
        const float4* g4 = reinterpret_cast<const float4*>(g_hs + r0 * 256);
        float4* s4 = reinterpret_cast<float4*>(&h_s[0][0]);
        for (int i = t; i < 512; i += 128) s4[i] = g4[i];
    }
    __syncthreads();

    if (t < 64) {
        float s[8];
#pragma unroll
        for (int r = 0; r < 8; r++) s[r] = bp1[t];
#pragma unroll 4
        for (int k = 0; k < 256; k++) {
            float w = __ldg(&g_wp1T[k * 64 + t]);
#pragma unroll
            for (int r = 0; r < 8; r++) s[r] = fmaf(h_s[r][k], w, s[r]);
        }
#pragma unroll
        for (int r = 0; r < 8; r++) hp[r][t] = tanhf(s[r]);
    } else {
        int j = t - 64;
        float s[8];
#pragma unroll
        for (int r = 0; r < 8; r++) s[r] = bv1[j];
#pragma unroll 4
        for (int k = 0; k < 256; k++) {
            float w = __ldg(&g_wv1T[k * 64 + j]);
#pragma unroll
            for (int r = 0; r < 8; r++) s[r] = fmaf(h_s[r][k], w, s[r]);
        }
#pragma unroll
        for (int r = 0; r < 8; r++) hv[r][j] = tanhf(s[r]);
    }
    __syncthreads();

    if (t < 40) {
        int r = t / 5, a = t % 5;
        float s = bp2[a];
#pragma unroll
        for (int k = 0; k < 64; k++) s = fmaf(hp[r][k], Wp2[a * 64 + k], s);
        logits[(r0 + r) * 5 + a] = s;
    }
    if (t >= 64 && t < 72) {
        int r = t - 64;
        float s = bv2[0];
#pragma unroll
        for (int k = 0; k < 64; k++) s = fmaf(hv[r][k], Wv2[k], s);
        vout[r0 + r] = s;
    }
}

// ----------------------------------------------------------------------------
// Launch
// ----------------------------------------------------------------------------
extern "C" void kernel_launch(void* const* d_in, const int* in_sizes, int n_in,
                              void* d_out, int out_size) {
    const float* image = (const float*)d_in[0];
    const int* la = (const int*)d_in[1];
    const float* done = (const float*)d_in[2];
    const float* h0 = (const float*)d_in[3];
    const float* c0 = (const float*)d_in[4];
    const float* W1 = (const float*)d_in[5];
    const float* b1 = (const float*)d_in[6];
    const float* W2 = (const float*)d_in[7];
    const float* b2 = (const float*)d_in[8];
    const float* W3 = (const float*)d_in[9];
    const float* b3 = (const float*)d_in[10];
    const float* Wfc = (const float*)d_in[11];
    const float* bfc = (const float*)d_in[12];
    const float* W_ih = (const float*)d_in[13];
    const float* W_hh = (const float*)d_in[14];
    const float* b_ih = (const float*)d_in[15];
    const float* b_hh = (const float*)d_in[16];
    const float* Wp1 = (const float*)d_in[17];
    const float* bp1 = (const float*)d_in[18];
    const float* Wp2 = (const float*)d_in[19];
    const float* bp2 = (const float*)d_in[20];
    const float* Wv1 = (const float*)d_in[21];
    const float* bv1 = (const float*)d_in[22];
    const float* Wv2 = (const float*)d_in[23];
    const float* bv2 = (const float*)d_in[24];

    float* out = (float*)d_out;
    float* o_logits = out;           // 5120
    float* o_v = out + 5120;         // 1024
    float* o_hT = out + 6144;        // 8192
    float* o_cT = out + 14336;       // 8192

    // conv smem: Ws OC*(K+4) + img IMG + B hi/lo 4*BN*36 + luts (K + NPX)
    const int SMEMC1 = (32 * 196 + 21168 + 4 * 128 * 36 + 192 + 400) * 4;  // 185856
    const int SMEMC2 = (64 * 516 + 12800 + 4 * 64 * 36 + 512 + 81) * 4;    // 222532
    const int SMEMC3 = (64 * 580 + 5184 + 4 * 64 * 36 + 576 + 49) * 4;     // 208580
    const int SMEML = (32768 + 2080 + 1024 + 8) * 4;                        // 143520

    cudaFuncSetAttribute((const void*)conv_mma_kernel<32, 400, 192, 21168, 1>,
                         cudaFuncAttributeMaxDynamicSharedMemorySize, SMEMC1);
    cudaFuncSetAttribute((const void*)conv_mma_kernel<64, 81, 512, 12800, 2>,
                         cudaFuncAttributeMaxDynamicSharedMemorySize, SMEMC2);
    cudaFuncSetAttribute((const void*)conv_mma_kernel<64, 49, 576, 5184, 2>,
                         cudaFuncAttributeMaxDynamicSharedMemorySize, SMEMC3);
    cudaFuncSetAttribute((const void*)lstm_kernel,
                         cudaFuncAttributeMaxDynamicSharedMemorySize, SMEML);

    prep_kernel<<<2176, 256>>>(W_hh, b_ih, b_hh, Wp1, Wv1, W_ih);
    conv_mma_kernel<32, 400, 192, 21168, 1><<<148, 128, SMEMC1>>>(W1, b1, image, 1.0f / 255.0f);
    conv_mma_kernel<64, 81, 512, 12800, 2><<<148, 128, SMEMC2>>>(W2, b2, nullptr, 1.0f);
    conv_mma_kernel<64, 49, 576, 5184, 2><<<148, 128, SMEMC3>>>(W3, b3, nullptr, 1.0f);
    gemm_fc_kernel<<<dim3(512 / 64, 1024 / 64), 128>>>(Wfc, bfc);
    onehot_kernel<<<4, 256>>>(la);
    gemm_pre_kernel<<<dim3(1024 / 64, 1024 / 64), 128>>>();
    lstm_kernel<<<32, 256, SMEML>>>(done, h0, c0, o_hT, o_cT);
    heads_kernel<<<128, 128>>>(bp1, Wp2, bp2, bv1, Wv2, bv2, o_logits, o_v);
}

// round 13
// speedup vs baseline: 1.7850x; 1.7850x over previous
#include <cuda_runtime.h>
#include <math.h>
#include <stdint.h>

// ----------------------------------------------------------------------------
// Problem constants
//   T=32, B=32, TB=1024, NA=5, HID=256, FEAT=512, IN_DIM=517 (pad 544), FLAT=3136
// Output layout (22528 floats): logits[1024*5] | v[1024] | hT[32*256] | cT[32*256]
// ----------------------------------------------------------------------------

#define TBn 1024
#define KPAD 544    // padded IN_DIM for tf32 GEMM (multiple of 32)

// Scratch (device globals; no allocation allowed)
__device__ float g_x1[TBn * 32 * 20 * 20];   // conv1 out
__device__ float g_x2[TBn * 64 * 9 * 9];     // conv2 out
__device__ float g_x3[TBn * 3136];           // conv3 out (flatten, C,H,W)
__device__ float g_xs[TBn * KPAD];           // feat || one-hot || zero pad
__device__ float g_pre[TBn * 1024];          // x @ W_ih^T + b_ih + b_hh
__device__ float g_whhT[256 * 1024];         // W_hh transposed: [k][4*HID]
__device__ float g_wihp[1024 * KPAD];        // W_ih zero-padded to KPAD
__device__ float g_bsum[1024];               // b_ih + b_hh
__device__ float g_wp1T[256 * 64];           // Wp1 transposed [k][64]
__device__ float g_wv1T[256 * 64];           // Wv1 transposed [k][64]
__device__ float g_hs[TBn * 256];            // all h outputs
// Pre-packed conv weights, transposed to [k][oc].
__device__ float g_w1p[192 * 32];            // conv1 W
__device__ float g_w2p[512 * 64];            // conv2 W
__device__ float g_w3p[576 * 64];            // conv3 W

__device__ __forceinline__ float sigmoidf(float x) { return 1.0f / (1.0f + expf(-x)); }

__device__ __forceinline__ unsigned f2tf(float f) {
    unsigned u;
    asm("cvt.rna.tf32.f32 %0, %1;" : "=r"(u) : "f"(f));
    return u;
}

// ---- cluster / DSMEM helpers ----
__device__ __forceinline__ uint32_t smem_u32(const void* p) {
    uint32_t a;
    asm("{ .reg .u64 t; cvta.to.shared.u64 t, %1; cvt.u32.u64 %0, t; }"
        : "=r"(a) : "l"(p));
    return a;
}
__device__ __forceinline__ uint32_t mapa_rank(uint32_t saddr, uint32_t rank) {
    uint32_t r;
    asm("mapa.shared::cluster.u32 %0, %1, %2;" : "=r"(r) : "r"(saddr), "r"(rank));
    return r;
}
__device__ __forceinline__ void st_cluster_f32(uint32_t addr, float v) {
    asm volatile("st.shared::cluster.f32 [%0], %1;" :: "r"(addr), "f"(v) : "memory");
}
#define CLUSTER_SYNC() do { \
    asm volatile("barrier.cluster.arrive.aligned;" ::: "memory"); \
    asm volatile("barrier.cluster.wait.aligned;" ::: "memory"); \
} while (0)

// ----------------------------------------------------------------------------
// prep
// ----------------------------------------------------------------------------
__global__ void prep_kernel(const float* __restrict__ W_hh,
                            const float* __restrict__ b_ih,
                            const float* __restrict__ b_hh,
                            const float* __restrict__ Wp1,
                            const float* __restrict__ Wv1,
                            const float* __restrict__ W1,
                            const float* __restrict__ W2,
                            const float* __restrict__ W3,
                            const float* __restrict__ W_ih) {
    int idx = blockIdx.x * blockDim.x + threadIdx.x;
    if (idx < 262144) {
        int j = idx >> 8, k = idx & 255;
        g_whhT[k * 1024 + j] = W_hh[idx];
    }
    if (idx < 16384) {
        int j = idx >> 8, k = idx & 255;
        g_wp1T[k * 64 + j] = Wp1[idx];
        g_wv1T[k * 64 + j] = Wv1[idx];
    }
    if (idx < 1024) g_bsum[idx] = b_ih[idx] + b_hh[idx];
    if (idx < 6144) {
        int oc = idx / 192, k = idx % 192;
        g_w1p[k * 32 + oc] = W1[idx];
    }
    if (idx < 32768) {
        int oc = idx >> 9, k = idx & 511;
        g_w2p[k * 64 + oc] = W2[idx];
    }
    if (idx < 36864) {
        int oc = idx / 576, k = idx % 576;
        g_w3p[k * 64 + oc] = W3[idx];
    }
    if (idx < 1024 * KPAD) {
        int row = idx / KPAD, col = idx % KPAD;
        g_wihp[idx] = (col < 517) ? W_ih[row * 517 + col] : 0.0f;
    }
}

// ----------------------------------------------------------------------------
// one-hot columns of xs (cols 512..516) + zero pad (517..543)
// ----------------------------------------------------------------------------
__global__ void onehot_kernel(const int* __restrict__ la) {
    int r = blockIdx.x * blockDim.x + threadIdx.x;
    if (r < TBn) {
        int a = la[r];
        float* p = g_xs + r * KPAD + 512;
#pragma unroll
        for (int j = 0; j < 5; j++) p[j] = (j == a) ? 1.0f : 0.0f;
#pragma unroll
        for (int j = 5; j < 32; j++) p[j] = 0.0f;
    }
}

// ----------------------------------------------------------------------------
// conv1: in (TB,3,84,84)/255, W (32,3,8,8) stride4 -> (TB,32,20,20) relu
// 1 image/block, 640 threads: (oy 0-19) x (quarter 0-3) x (oc-group 0-7 of 4).
// ----------------------------------------------------------------------------
__global__ void __launch_bounds__(640, 1)
conv1_kernel(const float* __restrict__ img, const float* __restrict__ b1) {
    extern __shared__ float sm[];            // 21168 floats (one image)
    int tid = threadIdx.x;
    {
        const float4* g4 = reinterpret_cast<const float4*>(img + blockIdx.x * 21168);
        float4* s4 = reinterpret_cast<float4*>(sm);
        for (int i = tid; i < 5292; i += 640) {
            float4 v = g4[i];
            v.x *= (1.0f / 255.0f); v.y *= (1.0f / 255.0f);
            v.z *= (1.0f / 255.0f); v.w *= (1.0f / 255.0f);
            s4[i] = v;
        }
    }
    __syncthreads();

    int oy = tid >> 5, rem = tid & 31;
    int q = rem >> 3, og = rem & 7;          // q: 5-px quarter, og: 4 oc
    const float4* w4 = reinterpret_cast<const float4*>(g_w1p);

    float acc[5][4];
#pragma unroll
    for (int p = 0; p < 5; p++)
#pragma unroll
        for (int c = 0; c < 4; c++) acc[p][c] = 0.0f;

    for (int ic = 0; ic < 3; ic++) {
        for (int ky = 0; ky < 8; ky++) {
            const float* row = sm + ic * 7056 + (oy * 4 + ky) * 84 + q * 20;
            float rr[24];
#pragma unroll
            for (int v = 0; v < 6; v++) {
                float4 t = *reinterpret_cast<const float4*>(row + v * 4);
                rr[v * 4 + 0] = t.x; rr[v * 4 + 1] = t.y;
                rr[v * 4 + 2] = t.z; rr[v * 4 + 3] = t.w;
            }
            int kbase = (ic * 8 + ky) * 8;
#pragma unroll
            for (int kx = 0; kx < 8; kx++) {
                int k = kbase + kx;
                float4 w = __ldg(&w4[k * 8 + og]);
#pragma unroll
                for (int p = 0; p < 5; p++) {
                    float v = rr[p * 4 + kx];
                    acc[p][0] = fmaf(v, w.x, acc[p][0]);
                    acc[p][1] = fmaf(v, w.y, acc[p][1]);
                    acc[p][2] = fmaf(v, w.z, acc[p][2]);
                    acc[p][3] = fmaf(v, w.w, acc[p][3]);
                }
            }
        }
    }
    float* o = g_x1 + blockIdx.x * 12800;
#pragma unroll
    for (int c = 0; c < 4; c++) {
        int oc = og * 4 + c;
        float bb = __ldg(&b1[oc]);
        float* op = o + oc * 400 + oy * 20 + q * 5;
#pragma unroll
        for (int p = 0; p < 5; p++) op[p] = fmaxf(acc[p][c] + bb, 0.0f);
    }
}

// ----------------------------------------------------------------------------
// conv2: (TB,32,20,20) * W(64,32,4,4) s2 -> (TB,64,9,9) relu
// ----------------------------------------------------------------------------
__global__ void __launch_bounds__(288, 1)
conv2_kernel(const float* __restrict__ b2) {
    extern __shared__ float sm[];            // 4 * 12800 floats
    int tid = threadIdx.x;
    {
        const float4* g4 = reinterpret_cast<const float4*>(g_x1 + blockIdx.x * 4 * 12800);
        float4* s4 = reinterpret_cast<float4*>(sm);
        for (int i = tid; i < 12800; i += 288) s4[i] = g4[i];
    }
    __syncthreads();

    int im = tid / 72, r = tid % 72;
    int oy = r >> 3, ocg = r & 7;
    const float* ims = sm + im * 12800;
    const float4* w4 = reinterpret_cast<const float4*>(g_w2p);

    float acc[9][8];
#pragma unroll
    for (int p = 0; p < 9; p++)
#pragma unroll
        for (int c = 0; c < 8; c++) acc[p][c] = 0.0f;

    for (int ic = 0; ic < 32; ic++) {
#pragma unroll
        for (int ky = 0; ky < 4; ky++) {
            const float* row = ims + ic * 400 + (oy * 2 + ky) * 20;
            float rr[20];
#pragma unroll
            for (int v = 0; v < 5; v++) {
                float4 t = *reinterpret_cast<const float4*>(row + v * 4);
                rr[v * 4 + 0] = t.x; rr[v * 4 + 1] = t.y;
                rr[v * 4 + 2] = t.z; rr[v * 4 + 3] = t.w;
            }
            int kbase = (ic * 4 + ky) * 4;
#pragma unroll
            for (int kx = 0; kx < 4; kx++) {
                int k = kbase + kx;
                float4 w0 = __ldg(&w4[k * 16 + ocg * 2]);
                float4 w1 = __ldg(&w4[k * 16 + ocg * 2 + 1]);
#pragma unroll
                for (int p = 0; p < 9; p++) {
                    float v = rr[p * 2 + kx];
                    acc[p][0] = fmaf(v, w0.x, acc[p][0]);
                    acc[p][1] = fmaf(v, w0.y, acc[p][1]);
                    acc[p][2] = fmaf(v, w0.z, acc[p][2]);
                    acc[p][3] = fmaf(v, w0.w, acc[p][3]);
                    acc[p][4] = fmaf(v, w1.x, acc[p][4]);
                    acc[p][5] = fmaf(v, w1.y, acc[p][5]);
                    acc[p][6] = fmaf(v, w1.z, acc[p][6]);
                    acc[p][7] = fmaf(v, w1.w, acc[p][7]);
                }
            }
        }
    }
    int n = blockIdx.x * 4 + im;
    float* o = g_x2 + n * 5184;
#pragma unroll
    for (int c = 0; c < 8; c++) {
        int oc = ocg * 8 + c;
        float bb = __ldg(&b2[oc]);
        float* op = o + oc * 81 + oy * 9;
#pragma unroll
        for (int p = 0; p < 9; p++) op[p] = fmaxf(acc[p][c] + bb, 0.0f);
    }
}

// ----------------------------------------------------------------------------
// conv3: (TB,64,9,9) * W(64,64,3,3) s1 -> (TB,64,7,7) relu -> flatten
// Persistent grid 148; chunks of <=4 images; 448 threads = 4 img x 112.
// ----------------------------------------------------------------------------
__global__ void __launch_bounds__(448, 1)
conv3_kernel(const float* __restrict__ b3) {
    extern __shared__ float sm[];            // 4 * 5184 floats
    int tid = threadIdx.x;
    int im = tid / 112, r = tid % 112;
    int oy = r >> 4, oh = r & 15;            // oh: 4-oc group
    const float4* w4 = reinterpret_cast<const float4*>(g_w3p);

    int s = (blockIdx.x * 1024) / 148;
    int e = ((blockIdx.x + 1) * 1024) / 148;

    for (int c0 = s; c0 < e; c0 += 4) {
        int cnt = min(4, e - c0);
        {
            const float4* g4 = reinterpret_cast<const float4*>(g_x2 + c0 * 5184);
            float4* s4 = reinterpret_cast<float4*>(sm);
            for (int i = tid; i < cnt * 1296; i += 448) s4[i] = g4[i];
        }
        __syncthreads();

        if (im < cnt) {
            const float* ims = sm + im * 5184;
            float acc[7][4];
#pragma unroll
            for (int p = 0; p < 7; p++)
#pragma unroll
                for (int c = 0; c < 4; c++) acc[p][c] = 0.0f;

            for (int ic = 0; ic < 64; ic++) {
#pragma unroll
                for (int ky = 0; ky < 3; ky++) {
                    const float* row = ims + ic * 81 + (oy + ky) * 9;
                    float rr[9];
#pragma unroll
                    for (int v = 0; v < 9; v++) rr[v] = row[v];
                    int kbase = (ic * 3 + ky) * 3;
#pragma unroll
                    for (int kx = 0; kx < 3; kx++) {
                        int k = kbase + kx;
                        float4 w = __ldg(&w4[k * 16 + oh]);
#pragma unroll
                        for (int p = 0; p < 7; p++) {
                            float v = rr[p + kx];
                            acc[p][0] = fmaf(v, w.x, acc[p][0]);
                            acc[p][1] = fmaf(v, w.y, acc[p][1]);
                            acc[p][2] = fmaf(v, w.z, acc[p][2]);
                            acc[p][3] = fmaf(v, w.w, acc[p][3]);
                        }
                    }
                }
            }
            int n = c0 + im;
            float* o = g_x3 + n * 3136;
#pragma unroll
            for (int c = 0; c < 4; c++) {
                int oc = oh * 4 + c;
                float bb = __ldg(&b3[oc]);
                float* op = o + oc * 49 + oy * 7;
#pragma unroll
                for (int p = 0; p < 7; p++) op[p] = fmaxf(acc[p][c] + bb, 0.0f);
            }
        }
        __syncthreads();
    }
}

// ----------------------------------------------------------------------------
// tf32 tensor-core GEMM: C[M x N] = act(A[M x K] * B[N x K]^T + bias)
// ----------------------------------------------------------------------------
__device__ __forceinline__ void mma_tf32(float* c, const unsigned* a, const unsigned* b) {
    asm volatile(
        "mma.sync.aligned.m16n8k8.row.col.f32.tf32.tf32.f32 "
        "{%0,%1,%2,%3}, {%4,%5,%6,%7}, {%8,%9}, {%0,%1,%2,%3};\n"
        : "+f"(c[0]), "+f"(c[1]), "+f"(c[2]), "+f"(c[3])
        : "r"(a[0]), "r"(a[1]), "r"(a[2]), "r"(a[3]), "r"(b[0]), "r"(b[1]));
}

__device__ __forceinline__ void gemm_tf32(const float* __restrict__ A, int lda,
                                          const float* __restrict__ B, int ldb,
                                          const float* __restrict__ bias,
                                          float* __restrict__ C, int ldc,
                                          int K, bool relu) {
    __shared__ unsigned As[2][64][36];
    __shared__ unsigned Bs[2][64][36];
    int tid = threadIdx.x, lane = tid & 31, warp = tid >> 5;
    int bm = blockIdx.y * 64, bn = blockIdx.x * 64;
    int wm = (warp & 1) << 5, wn = (warp >> 1) << 5;

    float c[2][4][4];
#pragma unroll
    for (int mt = 0; mt < 2; mt++)
#pragma unroll
        for (int nt = 0; nt < 4; nt++)
#pragma unroll
            for (int i = 0; i < 4; i++) c[mt][nt][i] = 0.0f;

    int ntiles = K >> 5;
    float4 pa[4], pb[4];

#pragma unroll
    for (int i = 0; i < 4; i++) {
        int idx = tid + (i << 7);
        int row = idx >> 3, c4 = (idx & 7) << 2;
        pa[i] = *reinterpret_cast<const float4*>(A + (bm + row) * lda + c4);
        pb[i] = *reinterpret_cast<const float4*>(B + (bn + row) * ldb + c4);
    }
#pragma unroll
    for (int i = 0; i < 4; i++) {
        int idx = tid + (i << 7);
        int row = idx >> 3, c4 = (idx & 7) << 2;
        uint4 ta = {f2tf(pa[i].x), f2tf(pa[i].y), f2tf(pa[i].z), f2tf(pa[i].w)};
        uint4 tb = {f2tf(pb[i].x), f2tf(pb[i].y), f2tf(pb[i].z), f2tf(pb[i].w)};
        *reinterpret_cast<uint4*>(&As[0][row][c4]) = ta;
        *reinterpret_cast<uint4*>(&Bs[0][row][c4]) = tb;
    }
    __syncthreads();

    for (int t = 0; t < ntiles; t++) {
        int buf = t & 1;
        if (t + 1 < ntiles) {
            int k0 = (t + 1) << 5;
#pragma unroll
            for (int i = 0; i < 4; i++) {
                int idx = tid + (i << 7);
                int row = idx >> 3, c4 = (idx & 7) << 2;
                pa[i] = *reinterpret_cast<const float4*>(A + (bm + row) * lda + k0 + c4);
                pb[i] = *reinterpret_cast<const float4*>(B + (bn + row) * ldb + k0 + c4);
            }
        }
        int r = lane >> 2, q = lane & 3;
#pragma unroll
        for (int ks = 0; ks < 4; ks++) {
            unsigned a[2][4], b[4][2];
            int kc = ks << 3;
#pragma unroll
            for (int mt = 0; mt < 2; mt++) {
                int mr = wm + (mt << 4) + r;
                a[mt][0] = As[buf][mr][kc + q];
                a[mt][1] = As[buf][mr + 8][kc + q];
                a[mt][2] = As[buf][mr][kc + q + 4];
                a[mt][3] = As[buf][mr + 8][kc + q + 4];
            }
#pragma unroll
            for (int nt = 0; nt < 4; nt++) {
                int nr = wn + (nt << 3) + r;
                b[nt][0] = Bs[buf][nr][kc + q];
                b[nt][1] = Bs[buf][nr][kc + q + 4];
            }
#pragma unroll
            for (int mt = 0; mt < 2; mt++)
#pragma unroll
                for (int nt = 0; nt < 4; nt++)
                    mma_tf32(c[mt][nt], a[mt], b[nt]);
        }
        if (t + 1 < ntiles) {
            int nbuf = buf ^ 1;
#pragma unroll
            for (int i = 0; i < 4; i++) {
                int idx = tid + (i << 7);
                int row = idx >> 3, c4 = (idx & 7) << 2;
                uint4 ta = {f2tf(pa[i].x), f2tf(pa[i].y), f2tf(pa[i].z), f2tf(pa[i].w)};
                uint4 tb = {f2tf(pb[i].x), f2tf(pb[i].y), f2tf(pb[i].z), f2tf(pb[i].w)};
                *reinterpret_cast<uint4*>(&As[nbuf][row][c4]) = ta;
                *reinterpret_cast<uint4*>(&Bs[nbuf][row][c4]) = tb;
            }
            __syncthreads();
        }
    }

#pragma unroll
    for (int mt = 0; mt < 2; mt++) {
#pragma unroll
        for (int nt = 0; nt < 4; nt++) {
            int row = bm + wm + (mt << 4) + (lane >> 2);
            int col = bn + wn + (nt << 3) + ((lane & 3) << 1);
            float b0 = bias[col], b1 = bias[col + 1];
            float v0 = c[mt][nt][0] + b0;
            float v1 = c[mt][nt][1] + b1;
            float v2 = c[mt][nt][2] + b0;
            float v3 = c[mt][nt][3] + b1;
            if (relu) {
                v0 = fmaxf(v0, 0.0f); v1 = fmaxf(v1, 0.0f);
                v2 = fmaxf(v2, 0.0f); v3 = fmaxf(v3, 0.0f);
            }
            C[row * ldc + col] = v0;
            C[row * ldc + col + 1] = v1;
            C[(row + 8) * ldc + col] = v2;
            C[(row + 8) * ldc + col + 1] = v3;
        }
    }
}

__global__ void __launch_bounds__(128)
gemm_fc_kernel(const float* __restrict__ Wfc, const float* __restrict__ bfc) {
    gemm_tf32(g_x3, 3136, Wfc, 3136, bfc, g_xs, KPAD, 3136, true);
}

__global__ void __launch_bounds__(128)
gemm_pre_kernel() {
    gemm_tf32(g_xs, KPAD, g_wihp, KPAD, g_bsum, g_pre, 1024, KPAD, false);
}

// ----------------------------------------------------------------------------
// LSTM: 4 clusters x 8 CTAs, W_hh slice SMEM-resident, DSMEM gate exchange.
// NEW mapping: thread = (2 cols x 2 batches): jg2 = tid>>2 (cols 2*jg2,+1),
// bp = tid&3 (batches 2bp, 2bp+1). Each ld.64 weight feeds 4 FMAs -> smem
// weight traffic halves (1MB -> 512KB per CTA-step), matching the FMA floor.
// Per-column k-summation order identical to before (bitwise same results).
// ----------------------------------------------------------------------------
__global__ void __launch_bounds__(256, 1) __cluster_dims__(8, 1, 1)
lstm_kernel(const float* __restrict__ done,
            const float* __restrict__ h0,
            const float* __restrict__ c0,
            float* __restrict__ hT,
            float* __restrict__ cT) {
    extern __shared__ float sm[];
    float* wsl = sm;                    // 256*128 = 32768 floats (weight slice)
    float* h_s = sm + 32768;            // 8*260 = 2080 floats (padded h, full copy)
    float* gbuf = h_s + 2080;           // 4*8*32 = 1024 floats (owned gate values)
    float* m_s = gbuf + 1024;           // 8 floats (masks)

    int tid = threadIdx.x;
    unsigned rank;
    asm("mov.u32 %0, %%cluster_ctarank;" : "=r"(rank));
    int cl = blockIdx.x >> 3;
    int bbase = cl * 8;

    {
        const float* src = g_whhT + 128 * (int)rank;
        for (int i = tid; i < 8192; i += 256) {
            int k = i >> 5, j4 = (i & 31) << 2;
            *reinterpret_cast<float4*>(&wsl[k * 128 + j4]) =
                *reinterpret_cast<const float4*>(&src[k * 1024 + j4]);
        }
    }
    for (int i = tid; i < 2048; i += 256) {
        int b = i >> 8, k = i & 255;
        h_s[b * 260 + k] = h0[(bbase + b) * 256 + k];
    }
    // owner state: thread t owns (batch ob, unit 32*rank + os)
    int ob = tid >> 5, os = tid & 31;
    int ou = 32 * (int)rank + os;
    float c_reg = c0[(bbase + ob) * 256 + ou];
    float hn = 0.0f;

    // compute mapping: 2 cols x 2 batches per thread
    int jg2 = tid >> 2, bp = tid & 3;
    int jbase = 2 * jg2;                          // 0..126 (even)
    int b0 = 2 * bp, b1 = b0 + 1;
    int gt = (int)rank >> 1;                      // gate type of this col slice
    int ubase = ((128 * (int)rank) & 255) + jbase;
    uint32_t owner = (uint32_t)(ubase >> 5);      // same owner for both cols
    uint32_t gbuf_a = smem_u32(gbuf);
    uint32_t h_a = smem_u32(h_s);
    uint32_t peer_gbuf = mapa_rank(gbuf_a, owner);
    uint32_t g0 = (uint32_t)(((gt * 8 + b0) * 32 + (ubase & 31)) * 4);
    uint32_t g1 = (uint32_t)(((gt * 8 + b1) * 32 + (ubase & 31)) * 4);
    uint32_t hpeer[8];
#pragma unroll
    for (int p = 0; p < 8; p++) hpeer[p] = mapa_rank(h_a, (uint32_t)p);
    uint32_t hoff = (uint32_t)((ob * 260 + ou) * 4);

    __syncthreads();
    CLUSTER_SYNC();

    for (int t = 0; t < 32; t++) {
        if (tid < 8) m_s[tid] = 1.0f - __ldg(&done[t * 32 + bbase + tid]);
        __syncthreads();
        for (int i = tid; i < 2048; i += 256) {
            int bb = i >> 8, k = i & 255;
            h_s[bb * 260 + k] *= m_s[bb];
        }
        c_reg *= m_s[ob];
        __syncthreads();

        int row0 = (t << 5) + bbase + b0;
        int row1 = row0 + 1;
        float2 a0 = *reinterpret_cast<const float2*>(
            g_pre + row0 * 1024 + 128 * (int)rank + jbase);
        float2 a1 = *reinterpret_cast<const float2*>(
            g_pre + row1 * 1024 + 128 * (int)rank + jbase);
        float acc00 = a0.x, acc01 = a0.y;   // batch b0, cols jbase, jbase+1
        float acc10 = a1.x, acc11 = a1.y;   // batch b1
        const float* hb0 = h_s + b0 * 260;
        const float* hb1 = h_s + b1 * 260;
#pragma unroll 8
        for (int k = 0; k < 256; k++) {
            float2 w = *reinterpret_cast<const float2*>(&wsl[k * 128 + jbase]);
            float h0k = hb0[k];
            float h1k = hb1[k];
            acc00 = fmaf(h0k, w.x, acc00);
            acc01 = fmaf(h0k, w.y, acc01);
            acc10 = fmaf(h1k, w.x, acc10);
            acc11 = fmaf(h1k, w.y, acc11);
        }
        st_cluster_f32(peer_gbuf + g0, acc00);
        st_cluster_f32(peer_gbuf + g0 + 4, acc01);
        st_cluster_f32(peer_gbuf + g1, acc10);
        st_cluster_f32(peer_gbuf + g1 + 4, acc11);
        CLUSTER_SYNC();

        // owner pointwise update for (ob, ou)
        {
            float gi = sigmoidf(gbuf[(0 * 8 + ob) * 32 + os]);
            float gf = sigmoidf(gbuf[(1 * 8 + ob) * 32 + os]);
            float gg = tanhf(gbuf[(2 * 8 + ob) * 32 + os]);
            float go = sigmoidf(gbuf[(3 * 8 + ob) * 32 + os]);
            c_reg = gf * c_reg + gi * gg;
            hn = go * tanhf(c_reg);
            g_hs[((t << 5) + bbase + ob) * 256 + ou] = hn;
#pragma unroll
            for (int p = 0; p < 8; p++) st_cluster_f32(hpeer[p] + hoff, hn);
        }
        CLUSTER_SYNC();
    }
    hT[(bbase + ob) * 256 + ou] = hn;
    cT[(bbase + ob) * 256 + ou] = c_reg;
}

// ----------------------------------------------------------------------------
// Heads: 8 rows per block; weights loaded once per k, 8 FMAs each.
// ----------------------------------------------------------------------------
__global__ void __launch_bounds__(128)
heads_kernel(const float* __restrict__ bp1,
             const float* __restrict__ Wp2,
             const float* __restrict__ bp2,
             const float* __restrict__ bv1,
             const float* __restrict__ Wv2,
             const float* __restrict__ bv2,
             float* __restrict__ logits,
             float* __restrict__ vout) {
    __shared__ float h_s[8][256];
    __shared__ float hp[8][64];
    __shared__ float hv[8][64];
    int r0 = blockIdx.x * 8, t = threadIdx.x;
    {
        const float4* g4 = reinterpret_cast<const float4*>(g_hs + r0 * 256);
        float4* s4 = reinterpret_cast<float4*>(&h_s[0][0]);
        for (int i = t; i < 512; i += 128) s4[i] = g4[i];
    }
    __syncthreads();

    if (t < 64) {
        float s[8];
#pragma unroll
        for (int r = 0; r < 8; r++) s[r] = bp1[t];
#pragma unroll 4
        for (int k = 0; k < 256; k++) {
            float w = __ldg(&g_wp1T[k * 64 + t]);
#pragma unroll
            for (int r = 0; r < 8; r++) s[r] = fmaf(h_s[r][k], w, s[r]);
        }
#pragma unroll
        for (int r = 0; r < 8; r++) hp[r][t] = tanhf(s[r]);
    } else {
        int j = t - 64;
        float s[8];
#pragma unroll
        for (int r = 0; r < 8; r++) s[r] = bv1[j];
#pragma unroll 4
        for (int k = 0; k < 256; k++) {
            float w = __ldg(&g_wv1T[k * 64 + j]);
#pragma unroll
            for (int r = 0; r < 8; r++) s[r] = fmaf(h_s[r][k], w, s[r]);
        }
#pragma unroll
        for (int r = 0; r < 8; r++) hv[r][j] = tanhf(s[r]);
    }
    __syncthreads();

    if (t < 40) {
        int r = t / 5, a = t % 5;
        float s = bp2[a];
#pragma unroll
        for (int k = 0; k < 64; k++) s = fmaf(hp[r][k], Wp2[a * 64 + k], s);
        logits[(r0 + r) * 5 + a] = s;
    }
    if (t >= 64 && t < 72) {
        int r = t - 64;
        float s = bv2[0];
#pragma unroll
        for (int k = 0; k < 64; k++) s = fmaf(hv[r][k], Wv2[k], s);
        vout[r0 + r] = s;
    }
}

// ----------------------------------------------------------------------------
// Launch
// ----------------------------------------------------------------------------
extern "C" void kernel_launch(void* const* d_in, const int* in_sizes, int n_in,
                              void* d_out, int out_size) {
    const float* image = (const float*)d_in[0];
    const int* la = (const int*)d_in[1];
    const float* done = (const float*)d_in[2];
    const float* h0 = (const float*)d_in[3];
    const float* c0 = (const float*)d_in[4];
    const float* W1 = (const float*)d_in[5];
    const float* b1 = (const float*)d_in[6];
    const float* W2 = (const float*)d_in[7];
    const float* b2 = (const float*)d_in[8];
    const float* W3 = (const float*)d_in[9];
    const float* b3 = (const float*)d_in[10];
    const float* Wfc = (const float*)d_in[11];
    const float* bfc = (const float*)d_in[12];
    const float* W_ih = (const float*)d_in[13];
    const float* W_hh = (const float*)d_in[14];
    const float* b_ih = (const float*)d_in[15];
    const float* b_hh = (const float*)d_in[16];
    const float* Wp1 = (const float*)d_in[17];
    const float* bp1 = (const float*)d_in[18];
    const float* Wp2 = (const float*)d_in[19];
    const float* bp2 = (const float*)d_in[20];
    const float* Wv1 = (const float*)d_in[21];
    const float* bv1 = (const float*)d_in[22];
    const float* Wv2 = (const float*)d_in[23];
    const float* bv2 = (const float*)d_in[24];

    float* out = (float*)d_out;
    float* o_logits = out;           // 5120
    float* o_v = out + 5120;         // 1024
    float* o_hT = out + 6144;        // 8192
    float* o_cT = out + 14336;       // 8192

    const int SMEM1 = 21168 * 4;        // 84672 (1 image)
    const int SMEM2 = 4 * 12800 * 4;    // 204800
    const int SMEM3 = 4 * 5184 * 4;     // 82944 (4-image chunk)
    const int SMEML = (32768 + 2080 + 1024 + 8) * 4;  // 143520
    cudaFuncSetAttribute(conv1_kernel, cudaFuncAttributeMaxDynamicSharedMemorySize, SMEM1);
    cudaFuncSetAttribute(conv2_kernel, cudaFuncAttributeMaxDynamicSharedMemorySize, SMEM2);
    cudaFuncSetAttribute(conv3_kernel, cudaFuncAttributeMaxDynamicSharedMemorySize, SMEM3);
    cudaFuncSetAttribute(lstm_kernel, cudaFuncAttributeMaxDynamicSharedMemorySize, SMEML);

    prep_kernel<<<2176, 256>>>(W_hh, b_ih, b_hh, Wp1, Wv1, W1, W2, W3, W_ih);
    conv1_kernel<<<1024, 640, SMEM1>>>(image, b1);
    conv2_kernel<<<256, 288, SMEM2>>>(b2);
    conv3_kernel<<<148, 448, SMEM3>>>(b3);
    gemm_fc_kernel<<<dim3(512 / 64, 1024 / 64), 128>>>(Wfc, bfc);
    onehot_kernel<<<4, 256>>>(la);
    gemm_pre_kernel<<<dim3(1024 / 64, 1024 / 64), 128>>>();
    lstm_kernel<<<32, 256, SMEML>>>(done, h0, c0, o_hT, o_cT);
    heads_kernel<<<128, 128>>>(bp1, Wp2, bp2, bv1, Wv2, bv2, o_logits, o_v);
}

// round 14
// speedup vs baseline: 2.2087x; 1.2374x over previous
#include <cuda_runtime.h>
#include <cuda_bf16.h>
#include <math.h>
#include <stdint.h>

// ----------------------------------------------------------------------------
// Problem constants
//   T=32, B=32, TB=1024, NA=5, HID=256, FEAT=512, IN_DIM=517 (pad 544), FLAT=3136
// Output layout (22528 floats): logits[1024*5] | v[1024] | hT[32*256] | cT[32*256]
// ----------------------------------------------------------------------------

#define TBn 1024
#define KPAD 544    // padded IN_DIM for tf32 GEMM (multiple of 32)

// Scratch (device globals; no allocation allowed)
__device__ float g_x1[TBn * 32 * 20 * 20];   // conv1 out
__device__ float g_x2[TBn * 64 * 9 * 9];     // conv2 out
__device__ float g_x3[TBn * 3136];           // conv3 out (flatten, C,H,W)
__device__ float g_xs[TBn * KPAD];           // feat || one-hot || zero pad
__device__ float g_pre[TBn * 1024];          // x @ W_ih^T + b_ih + b_hh
__device__ float g_whhT[256 * 1024];         // W_hh transposed: [k][4*HID]
__device__ float g_wihp[1024 * KPAD];        // W_ih zero-padded to KPAD
__device__ float g_bsum[1024];               // b_ih + b_hh
__device__ float g_wp1T[256 * 64];           // Wp1 transposed [k][64]
__device__ float g_wv1T[256 * 64];           // Wv1 transposed [k][64]
__device__ float g_hs[TBn * 256];            // all h outputs
// bf16 hi/lo split conv weights, [oc][k/2] packed bf16x2 (k-even in low half)
__device__ unsigned g_w1h[32 * 96],  g_w1l[32 * 96];    // conv1 (scaled 1/255)
__device__ unsigned g_w2h[64 * 256], g_w2l[64 * 256];   // conv2
__device__ unsigned g_w3h[64 * 288], g_w3l[64 * 288];   // conv3
// im2col LUTs: src = in[img*IMG + lutk[k] + lutn[px]]
__device__ int g_lutk1[192], g_lutn1[400];
__device__ int g_lutk2[512], g_lutn2[81];
__device__ int g_lutk3[576], g_lutn3[49];

__device__ __forceinline__ float sigmoidf(float x) { return 1.0f / (1.0f + expf(-x)); }

__device__ __forceinline__ unsigned f2tf(float f) {
    unsigned u;
    asm("cvt.rna.tf32.f32 %0, %1;" : "=r"(u) : "f"(f));
    return u;
}

// pack two floats into bf16x2 hi + residual-lo (v0 in low half)
__device__ __forceinline__ void packhl(float v0, float v1, unsigned& h, unsigned& l) {
    __nv_bfloat162 h2 = __floats2bfloat162_rn(v0, v1);
    float l0 = v0 - __low2float(h2);
    float l1 = v1 - __high2float(h2);
    __nv_bfloat162 l2 = __floats2bfloat162_rn(l0, l1);
    h = *reinterpret_cast<unsigned*>(&h2);
    l = *reinterpret_cast<unsigned*>(&l2);
}

// ---- cluster / DSMEM helpers ----
__device__ __forceinline__ uint32_t smem_u32(const void* p) {
    uint32_t a;
    asm("{ .reg .u64 t; cvta.to.shared.u64 t, %1; cvt.u32.u64 %0, t; }"
        : "=r"(a) : "l"(p));
    return a;
}
__device__ __forceinline__ uint32_t mapa_rank(uint32_t saddr, uint32_t rank) {
    uint32_t r;
    asm("mapa.shared::cluster.u32 %0, %1, %2;" : "=r"(r) : "r"(saddr), "r"(rank));
    return r;
}
__device__ __forceinline__ void st_cluster_f32(uint32_t addr, float v) {
    asm volatile("st.shared::cluster.f32 [%0], %1;" :: "r"(addr), "f"(v) : "memory");
}
#define CLUSTER_SYNC() do { \
    asm volatile("barrier.cluster.arrive.aligned;" ::: "memory"); \
    asm volatile("barrier.cluster.wait.aligned;" ::: "memory"); \
} while (0)

// ----------------------------------------------------------------------------
// prep: transposes, bias sum, W_ih pad, conv weight bf16-split packs, LUTs
// ----------------------------------------------------------------------------
__global__ void prep_kernel(const float* __restrict__ W_hh,
                            const float* __restrict__ b_ih,
                            const float* __restrict__ b_hh,
                            const float* __restrict__ Wp1,
                            const float* __restrict__ Wv1,
                            const float* __restrict__ W1,
                            const float* __restrict__ W2,
                            const float* __restrict__ W3,
                            const float* __restrict__ W_ih) {
    int idx = blockIdx.x * blockDim.x + threadIdx.x;
    if (idx < 262144) {
        int j = idx >> 8, k = idx & 255;
        g_whhT[k * 1024 + j] = W_hh[idx];
    }
    if (idx < 16384) {
        int j = idx >> 8, k = idx & 255;
        g_wp1T[k * 64 + j] = Wp1[idx];
        g_wv1T[k * 64 + j] = Wv1[idx];
    }
    if (idx < 1024) g_bsum[idx] = b_ih[idx] + b_hh[idx];
    if (idx < 1024 * KPAD) {
        int row = idx / KPAD, col = idx % KPAD;
        g_wihp[idx] = (col < 517) ? W_ih[row * 517 + col] : 0.0f;
    }
    // conv weight packs (bf16 hi/lo pairs along k)
    if (idx < 32 * 96) {
        int oc = idx / 96, pk = idx % 96;
        float v0 = W1[oc * 192 + 2 * pk] * (1.0f / 255.0f);
        float v1 = W1[oc * 192 + 2 * pk + 1] * (1.0f / 255.0f);
        packhl(v0, v1, g_w1h[idx], g_w1l[idx]);
    }
    if (idx < 64 * 256) {
        int oc = idx >> 8, pk = idx & 255;
        packhl(W2[oc * 512 + 2 * pk], W2[oc * 512 + 2 * pk + 1],
               g_w2h[idx], g_w2l[idx]);
    }
    if (idx < 64 * 288) {
        int oc = idx / 288, pk = idx % 288;
        packhl(W3[oc * 576 + 2 * pk], W3[oc * 576 + 2 * pk + 1],
               g_w3h[idx], g_w3l[idx]);
    }
    // LUTs
    if (idx < 192) {
        int ic = idx >> 6, ky = (idx >> 3) & 7, kx = idx & 7;
        g_lutk1[idx] = ic * 7056 + ky * 84 + kx;
    }
    if (idx < 400) g_lutn1[idx] = (idx / 20) * 336 + (idx % 20) * 4;
    if (idx < 512) {
        int ic = idx >> 4, ky = (idx >> 2) & 3, kx = idx & 3;
        g_lutk2[idx] = ic * 400 + ky * 20 + kx;
    }
    if (idx < 81) g_lutn2[idx] = (idx / 9) * 40 + (idx % 9) * 2;
    if (idx < 576) {
        int ic = idx / 9, r = idx % 9;
        g_lutk3[idx] = ic * 81 + (r / 3) * 9 + (r % 3);
    }
    if (idx < 49) g_lutn3[idx] = (idx / 7) * 9 + (idx % 7);
}

// ----------------------------------------------------------------------------
// one-hot columns of xs (cols 512..516) + zero pad (517..543)
// ----------------------------------------------------------------------------
__global__ void onehot_kernel(const int* __restrict__ la) {
    int r = blockIdx.x * blockDim.x + threadIdx.x;
    if (r < TBn) {
        int a = la[r];
        float* p = g_xs + r * KPAD + 512;
#pragma unroll
        for (int j = 0; j < 5; j++) p[j] = (j == a) ? 1.0f : 0.0f;
#pragma unroll
        for (int j = 5; j < 32; j++) p[j] = 0.0f;
    }
}

// ----------------------------------------------------------------------------
// bf16 m16n8k16 mma
// ----------------------------------------------------------------------------
__device__ __forceinline__ void mma_bf16(float* c, const unsigned* a, const unsigned* b) {
    asm volatile(
        "mma.sync.aligned.m16n8k16.row.col.f32.bf16.bf16.f32 "
        "{%0,%1,%2,%3}, {%4,%5,%6,%7}, {%8,%9}, {%0,%1,%2,%3};\n"
        : "+f"(c[0]), "+f"(c[1]), "+f"(c[2]), "+f"(c[3])
        : "r"(a[0]), "r"(a[1]), "r"(a[2]), "r"(a[3]), "r"(b[0]), "r"(b[1]));
}

// ----------------------------------------------------------------------------
// Implicit-GEMM conv, bf16x3 (hi/lo split, lo*lo dropped ~ fp32 accuracy).
// C[row=(img,px)][oc] = sum_k im2col[row][k] * W[oc][k]; +bias, relu,
// stored transposed to out[img][oc][px].
// M = 1024*NPX (exactly divisible by 64), grid = M/64 blocks, 128 threads.
// A gathered from `in` via LUTs, split hi/lo at gather; W pre-split in prep.
// Double-buffered smem, register prefetch, one sync per 32-k chunk.
// ----------------------------------------------------------------------------
template<int OC, int NPX, int K, int IMG>
__global__ void __launch_bounds__(128)
conv_bf16_kernel(const float* __restrict__ in_ext, const float* __restrict__ bias) {
    constexpr int NCH = K / 32;
    constexpr int KP = K / 2;
    constexpr int MT = (OC == 64) ? 2 : 1;
    constexpr int BITS = (OC * 16) / 128;     // B elems per thread per chunk

    const float* in = (K == 192) ? in_ext : ((K == 512) ? (const float*)g_x1 : (const float*)g_x2);
    float* out = (K == 192) ? (float*)g_x1 : ((K == 512) ? (float*)g_x2 : (float*)g_x3);
    const int* lutk = (K == 192) ? g_lutk1 : ((K == 512) ? g_lutk2 : g_lutk3);
    const int* lutn = (K == 192) ? g_lutn1 : ((K == 512) ? g_lutn2 : g_lutn3);
    const unsigned* wh = (K == 192) ? g_w1h : ((K == 512) ? g_w2h : g_w3h);
    const unsigned* wl = (K == 192) ? g_w1l : ((K == 512) ? g_w2l : g_w3l);

    __shared__ unsigned Ah[2][64][18], Al[2][64][18];
    __shared__ unsigned Bh[2][OC][18], Bl[2][OC][18];

    int tid = threadIdx.x, lane = tid & 31, warp = tid >> 5;
    int wm = (OC == 64) ? ((warp & 1) * 32) : (warp * 16);
    int wn = (OC == 64) ? ((warp >> 1) * 32) : 0;
    int bm = blockIdx.x * 64;
    int trow = tid >> 4, tpk = tid & 15;

    float c[MT][4][4];
#pragma unroll
    for (int mt = 0; mt < MT; mt++)
#pragma unroll
        for (int nt = 0; nt < 4; nt++)
#pragma unroll
            for (int i = 0; i < 4; i++) c[mt][nt][i] = 0.0f;

    // prologue: chunk 0
    {
        int koff0 = __ldg(&lutk[2 * tpk]);
        int koff1 = __ldg(&lutk[2 * tpk + 1]);
#pragma unroll
        for (int it = 0; it < 8; it++) {
            int grow = bm + trow + 8 * it;
            int img = grow / NPX;
            int px = grow - img * NPX;
            int base = img * IMG + __ldg(&lutn[px]);
            float v0 = __ldg(&in[base + koff0]);
            float v1 = __ldg(&in[base + koff1]);
            unsigned h, l;
            packhl(v0, v1, h, l);
            Ah[0][trow + 8 * it][tpk] = h;
            Al[0][trow + 8 * it][tpk] = l;
        }
#pragma unroll
        for (int it = 0; it < BITS; it++) {
            int bidx = it * 128 + tid;
            int rrow = bidx >> 4, pk = bidx & 15;
            Bh[0][rrow][pk] = __ldg(&wh[rrow * KP + pk]);
            Bl[0][rrow][pk] = __ldg(&wl[rrow * KP + pk]);
        }
    }
    __syncthreads();

    for (int ch = 0; ch < NCH; ch++) {
        int buf = ch & 1;
        float va0[8], va1[8];
        unsigned vbh[BITS], vbl[BITS];
        if (ch + 1 < NCH) {
            int k0 = (ch + 1) * 32, kp0 = (ch + 1) * 16;
            int koff0 = __ldg(&lutk[k0 + 2 * tpk]);
            int koff1 = __ldg(&lutk[k0 + 2 * tpk + 1]);
#pragma unroll
            for (int it = 0; it < 8; it++) {
                int grow = bm + trow + 8 * it;
                int img = grow / NPX;
                int px = grow - img * NPX;
                int base = img * IMG + __ldg(&lutn[px]);
                va0[it] = __ldg(&in[base + koff0]);
                va1[it] = __ldg(&in[base + koff1]);
            }
#pragma unroll
            for (int it = 0; it < BITS; it++) {
                int bidx = it * 128 + tid;
                int rrow = bidx >> 4, pk = bidx & 15;
                vbh[it] = __ldg(&wh[rrow * KP + kp0 + pk]);
                vbl[it] = __ldg(&wl[rrow * KP + kp0 + pk]);
            }
        }

        int r = lane >> 2, q = lane & 3;
#pragma unroll
        for (int ks = 0; ks < 2; ks++) {
            unsigned ah[MT][4], al[MT][4];
#pragma unroll
            for (int mt = 0; mt < MT; mt++) {
                int mr = wm + mt * 16 + r;
                ah[mt][0] = Ah[buf][mr][ks * 8 + q];
                ah[mt][1] = Ah[buf][mr + 8][ks * 8 + q];
                ah[mt][2] = Ah[buf][mr][ks * 8 + q + 4];
                ah[mt][3] = Ah[buf][mr + 8][ks * 8 + q + 4];
                al[mt][0] = Al[buf][mr][ks * 8 + q];
                al[mt][1] = Al[buf][mr + 8][ks * 8 + q];
                al[mt][2] = Al[buf][mr][ks * 8 + q + 4];
                al[mt][3] = Al[buf][mr + 8][ks * 8 + q + 4];
            }
#pragma unroll
            for (int nt = 0; nt < 4; nt++) {
                int nc = wn + nt * 8 + r;
                unsigned bh2[2] = {Bh[buf][nc][ks * 8 + q], Bh[buf][nc][ks * 8 + q + 4]};
                unsigned bl2[2] = {Bl[buf][nc][ks * 8 + q], Bl[buf][nc][ks * 8 + q + 4]};
#pragma unroll
                for (int mt = 0; mt < MT; mt++) {
                    mma_bf16(c[mt][nt], ah[mt], bh2);
                    mma_bf16(c[mt][nt], ah[mt], bl2);
                    mma_bf16(c[mt][nt], al[mt], bh2);
                }
            }
        }

        if (ch + 1 < NCH) {
            int nbuf = buf ^ 1;
#pragma unroll
            for (int it = 0; it < 8; it++) {
                unsigned h, l;
                packhl(va0[it], va1[it], h, l);
                Ah[nbuf][trow + 8 * it][tpk] = h;
                Al[nbuf][trow + 8 * it][tpk] = l;
            }
#pragma unroll
            for (int it = 0; it < BITS; it++) {
                int bidx = it * 128 + tid;
                int rrow = bidx >> 4, pk = bidx & 15;
                Bh[nbuf][rrow][pk] = vbh[it];
                Bl[nbuf][rrow][pk] = vbl[it];
            }
        }
        __syncthreads();
    }

    // epilogue: transposed store out[img][oc][px], bias + relu
#pragma unroll
    for (int mt = 0; mt < MT; mt++) {
#pragma unroll
        for (int nt = 0; nt < 4; nt++) {
            int row = bm + wm + mt * 16 + (lane >> 2);
            int col = wn + nt * 8 + ((lane & 3) << 1);
            float b0 = __ldg(&bias[col]);
            float b1 = __ldg(&bias[col + 1]);
            int img0 = row / NPX, px0 = row - img0 * NPX;
            int row2 = row + 8;
            int img2 = row2 / NPX, px2 = row2 - img2 * NPX;
            out[img0 * (OC * NPX) + col * NPX + px0] = fmaxf(c[mt][nt][0] + b0, 0.0f);
            out[img0 * (OC * NPX) + (col + 1) * NPX + px0] = fmaxf(c[mt][nt][1] + b1, 0.0f);
            out[img2 * (OC * NPX) + col * NPX + px2] = fmaxf(c[mt][nt][2] + b0, 0.0f);
            out[img2 * (OC * NPX) + (col + 1) * NPX + px2] = fmaxf(c[mt][nt][3] + b1, 0.0f);
        }
    }
}

// ----------------------------------------------------------------------------
// tf32 tensor-core GEMM: C[M x N] = act(A[M x K] * B[N x K]^T + bias)
// ----------------------------------------------------------------------------
__device__ __forceinline__ void mma_tf32(float* c, const unsigned* a, const unsigned* b) {
    asm volatile(
        "mma.sync.aligned.m16n8k8.row.col.f32.tf32.tf32.f32 "
        "{%0,%1,%2,%3}, {%4,%5,%6,%7}, {%8,%9}, {%0,%1,%2,%3};\n"
        : "+f"(c[0]), "+f"(c[1]), "+f"(c[2]), "+f"(c[3])
        : "r"(a[0]), "r"(a[1]), "r"(a[2]), "r"(a[3]), "r"(b[0]), "r"(b[1]));
}

__device__ __forceinline__ void gemm_tf32(const float* __restrict__ A, int lda,
                                          const float* __restrict__ B, int ldb,
                                          const float* __restrict__ bias,
                                          float* __restrict__ C, int ldc,
                                          int K, bool relu) {
    __shared__ unsigned As[2][64][36];
    __shared__ unsigned Bs[2][64][36];
    int tid = threadIdx.x, lane = tid & 31, warp = tid >> 5;
    int bm = blockIdx.y * 64, bn = blockIdx.x * 64;
    int wm = (warp & 1) << 5, wn = (warp >> 1) << 5;

    float c[2][4][4];
#pragma unroll
    for (int mt = 0; mt < 2; mt++)
#pragma unroll
        for (int nt = 0; nt < 4; nt++)
#pragma unroll
            for (int i = 0; i < 4; i++) c[mt][nt][i] = 0.0f;

    int ntiles = K >> 5;
    float4 pa[4], pb[4];

#pragma unroll
    for (int i = 0; i < 4; i++) {
        int idx = tid + (i << 7);
        int row = idx >> 3, c4 = (idx & 7) << 2;
        pa[i] = *reinterpret_cast<const float4*>(A + (bm + row) * lda + c4);
        pb[i] = *reinterpret_cast<const float4*>(B + (bn + row) * ldb + c4);
    }
#pragma unroll
    for (int i = 0; i < 4; i++) {
        int idx = tid + (i << 7);
        int row = idx >> 3, c4 = (idx & 7) << 2;
        uint4 ta = {f2tf(pa[i].x), f2tf(pa[i].y), f2tf(pa[i].z), f2tf(pa[i].w)};
        uint4 tb = {f2tf(pb[i].x), f2tf(pb[i].y), f2tf(pb[i].z), f2tf(pb[i].w)};
        *reinterpret_cast<uint4*>(&As[0][row][c4]) = ta;
        *reinterpret_cast<uint4*>(&Bs[0][row][c4]) = tb;
    }
    __syncthreads();

    for (int t = 0; t < ntiles; t++) {
        int buf = t & 1;
        if (t + 1 < ntiles) {
            int k0 = (t + 1) << 5;
#pragma unroll
            for (int i = 0; i < 4; i++) {
                int idx = tid + (i << 7);
                int row = idx >> 3, c4 = (idx & 7) << 2;
                pa[i] = *reinterpret_cast<const float4*>(A + (bm + row) * lda + k0 + c4);
                pb[i] = *reinterpret_cast<const float4*>(B + (bn + row) * ldb + k0 + c4);
            }
        }
        int r = lane >> 2, q = lane & 3;
#pragma unroll
        for (int ks = 0; ks < 4; ks++) {
            unsigned a[2][4], b[4][2];
            int kc = ks << 3;
#pragma unroll
            for (int mt = 0; mt < 2; mt++) {
                int mr = wm + (mt << 4) + r;
                a[mt][0] = As[buf][mr][kc + q];
                a[mt][1] = As[buf][mr + 8][kc + q];
                a[mt][2] = As[buf][mr][kc + q + 4];
                a[mt][3] = As[buf][mr + 8][kc + q + 4];
            }
#pragma unroll
            for (int nt = 0; nt < 4; nt++) {
                int nr = wn + (nt << 3) + r;
                b[nt][0] = Bs[buf][nr][kc + q];
                b[nt][1] = Bs[buf][nr][kc + q + 4];
            }
#pragma unroll
            for (int mt = 0; mt < 2; mt++)
#pragma unroll
                for (int nt = 0; nt < 4; nt++)
                    mma_tf32(c[mt][nt], a[mt], b[nt]);
        }
        if (t + 1 < ntiles) {
            int nbuf = buf ^ 1;
#pragma unroll
            for (int i = 0; i < 4; i++) {
                int idx = tid + (i << 7);
                int row = idx >> 3, c4 = (idx & 7) << 2;
                uint4 ta = {f2tf(pa[i].x), f2tf(pa[i].y), f2tf(pa[i].z), f2tf(pa[i].w)};
                uint4 tb = {f2tf(pb[i].x), f2tf(pb[i].y), f2tf(pb[i].z), f2tf(pb[i].w)};
                *reinterpret_cast<uint4*>(&As[nbuf][row][c4]) = ta;
                *reinterpret_cast<uint4*>(&Bs[nbuf][row][c4]) = tb;
            }
            __syncthreads();
        }
    }

#pragma unroll
    for (int mt = 0; mt < 2; mt++) {
#pragma unroll
        for (int nt = 0; nt < 4; nt++) {
            int row = bm + wm + (mt << 4) + (lane >> 2);
            int col = bn + wn + (nt << 3) + ((lane & 3) << 1);
            float b0 = bias[col], b1 = bias[col + 1];
            float v0 = c[mt][nt][0] + b0;
            float v1 = c[mt][nt][1] + b1;
            float v2 = c[mt][nt][2] + b0;
            float v3 = c[mt][nt][3] + b1;
            if (relu) {
                v0 = fmaxf(v0, 0.0f); v1 = fmaxf(v1, 0.0f);
                v2 = fmaxf(v2, 0.0f); v3 = fmaxf(v3, 0.0f);
            }
            C[row * ldc + col] = v0;
            C[row * ldc + col + 1] = v1;
            C[(row + 8) * ldc + col] = v2;
            C[(row + 8) * ldc + col + 1] = v3;
        }
    }
}

__global__ void __launch_bounds__(128)
gemm_fc_kernel(const float* __restrict__ Wfc, const float* __restrict__ bfc) {
    gemm_tf32(g_x3, 3136, Wfc, 3136, bfc, g_xs, KPAD, 3136, true);
}

__global__ void __launch_bounds__(128)
gemm_pre_kernel() {
    gemm_tf32(g_xs, KPAD, g_wihp, KPAD, g_bsum, g_pre, 1024, KPAD, false);
}

// ----------------------------------------------------------------------------
// LSTM: 4 clusters x 8 CTAs, W_hh slice SMEM-resident, DSMEM gate exchange.
// Thread = (2 cols x 2 batches).
// ----------------------------------------------------------------------------
__global__ void __launch_bounds__(256, 1) __cluster_dims__(8, 1, 1)
lstm_kernel(const float* __restrict__ done,
            const float* __restrict__ h0,
            const float* __restrict__ c0,
            float* __restrict__ hT,
            float* __restrict__ cT) {
    extern __shared__ float sm[];
    float* wsl = sm;                    // 256*128 floats (weight slice)
    float* h_s = sm + 32768;            // 8*260 floats
    float* gbuf = h_s + 2080;           // 4*8*32 floats
    float* m_s = gbuf + 1024;           // 8 floats

    int tid = threadIdx.x;
    unsigned rank;
    asm("mov.u32 %0, %%cluster_ctarank;" : "=r"(rank));
    int cl = blockIdx.x >> 3;
    int bbase = cl * 8;

    {
        const float* src = g_whhT + 128 * (int)rank;
        for (int i = tid; i < 8192; i += 256) {
            int k = i >> 5, j4 = (i & 31) << 2;
            *reinterpret_cast<float4*>(&wsl[k * 128 + j4]) =
                *reinterpret_cast<const float4*>(&src[k * 1024 + j4]);
        }
    }
    for (int i = tid; i < 2048; i += 256) {
        int b = i >> 8, k = i & 255;
        h_s[b * 260 + k] = h0[(bbase + b) * 256 + k];
    }
    int ob = tid >> 5, os = tid & 31;
    int ou = 32 * (int)rank + os;
    float c_reg = c0[(bbase + ob) * 256 + ou];
    float hn = 0.0f;

    int jg2 = tid >> 2, bp = tid & 3;
    int jbase = 2 * jg2;
    int b0 = 2 * bp, b1 = b0 + 1;
    int gt = (int)rank >> 1;
    int ubase = ((128 * (int)rank) & 255) + jbase;
    uint32_t owner = (uint32_t)(ubase >> 5);
    uint32_t gbuf_a = smem_u32(gbuf);
    uint32_t h_a = smem_u32(h_s);
    uint32_t peer_gbuf = mapa_rank(gbuf_a, owner);
    uint32_t g0 = (uint32_t)(((gt * 8 + b0) * 32 + (ubase & 31)) * 4);
    uint32_t g1 = (uint32_t)(((gt * 8 + b1) * 32 + (ubase & 31)) * 4);
    uint32_t hpeer[8];
#pragma unroll
    for (int p = 0; p < 8; p++) hpeer[p] = mapa_rank(h_a, (uint32_t)p);
    uint32_t hoff = (uint32_t)((ob * 260 + ou) * 4);

    __syncthreads();
    CLUSTER_SYNC();

    for (int t = 0; t < 32; t++) {
        if (tid < 8) m_s[tid] = 1.0f - __ldg(&done[t * 32 + bbase + tid]);
        __syncthreads();
        for (int i = tid; i < 2048; i += 256) {
            int bb = i >> 8, k = i & 255;
            h_s[bb * 260 + k] *= m_s[bb];
        }
        c_reg *= m_s[ob];
        __syncthreads();

        int row0 = (t << 5) + bbase + b0;
        int row1 = row0 + 1;
        float2 a0 = *reinterpret_cast<const float2*>(
            g_pre + row0 * 1024 + 128 * (int)rank + jbase);
        float2 a1 = *reinterpret_cast<const float2*>(
            g_pre + row1 * 1024 + 128 * (int)rank + jbase);
        float acc00 = a0.x, acc01 = a0.y;
        float acc10 = a1.x, acc11 = a1.y;
        const float* hb0 = h_s + b0 * 260;
        const float* hb1 = h_s + b1 * 260;
#pragma unroll 8
        for (int k = 0; k < 256; k++) {
            float2 w = *reinterpret_cast<const float2*>(&wsl[k * 128 + jbase]);
            float h0k = hb0[k];
            float h1k = hb1[k];
            acc00 = fmaf(h0k, w.x, acc00);
            acc01 = fmaf(h0k, w.y, acc01);
            acc10 = fmaf(h1k, w.x, acc10);
            acc11 = fmaf(h1k, w.y, acc11);
        }
        st_cluster_f32(peer_gbuf + g0, acc00);
        st_cluster_f32(peer_gbuf + g0 + 4, acc01);
        st_cluster_f32(peer_gbuf + g1, acc10);
        st_cluster_f32(peer_gbuf + g1 + 4, acc11);
        CLUSTER_SYNC();

        {
            float gi = sigmoidf(gbuf[(0 * 8 + ob) * 32 + os]);
            float gf = sigmoidf(gbuf[(1 * 8 + ob) * 32 + os]);
            float gg = tanhf(gbuf[(2 * 8 + ob) * 32 + os]);
            float go = sigmoidf(gbuf[(3 * 8 + ob) * 32 + os]);
            c_reg = gf * c_reg + gi * gg;
            hn = go * tanhf(c_reg);
            g_hs[((t << 5) + bbase + ob) * 256 + ou] = hn;
#pragma unroll
            for (int p = 0; p < 8; p++) st_cluster_f32(hpeer[p] + hoff, hn);
        }
        CLUSTER_SYNC();
    }
    hT[(bbase + ob) * 256 + ou] = hn;
    cT[(bbase + ob) * 256 + ou] = c_reg;
}

// ----------------------------------------------------------------------------
// Heads: 8 rows per block; weights loaded once per k, 8 FMAs each.
// ----------------------------------------------------------------------------
__global__ void __launch_bounds__(128)
heads_kernel(const float* __restrict__ bp1,
             const float* __restrict__ Wp2,
             const float* __restrict__ bp2,
             const float* __restrict__ bv1,
             const float* __restrict__ Wv2,
             const float* __restrict__ bv2,
             float* __restrict__ logits,
             float* __restrict__ vout) {
    __shared__ float h_s[8][256];
    __shared__ float hp[8][64];
    __shared__ float hv[8][64];
    int r0 = blockIdx.x * 8, t = threadIdx.x;
    {
        const float4* g4 = reinterpret_cast<const float4*>(g_hs + r0 * 256);
        float4* s4 = reinterpret_cast<float4*>(&h_s[0][0]);
        for (int i = t; i < 512; i += 128) s4[i] = g4[i];
    }
    __syncthreads();

    if (t < 64) {
        float s[8];
#pragma unroll
        for (int r = 0; r < 8; r++) s[r] = bp1[t];
#pragma unroll 4
        for (int k = 0; k < 256; k++) {
            float w = __ldg(&g_wp1T[k * 64 + t]);
#pragma unroll
            for (int r = 0; r < 8; r++) s[r] = fmaf(h_s[r][k], w, s[r]);
        }
#pragma unroll
        for (int r = 0; r < 8; r++) hp[r][t] = tanhf(s[r]);
    } else {
        int j = t - 64;
        float s[8];
#pragma unroll
        for (int r = 0; r < 8; r++) s[r] = bv1[j];
#pragma unroll 4
        for (int k = 0; k < 256; k++) {
            float w = __ldg(&g_wv1T[k * 64 + j]);
#pragma unroll
            for (int r = 0; r < 8; r++) s[r] = fmaf(h_s[r][k], w, s[r]);
        }
#pragma unroll
        for (int r = 0; r < 8; r++) hv[r][j] = tanhf(s[r]);
    }
    __syncthreads();

    if (t < 40) {
        int r = t / 5, a = t % 5;
        float s = bp2[a];
#pragma unroll
        for (int k = 0; k < 64; k++) s = fmaf(hp[r][k], Wp2[a * 64 + k], s);
        logits[(r0 + r) * 5 + a] = s;
    }
    if (t >= 64 && t < 72) {
        int r = t - 64;
        float s = bv2[0];
#pragma unroll
        for (int k = 0; k < 64; k++) s = fmaf(hv[r][k], Wv2[k], s);
        vout[r0 + r] = s;
    }
}

// ----------------------------------------------------------------------------
// Launch
// ----------------------------------------------------------------------------
extern "C" void kernel_launch(void* const* d_in, const int* in_sizes, int n_in,
                              void* d_out, int out_size) {
    const float* image = (const float*)d_in[0];
    const int* la = (const int*)d_in[1];
    const float* done = (const float*)d_in[2];
    const float* h0 = (const float*)d_in[3];
    const float* c0 = (const float*)d_in[4];
    const float* W1 = (const float*)d_in[5];
    const float* b1 = (const float*)d_in[6];
    const float* W2 = (const float*)d_in[7];
    const float* b2 = (const float*)d_in[8];
    const float* W3 = (const float*)d_in[9];
    const float* b3 = (const float*)d_in[10];
    const float* Wfc = (const float*)d_in[11];
    const float* bfc = (const float*)d_in[12];
    const float* W_ih = (const float*)d_in[13];
    const float* W_hh = (const float*)d_in[14];
    const float* b_ih = (const float*)d_in[15];
    const float* b_hh = (const float*)d_in[16];
    const float* Wp1 = (const float*)d_in[17];
    const float* bp1 = (const float*)d_in[18];
    const float* Wp2 = (const float*)d_in[19];
    const float* bp2 = (const float*)d_in[20];
    const float* Wv1 = (const float*)d_in[21];
    const float* bv1 = (const float*)d_in[22];
    const float* Wv2 = (const float*)d_in[23];
    const float* bv2 = (const float*)d_in[24];

    float* out = (float*)d_out;
    float* o_logits = out;           // 5120
    float* o_v = out + 5120;         // 1024
    float* o_hT = out + 6144;        // 8192
    float* o_cT = out + 14336;       // 8192

    const int SMEML = (32768 + 2080 + 1024 + 8) * 4;  // 143520
    cudaFuncSetAttribute(lstm_kernel, cudaFuncAttributeMaxDynamicSharedMemorySize, SMEML);

    prep_kernel<<<2176, 256>>>(W_hh, b_ih, b_hh, Wp1, Wv1, W1, W2, W3, W_ih);
    conv_bf16_kernel<32, 400, 192, 21168><<<6400, 128>>>(image, b1);
    conv_bf16_kernel<64, 81, 512, 12800><<<1296, 128>>>(nullptr, b2);
    conv_bf16_kernel<64, 49, 576, 5184><<<784, 128>>>(nullptr, b3);
    gemm_fc_kernel<<<dim3(512 / 64, 1024 / 64), 128>>>(Wfc, bfc);
    onehot_kernel<<<4, 256>>>(la);
    gemm_pre_kernel<<<dim3(1024 / 64, 1024 / 64), 128>>>();
    lstm_kernel<<<32, 256, SMEML>>>(done, h0, c0, o_hT, o_cT);
    heads_kernel<<<128, 128>>>(bp1, Wp2, bp2, bv1, Wv2, bv2, o_logits, o_v);
}

// round 15
// speedup vs baseline: 2.2167x; 1.0036x over previous
#include <cuda_runtime.h>
#include <cuda_bf16.h>
#include <math.h>
#include <stdint.h>

// ----------------------------------------------------------------------------
// Problem constants
//   T=32, B=32, TB=1024, NA=5, HID=256, FEAT=512, IN_DIM=517 (pad 544), FLAT=3136
// Output layout (22528 floats): logits[1024*5] | v[1024] | hT[32*256] | cT[32*256]
// ----------------------------------------------------------------------------

#define TBn 1024
#define KPAD 544    // padded IN_DIM for tf32 GEMM (multiple of 32)

// Scratch (device globals; no allocation allowed)
__device__ float g_x1[TBn * 32 * 20 * 20];   // conv1 out
__device__ float g_x2[TBn * 64 * 9 * 9];     // conv2 out
__device__ float g_x3[TBn * 3136];           // conv3 out (flatten, C,H,W)
__device__ float g_xs[TBn * KPAD];           // feat || one-hot || zero pad
__device__ float g_pre[TBn * 1024];          // x @ W_ih^T + b_ih + b_hh
__device__ float g_whhT[256 * 1024];         // W_hh transposed: [k][4*HID]
__device__ float g_wihp[1024 * KPAD];        // W_ih zero-padded to KPAD
__device__ float g_bsum[1024];               // b_ih + b_hh
__device__ float g_wp1T[256 * 64];           // Wp1 transposed [k][64]
__device__ float g_wv1T[256 * 64];           // Wv1 transposed [k][64]
__device__ float g_hs[TBn * 256];            // all h outputs
// bf16 hi/lo split conv weights, [oc][k/2] packed bf16x2 (k-even in low half)
__device__ unsigned g_w1h[32 * 96],  g_w1l[32 * 96];    // conv1 (scaled 1/255)
__device__ unsigned g_w2h[64 * 256], g_w2l[64 * 256];   // conv2
__device__ unsigned g_w3h[64 * 288], g_w3l[64 * 288];   // conv3
// im2col LUTs: src = in[img*IMG + lutk[k] + lutn[px]]
__device__ int g_lutk1[192], g_lutn1[400];
__device__ int g_lutk2[512], g_lutn2[81];
__device__ int g_lutk3[576], g_lutn3[49];

__device__ __forceinline__ float sigmoidf(float x) { return 1.0f / (1.0f + expf(-x)); }

__device__ __forceinline__ unsigned f2tf(float f) {
    unsigned u;
    asm("cvt.rna.tf32.f32 %0, %1;" : "=r"(u) : "f"(f));
    return u;
}

// pack two floats into bf16x2 hi + residual-lo (v0 in low half)
__device__ __forceinline__ void packhl(float v0, float v1, unsigned& h, unsigned& l) {
    __nv_bfloat162 h2 = __floats2bfloat162_rn(v0, v1);
    float l0 = v0 - __low2float(h2);
    float l1 = v1 - __high2float(h2);
    __nv_bfloat162 l2 = __floats2bfloat162_rn(l0, l1);
    h = *reinterpret_cast<unsigned*>(&h2);
    l = *reinterpret_cast<unsigned*>(&l2);
}

// ---- cluster / DSMEM helpers ----
__device__ __forceinline__ uint32_t smem_u32(const void* p) {
    uint32_t a;
    asm("{ .reg .u64 t; cvta.to.shared.u64 t, %1; cvt.u32.u64 %0, t; }"
        : "=r"(a) : "l"(p));
    return a;
}
__device__ __forceinline__ uint32_t mapa_rank(uint32_t saddr, uint32_t rank) {
    uint32_t r;
    asm("mapa.shared::cluster.u32 %0, %1, %2;" : "=r"(r) : "r"(saddr), "r"(rank));
    return r;
}
__device__ __forceinline__ void st_cluster_f32(uint32_t addr, float v) {
    asm volatile("st.shared::cluster.f32 [%0], %1;" :: "r"(addr), "f"(v) : "memory");
}
#define CLUSTER_SYNC() do { \
    asm volatile("barrier.cluster.arrive.aligned;" ::: "memory"); \
    asm volatile("barrier.cluster.wait.aligned;" ::: "memory"); \
} while (0)

// ----------------------------------------------------------------------------
// prep: transposes, bias sum, W_ih pad, conv weight bf16-split packs, LUTs
// ----------------------------------------------------------------------------
__global__ void prep_kernel(const float* __restrict__ W_hh,
                            const float* __restrict__ b_ih,
                            const float* __restrict__ b_hh,
                            const float* __restrict__ Wp1,
                            const float* __restrict__ Wv1,
                            const float* __restrict__ W1,
                            const float* __restrict__ W2,
                            const float* __restrict__ W3,
                            const float* __restrict__ W_ih) {
    int idx = blockIdx.x * blockDim.x + threadIdx.x;
    if (idx < 262144) {
        int j = idx >> 8, k = idx & 255;
        g_whhT[k * 1024 + j] = W_hh[idx];
    }
    if (idx < 16384) {
        int j = idx >> 8, k = idx & 255;
        g_wp1T[k * 64 + j] = Wp1[idx];
        g_wv1T[k * 64 + j] = Wv1[idx];
    }
    if (idx < 1024) g_bsum[idx] = b_ih[idx] + b_hh[idx];
    if (idx < 1024 * KPAD) {
        int row = idx / KPAD, col = idx % KPAD;
        g_wihp[idx] = (col < 517) ? W_ih[row * 517 + col] : 0.0f;
    }
    // conv weight packs (bf16 hi/lo pairs along k)
    if (idx < 32 * 96) {
        int oc = idx / 96, pk = idx % 96;
        float v0 = W1[oc * 192 + 2 * pk] * (1.0f / 255.0f);
        float v1 = W1[oc * 192 + 2 * pk + 1] * (1.0f / 255.0f);
        packhl(v0, v1, g_w1h[idx], g_w1l[idx]);
    }
    if (idx < 64 * 256) {
        int oc = idx >> 8, pk = idx & 255;
        packhl(W2[oc * 512 + 2 * pk], W2[oc * 512 + 2 * pk + 1],
               g_w2h[idx], g_w2l[idx]);
    }
    if (idx < 64 * 288) {
        int oc = idx / 288, pk = idx % 288;
        packhl(W3[oc * 576 + 2 * pk], W3[oc * 576 + 2 * pk + 1],
               g_w3h[idx], g_w3l[idx]);
    }
    // LUTs
    if (idx < 192) {
        int ic = idx >> 6, ky = (idx >> 3) & 7, kx = idx & 7;
        g_lutk1[idx] = ic * 7056 + ky * 84 + kx;
    }
    if (idx < 400) g_lutn1[idx] = (idx / 20) * 336 + (idx % 20) * 4;
    if (idx < 512) {
        int ic = idx >> 4, ky = (idx >> 2) & 3, kx = idx & 3;
        g_lutk2[idx] = ic * 400 + ky * 20 + kx;
    }
    if (idx < 81) g_lutn2[idx] = (idx / 9) * 40 + (idx % 9) * 2;
    if (idx < 576) {
        int ic = idx / 9, r = idx % 9;
        g_lutk3[idx] = ic * 81 + (r / 3) * 9 + (r % 3);
    }
    if (idx < 49) g_lutn3[idx] = (idx / 7) * 9 + (idx % 7);
}

// ----------------------------------------------------------------------------
// one-hot columns of xs (cols 512..516) + zero pad (517..543)
// ----------------------------------------------------------------------------
__global__ void onehot_kernel(const int* __restrict__ la) {
    int r = blockIdx.x * blockDim.x + threadIdx.x;
    if (r < TBn) {
        int a = la[r];
        float* p = g_xs + r * KPAD + 512;
#pragma unroll
        for (int j = 0; j < 5; j++) p[j] = (j == a) ? 1.0f : 0.0f;
#pragma unroll
        for (int j = 5; j < 32; j++) p[j] = 0.0f;
    }
}

// ----------------------------------------------------------------------------
// bf16 m16n8k16 mma
// ----------------------------------------------------------------------------
__device__ __forceinline__ void mma_bf16(float* c, const unsigned* a, const unsigned* b) {
    asm volatile(
        "mma.sync.aligned.m16n8k16.row.col.f32.bf16.bf16.f32 "
        "{%0,%1,%2,%3}, {%4,%5,%6,%7}, {%8,%9}, {%0,%1,%2,%3};\n"
        : "+f"(c[0]), "+f"(c[1]), "+f"(c[2]), "+f"(c[3])
        : "r"(a[0]), "r"(a[1]), "r"(a[2]), "r"(a[3]), "r"(b[0]), "r"(b[1]));
}

// ----------------------------------------------------------------------------
// Implicit-GEMM conv, bf16x3 (hi/lo split, lo*lo dropped ~ fp32 accuracy).
// C[row=(img,px)][oc]; BM=128 rows/block, 256 threads (8 warps).
// OC=64: warps 4(M)x2(N), 32x32 tiles. OC=32: 8 M-warps of 16 rows.
// Row base addresses hoisted out of the k-chunk loop (chunk-invariant).
// ----------------------------------------------------------------------------
template<int OC, int NPX, int K, int IMG>
__global__ void __launch_bounds__(256)
conv_bf16_kernel(const float* __restrict__ in_ext, const float* __restrict__ bias) {
    constexpr int NCH = K / 32;
    constexpr int KP = K / 2;
    constexpr int MT = (OC == 64) ? 2 : 1;
    constexpr int BITS = (OC * 16) / 256;     // B elems per thread per chunk

    const float* in = (K == 192) ? in_ext : ((K == 512) ? (const float*)g_x1 : (const float*)g_x2);
    float* out = (K == 192) ? (float*)g_x1 : ((K == 512) ? (float*)g_x2 : (float*)g_x3);
    const int* lutk = (K == 192) ? g_lutk1 : ((K == 512) ? g_lutk2 : g_lutk3);
    const int* lutn = (K == 192) ? g_lutn1 : ((K == 512) ? g_lutn2 : g_lutn3);
    const unsigned* wh = (K == 192) ? g_w1h : ((K == 512) ? g_w2h : g_w3h);
    const unsigned* wl = (K == 192) ? g_w1l : ((K == 512) ? g_w2l : g_w3l);

    __shared__ unsigned Ah[2][128][18], Al[2][128][18];
    __shared__ unsigned Bh[2][OC][18], Bl[2][OC][18];

    int tid = threadIdx.x, lane = tid & 31, warp = tid >> 5;
    int wm = (OC == 64) ? ((warp & 3) * 32) : (warp * 16);
    int wn = (OC == 64) ? ((warp >> 2) * 32) : 0;
    int bm = blockIdx.x * 128;
    int trow = tid >> 4, tpk = tid & 15;      // trow 0..15, 8 row-slots each

    // hoisted per-row gather bases (chunk-invariant)
    int base[8];
#pragma unroll
    for (int it = 0; it < 8; it++) {
        int grow = bm + trow + 16 * it;
        int img = grow / NPX;
        int px = grow - img * NPX;
        base[it] = img * IMG + __ldg(&lutn[px]);
    }

    float c[MT][4][4];
#pragma unroll
    for (int mt = 0; mt < MT; mt++)
#pragma unroll
        for (int nt = 0; nt < 4; nt++)
#pragma unroll
            for (int i = 0; i < 4; i++) c[mt][nt][i] = 0.0f;

    // prologue: chunk 0
    {
        int koff0 = __ldg(&lutk[2 * tpk]);
        int koff1 = __ldg(&lutk[2 * tpk + 1]);
#pragma unroll
        for (int it = 0; it < 8; it++) {
            float v0 = __ldg(&in[base[it] + koff0]);
            float v1 = __ldg(&in[base[it] + koff1]);
            unsigned h, l;
            packhl(v0, v1, h, l);
            Ah[0][trow + 16 * it][tpk] = h;
            Al[0][trow + 16 * it][tpk] = l;
        }
#pragma unroll
        for (int it = 0; it < BITS; it++) {
            int bidx = it * 256 + tid;
            int rrow = bidx >> 4, pk = bidx & 15;
            Bh[0][rrow][pk] = __ldg(&wh[rrow * KP + pk]);
            Bl[0][rrow][pk] = __ldg(&wl[rrow * KP + pk]);
        }
    }
    __syncthreads();

    for (int ch = 0; ch < NCH; ch++) {
        int buf = ch & 1;
        float va0[8], va1[8];
        unsigned vbh[BITS], vbl[BITS];
        if (ch + 1 < NCH) {
            int k0 = (ch + 1) * 32, kp0 = (ch + 1) * 16;
            int koff0 = __ldg(&lutk[k0 + 2 * tpk]);
            int koff1 = __ldg(&lutk[k0 + 2 * tpk + 1]);
#pragma unroll
            for (int it = 0; it < 8; it++) {
                va0[it] = __ldg(&in[base[it] + koff0]);
                va1[it] = __ldg(&in[base[it] + koff1]);
            }
#pragma unroll
            for (int it = 0; it < BITS; it++) {
                int bidx = it * 256 + tid;
                int rrow = bidx >> 4, pk = bidx & 15;
                vbh[it] = __ldg(&wh[rrow * KP + kp0 + pk]);
                vbl[it] = __ldg(&wl[rrow * KP + kp0 + pk]);
            }
        }

        int r = lane >> 2, q = lane & 3;
#pragma unroll
        for (int ks = 0; ks < 2; ks++) {
            unsigned ah[MT][4], al[MT][4];
#pragma unroll
            for (int mt = 0; mt < MT; mt++) {
                int mr = wm + mt * 16 + r;
                ah[mt][0] = Ah[buf][mr][ks * 8 + q];
                ah[mt][1] = Ah[buf][mr + 8][ks * 8 + q];
                ah[mt][2] = Ah[buf][mr][ks * 8 + q + 4];
                ah[mt][3] = Ah[buf][mr + 8][ks * 8 + q + 4];
                al[mt][0] = Al[buf][mr][ks * 8 + q];
                al[mt][1] = Al[buf][mr + 8][ks * 8 + q];
                al[mt][2] = Al[buf][mr][ks * 8 + q + 4];
                al[mt][3] = Al[buf][mr + 8][ks * 8 + q + 4];
            }
#pragma unroll
            for (int nt = 0; nt < 4; nt++) {
                int nc = wn + nt * 8 + r;
                unsigned bh2[2] = {Bh[buf][nc][ks * 8 + q], Bh[buf][nc][ks * 8 + q + 4]};
                unsigned bl2[2] = {Bl[buf][nc][ks * 8 + q], Bl[buf][nc][ks * 8 + q + 4]};
#pragma unroll
                for (int mt = 0; mt < MT; mt++) {
                    mma_bf16(c[mt][nt], ah[mt], bh2);
                    mma_bf16(c[mt][nt], ah[mt], bl2);
                    mma_bf16(c[mt][nt], al[mt], bh2);
                }
            }
        }

        if (ch + 1 < NCH) {
            int nbuf = buf ^ 1;
#pragma unroll
            for (int it = 0; it < 8; it++) {
                unsigned h, l;
                packhl(va0[it], va1[it], h, l);
                Ah[nbuf][trow + 16 * it][tpk] = h;
                Al[nbuf][trow + 16 * it][tpk] = l;
            }
#pragma unroll
            for (int it = 0; it < BITS; it++) {
                int bidx = it * 256 + tid;
                int rrow = bidx >> 4, pk = bidx & 15;
                Bh[nbuf][rrow][pk] = vbh[it];
                Bl[nbuf][rrow][pk] = vbl[it];
            }
        }
        __syncthreads();
    }

    // epilogue: transposed store out[img][oc][px], bias + relu
#pragma unroll
    for (int mt = 0; mt < MT; mt++) {
#pragma unroll
        for (int nt = 0; nt < 4; nt++) {
            int row = bm + wm + mt * 16 + (lane >> 2);
            int col = wn + nt * 8 + ((lane & 3) << 1);
            float b0 = __ldg(&bias[col]);
            float b1 = __ldg(&bias[col + 1]);
            int img0 = row / NPX, px0 = row - img0 * NPX;
            int row2 = row + 8;
            int img2 = row2 / NPX, px2 = row2 - img2 * NPX;
            out[img0 * (OC * NPX) + col * NPX + px0] = fmaxf(c[mt][nt][0] + b0, 0.0f);
            out[img0 * (OC * NPX) + (col + 1) * NPX + px0] = fmaxf(c[mt][nt][1] + b1, 0.0f);
            out[img2 * (OC * NPX) + col * NPX + px2] = fmaxf(c[mt][nt][2] + b0, 0.0f);
            out[img2 * (OC * NPX) + (col + 1) * NPX + px2] = fmaxf(c[mt][nt][3] + b1, 0.0f);
        }
    }
}

// ----------------------------------------------------------------------------
// tf32 tensor-core GEMM: C[M x N] = act(A[M x K] * B[N x K]^T + bias)
// ----------------------------------------------------------------------------
__device__ __forceinline__ void mma_tf32(float* c, const unsigned* a, const unsigned* b) {
    asm volatile(
        "mma.sync.aligned.m16n8k8.row.col.f32.tf32.tf32.f32 "
        "{%0,%1,%2,%3}, {%4,%5,%6,%7}, {%8,%9}, {%0,%1,%2,%3};\n"
        : "+f"(c[0]), "+f"(c[1]), "+f"(c[2]), "+f"(c[3])
        : "r"(a[0]), "r"(a[1]), "r"(a[2]), "r"(a[3]), "r"(b[0]), "r"(b[1]));
}

__device__ __forceinline__ void gemm_tf32(const float* __restrict__ A, int lda,
                                          const float* __restrict__ B, int ldb,
                                          const float* __restrict__ bias,
                                          float* __restrict__ C, int ldc,
                                          int K, bool relu) {
    __shared__ unsigned As[2][64][36];
    __shared__ unsigned Bs[2][64][36];
    int tid = threadIdx.x, lane = tid & 31, warp = tid >> 5;
    int bm = blockIdx.y * 64, bn = blockIdx.x * 64;
    int wm = (warp & 1) << 5, wn = (warp >> 1) << 5;

    float c[2][4][4];
#pragma unroll
    for (int mt = 0; mt < 2; mt++)
#pragma unroll
        for (int nt = 0; nt < 4; nt++)
#pragma unroll
            for (int i = 0; i < 4; i++) c[mt][nt][i] = 0.0f;

    int ntiles = K >> 5;
    float4 pa[4], pb[4];

#pragma unroll
    for (int i = 0; i < 4; i++) {
        int idx = tid + (i << 7);
        int row = idx >> 3, c4 = (idx & 7) << 2;
        pa[i] = *reinterpret_cast<const float4*>(A + (bm + row) * lda + c4);
        pb[i] = *reinterpret_cast<const float4*>(B + (bn + row) * ldb + c4);
    }
#pragma unroll
    for (int i = 0; i < 4; i++) {
        int idx = tid + (i << 7);
        int row = idx >> 3, c4 = (idx & 7) << 2;
        uint4 ta = {f2tf(pa[i].x), f2tf(pa[i].y), f2tf(pa[i].z), f2tf(pa[i].w)};
        uint4 tb = {f2tf(pb[i].x), f2tf(pb[i].y), f2tf(pb[i].z), f2tf(pb[i].w)};
        *reinterpret_cast<uint4*>(&As[0][row][c4]) = ta;
        *reinterpret_cast<uint4*>(&Bs[0][row][c4]) = tb;
    }
    __syncthreads();

    for (int t = 0; t < ntiles; t++) {
        int buf = t & 1;
        if (t + 1 < ntiles) {
            int k0 = (t + 1) << 5;
#pragma unroll
            for (int i = 0; i < 4; i++) {
                int idx = tid + (i << 7);
                int row = idx >> 3, c4 = (idx & 7) << 2;
                pa[i] = *reinterpret_cast<const float4*>(A + (bm + row) * lda + k0 + c4);
                pb[i] = *reinterpret_cast<const float4*>(B + (bn + row) * ldb + k0 + c4);
            }
        }
        int r = lane >> 2, q = lane & 3;
#pragma unroll
        for (int ks = 0; ks < 4; ks++) {
            unsigned a[2][4], b[4][2];
            int kc = ks << 3;
#pragma unroll
            for (int mt = 0; mt < 2; mt++) {
                int mr = wm + (mt << 4) + r;
                a[mt][0] = As[buf][mr][kc + q];
                a[mt][1] = As[buf][mr + 8][kc + q];
                a[mt][2] = As[buf][mr][kc + q + 4];
                a[mt][3] = As[buf][mr + 8][kc + q + 4];
            }
#pragma unroll
            for (int nt = 0; nt < 4; nt++) {
                int nr = wn + (nt << 3) + r;
                b[nt][0] = Bs[buf][nr][kc + q];
                b[nt][1] = Bs[buf][nr][kc + q + 4];
            }
#pragma unroll
            for (int mt = 0; mt < 2; mt++)
#pragma unroll
                for (int nt = 0; nt < 4; nt++)
                    mma_tf32(c[mt][nt], a[mt], b[nt]);
        }
        if (t + 1 < ntiles) {
            int nbuf = buf ^ 1;
#pragma unroll
            for (int i = 0; i < 4; i++) {
                int idx = tid + (i << 7);
                int row = idx >> 3, c4 = (idx & 7) << 2;
                uint4 ta = {f2tf(pa[i].x), f2tf(pa[i].y), f2tf(pa[i].z), f2tf(pa[i].w)};
                uint4 tb = {f2tf(pb[i].x), f2tf(pb[i].y), f2tf(pb[i].z), f2tf(pb[i].w)};
                *reinterpret_cast<uint4*>(&As[nbuf][row][c4]) = ta;
                *reinterpret_cast<uint4*>(&Bs[nbuf][row][c4]) = tb;
            }
            __syncthreads();
        }
    }

#pragma unroll
    for (int mt = 0; mt < 2; mt++) {
#pragma unroll
        for (int nt = 0; nt < 4; nt++) {
            int row = bm + wm + (mt << 4) + (lane >> 2);
            int col = bn + wn + (nt << 3) + ((lane & 3) << 1);
            float b0 = bias[col], b1 = bias[col + 1];
            float v0 = c[mt][nt][0] + b0;
            float v1 = c[mt][nt][1] + b1;
            float v2 = c[mt][nt][2] + b0;
            float v3 = c[mt][nt][3] + b1;
            if (relu) {
                v0 = fmaxf(v0, 0.0f); v1 = fmaxf(v1, 0.0f);
                v2 = fmaxf(v2, 0.0f); v3 = fmaxf(v3, 0.0f);
            }
            C[row * ldc + col] = v0;
            C[row * ldc + col + 1] = v1;
            C[(row + 8) * ldc + col] = v2;
            C[(row + 8) * ldc + col + 1] = v3;
        }
    }
}

__global__ void __launch_bounds__(128)
gemm_fc_kernel(const float* __restrict__ Wfc, const float* __restrict__ bfc) {
    gemm_tf32(g_x3, 3136, Wfc, 3136, bfc, g_xs, KPAD, 3136, true);
}

__global__ void __launch_bounds__(128)
gemm_pre_kernel() {
    gemm_tf32(g_xs, KPAD, g_wihp, KPAD, g_bsum, g_pre, 1024, KPAD, false);
}

// ----------------------------------------------------------------------------
// LSTM: 4 clusters x 8 CTAs, W_hh slice SMEM-resident, DSMEM gate exchange.
// Thread = (2 cols x 2 batches).
// ----------------------------------------------------------------------------
__global__ void __launch_bounds__(256, 1) __cluster_dims__(8, 1, 1)
lstm_kernel(const float* __restrict__ done,
            const float* __restrict__ h0,
            const float* __restrict__ c0,
            float* __restrict__ hT,
            float* __restrict__ cT) {
    extern __shared__ float sm[];
    float* wsl = sm;                    // 256*128 floats (weight slice)
    float* h_s = sm + 32768;            // 8*260 floats
    float* gbuf = h_s + 2080;           // 4*8*32 floats
    float* m_s = gbuf + 1024;           // 8 floats

    int tid = threadIdx.x;
    unsigned rank;
    asm("mov.u32 %0, %%cluster_ctarank;" : "=r"(rank));
    int cl = blockIdx.x >> 3;
    int bbase = cl * 8;

    {
        const float* src = g_whhT + 128 * (int)rank;
        for (int i = tid; i < 8192; i += 256) {
            int k = i >> 5, j4 = (i & 31) << 2;
            *reinterpret_cast<float4*>(&wsl[k * 128 + j4]) =
                *reinterpret_cast<const float4*>(&src[k * 1024 + j4]);
        }
    }
    for (int i = tid; i < 2048; i += 256) {
        int b = i >> 8, k = i & 255;
        h_s[b * 260 + k] = h0[(bbase + b) * 256 + k];
    }
    int ob = tid >> 5, os = tid & 31;
    int ou = 32 * (int)rank + os;
    float c_reg = c0[(bbase + ob) * 256 + ou];
    float hn = 0.0f;

    int jg2 = tid >> 2, bp = tid & 3;
    int jbase = 2 * jg2;
    int b0 = 2 * bp, b1 = b0 + 1;
    int gt = (int)rank >> 1;
    int ubase = ((128 * (int)rank) & 255) + jbase;
    uint32_t owner = (uint32_t)(ubase >> 5);
    uint32_t gbuf_a = smem_u32(gbuf);
    uint32_t h_a = smem_u32(h_s);
    uint32_t peer_gbuf = mapa_rank(gbuf_a, owner);
    uint32_t g0 = (uint32_t)(((gt * 8 + b0) * 32 + (ubase & 31)) * 4);
    uint32_t g1 = (uint32_t)(((gt * 8 + b1) * 32 + (ubase & 31)) * 4);
    uint32_t hpeer[8];
#pragma unroll
    for (int p = 0; p < 8; p++) hpeer[p] = mapa_rank(h_a, (uint32_t)p);
    uint32_t hoff = (uint32_t)((ob * 260 + ou) * 4);

    __syncthreads();
    CLUSTER_SYNC();

    for (int t = 0; t < 32; t++) {
        if (tid < 8) m_s[tid] = 1.0f - __ldg(&done[t * 32 + bbase + tid]);
        __syncthreads();
        for (int i = tid; i < 2048; i += 256) {
            int bb = i >> 8, k = i & 255;
            h_s[bb * 260 + k] *= m_s[bb];
        }
        c_reg *= m_s[ob];
        __syncthreads();

        int row0 = (t << 5) + bbase + b0;
        int row1 = row0 + 1;
        float2 a0 = *reinterpret_cast<const float2*>(
            g_pre + row0 * 1024 + 128 * (int)rank + jbase);
        float2 a1 = *reinterpret_cast<const float2*>(
            g_pre + row1 * 1024 + 128 * (int)rank + jbase);
        float acc00 = a0.x, acc01 = a0.y;
        float acc10 = a1.x, acc11 = a1.y;
        const float* hb0 = h_s + b0 * 260;
        const float* hb1 = h_s + b1 * 260;
#pragma unroll 8
        for (int k = 0; k < 256; k++) {
            float2 w = *reinterpret_cast<const float2*>(&wsl[k * 128 + jbase]);
            float h0k = hb0[k];
            float h1k = hb1[k];
            acc00 = fmaf(h0k, w.x, acc00);
            acc01 = fmaf(h0k, w.y, acc01);
            acc10 = fmaf(h1k, w.x, acc10);
            acc11 = fmaf(h1k, w.y, acc11);
        }
        st_cluster_f32(peer_gbuf + g0, acc00);
        st_cluster_f32(peer_gbuf + g0 + 4, acc01);
        st_cluster_f32(peer_gbuf + g1, acc10);
        st_cluster_f32(peer_gbuf + g1 + 4, acc11);
        CLUSTER_SYNC();

        {
            float gi = sigmoidf(gbuf[(0 * 8 + ob) * 32 + os]);
            float gf = sigmoidf(gbuf[(1 * 8 + ob) * 32 + os]);
            float gg = tanhf(gbuf[(2 * 8 + ob) * 32 + os]);
            float go = sigmoidf(gbuf[(3 * 8 + ob) * 32 + os]);
            c_reg = gf * c_reg + gi * gg;
            hn = go * tanhf(c_reg);
            g_hs[((t << 5) + bbase + ob) * 256 + ou] = hn;
#pragma unroll
            for (int p = 0; p < 8; p++) st_cluster_f32(hpeer[p] + hoff, hn);
        }
        CLUSTER_SYNC();
    }
    hT[(bbase + ob) * 256 + ou] = hn;
    cT[(bbase + ob) * 256 + ou] = c_reg;
}

// ----------------------------------------------------------------------------
// Heads: 8 rows per block; weights loaded once per k, 8 FMAs each.
// ----------------------------------------------------------------------------
__global__ void __launch_bounds__(128)
heads_kernel(const float* __restrict__ bp1,
             const float* __restrict__ Wp2,
             const float* __restrict__ bp2,
             const float* __restrict__ bv1,
             const float* __restrict__ Wv2,
             const float* __restrict__ bv2,
             float* __restrict__ logits,
             float* __restrict__ vout) {
    __shared__ float h_s[8][256];
    __shared__ float hp[8][64];
    __shared__ float hv[8][64];
    int r0 = blockIdx.x * 8, t = threadIdx.x;
    {
        const float4* g4 = reinterpret_cast<const float4*>(g_hs + r0 * 256);
        float4* s4 = reinterpret_cast<float4*>(&h_s[0][0]);
        for (int i = t; i < 512; i += 128) s4[i] = g4[i];
    }
    __syncthreads();

    if (t < 64) {
        float s[8];
#pragma unroll
        for (int r = 0; r < 8; r++) s[r] = bp1[t];
#pragma unroll 4
        for (int k = 0; k < 256; k++) {
            float w = __ldg(&g_wp1T[k * 64 + t]);
#pragma unroll
            for (int r = 0; r < 8; r++) s[r] = fmaf(h_s[r][k], w, s[r]);
        }
#pragma unroll
        for (int r = 0; r < 8; r++) hp[r][t] = tanhf(s[r]);
    } else {
        int j = t - 64;
        float s[8];
#pragma unroll
        for (int r = 0; r < 8; r++) s[r] = bv1[j];
#pragma unroll 4
        for (int k = 0; k < 256; k++) {
            float w = __ldg(&g_wv1T[k * 64 + j]);
#pragma unroll
            for (int r = 0; r < 8; r++) s[r] = fmaf(h_s[r][k], w, s[r]);
        }
#pragma unroll
        for (int r = 0; r < 8; r++) hv[r][j] = tanhf(s[r]);
    }
    __syncthreads();

    if (t < 40) {
        int r = t / 5, a = t % 5;
        float s = bp2[a];
#pragma unroll
        for (int k = 0; k < 64; k++) s = fmaf(hp[r][k], Wp2[a * 64 + k], s);
        logits[(r0 + r) * 5 + a] = s;
    }
    if (t >= 64 && t < 72) {
        int r = t - 64;
        float s = bv2[0];
#pragma unroll
        for (int k = 0; k < 64; k++) s = fmaf(hv[r][k], Wv2[k], s);
        vout[r0 + r] = s;
    }
}

// ----------------------------------------------------------------------------
// Launch
// ----------------------------------------------------------------------------
extern "C" void kernel_launch(void* const* d_in, const int* in_sizes, int n_in,
                              void* d_out, int out_size) {
    const float* image = (const float*)d_in[0];
    const int* la = (const int*)d_in[1];
    const float* done = (const float*)d_in[2];
    const float* h0 = (const float*)d_in[3];
    const float* c0 = (const float*)d_in[4];
    const float* W1 = (const float*)d_in[5];
    const float* b1 = (const float*)d_in[6];
    const float* W2 = (const float*)d_in[7];
    const float* b2 = (const float*)d_in[8];
    const float* W3 = (const float*)d_in[9];
    const float* b3 = (const float*)d_in[10];
    const float* Wfc = (const float*)d_in[11];
    const float* bfc = (const float*)d_in[12];
    const float* W_ih = (const float*)d_in[13];
    const float* W_hh = (const float*)d_in[14];
    const float* b_ih = (const float*)d_in[15];
    const float* b_hh = (const float*)d_in[16];
    const float* Wp1 = (const float*)d_in[17];
    const float* bp1 = (const float*)d_in[18];
    const float* Wp2 = (const float*)d_in[19];
    const float* bp2 = (const float*)d_in[20];
    const float* Wv1 = (const float*)d_in[21];
    const float* bv1 = (const float*)d_in[22];
    const float* Wv2 = (const float*)d_in[23];
    const float* bv2 = (const float*)d_in[24];

    float* out = (float*)d_out;
    float* o_logits = out;           // 5120
    float* o_v = out + 5120;         // 1024
    float* o_hT = out + 6144;        // 8192
    float* o_cT = out + 14336;       // 8192

    const int SMEML = (32768 + 2080 + 1024 + 8) * 4;  // 143520
    cudaFuncSetAttribute(lstm_kernel, cudaFuncAttributeMaxDynamicSharedMemorySize, SMEML);

    prep_kernel<<<2176, 256>>>(W_hh, b_ih, b_hh, Wp1, Wv1, W1, W2, W3, W_ih);
    conv_bf16_kernel<32, 400, 192, 21168><<<3200, 256>>>(image, b1);
    conv_bf16_kernel<64, 81, 512, 12800><<<648, 256>>>(nullptr, b2);
    conv_bf16_kernel<64, 49, 576, 5184><<<392, 256>>>(nullptr, b3);
    gemm_fc_kernel<<<dim3(512 / 64, 1024 / 64), 128>>>(Wfc, bfc);
    onehot_kernel<<<4, 256>>>(la);
    gemm_pre_kernel<<<dim3(1024 / 64, 1024 / 64), 128>>>();
    lstm_kernel<<<32, 256, SMEML>>>(done, h0, c0, o_hT, o_cT);
    heads_kernel<<<128, 128>>>(bp1, Wp2, bp2, bv1, Wv2, bv2, o_logits, o_v);
}

// round 16
// speedup vs baseline: 2.3848x; 1.0758x over previous
#include <cuda_runtime.h>
#include <cuda_bf16.h>
#include <math.h>
#include <stdint.h>

// ----------------------------------------------------------------------------
// Problem constants
//   T=32, B=32, TB=1024, NA=5, HID=256, FEAT=512, IN_DIM=517 (pad 544), FLAT=3136
// Output layout (22528 floats): logits[1024*5] | v[1024] | hT[32*256] | cT[32*256]
// Intermediate layouts: g_x1, g_x2 are NHWC ([img][px][ic]); g_x3 CHW (flatten).
// ----------------------------------------------------------------------------

#define TBn 1024
#define KPAD 544    // padded IN_DIM for tf32 GEMM (multiple of 32)

// Scratch (device globals; no allocation allowed)
__device__ float g_x1[TBn * 400 * 32];       // conv1 out (NHWC)
__device__ float g_x2[TBn * 81 * 64];        // conv2 out (NHWC)
__device__ float g_x3[TBn * 3136];           // conv3 out (CHW flatten)
__device__ float g_xs[TBn * KPAD];           // feat || one-hot || zero pad
__device__ float g_pre[TBn * 1024];          // x @ W_ih^T + b_ih + b_hh
__device__ float g_whhT[256 * 1024];         // W_hh transposed: [k][4*HID]
__device__ float g_wihp[1024 * KPAD];        // W_ih zero-padded to KPAD
__device__ float g_bsum[1024];               // b_ih + b_hh
__device__ float g_wp1T[256 * 64];           // Wp1 transposed [k][64]
__device__ float g_wv1T[256 * 64];           // Wv1 transposed [k][64]
__device__ float g_hs[TBn * 256];            // all h outputs
// bf16 hi/lo split conv weights, [oc][k/2] packed bf16x2.
// conv1: k-order (ic,ky,kx) [matches CHW gather]. conv2/conv3: k-order (pos,ic).
__device__ unsigned g_w1h[32 * 96],  g_w1l[32 * 96];    // conv1 (scaled 1/255)
__device__ unsigned g_w2h[64 * 256], g_w2l[64 * 256];   // conv2
__device__ unsigned g_w3h[64 * 288], g_w3l[64 * 288];   // conv3
// conv1 im2col LUTs (CHW raw input): src = in[img*21168 + lutk[k] + lutn[px]]
__device__ int g_lutk1[192], g_lutn1[400];

__device__ __forceinline__ float sigmoidf(float x) { return 1.0f / (1.0f + expf(-x)); }

__device__ __forceinline__ unsigned f2tf(float f) {
    unsigned u;
    asm("cvt.rna.tf32.f32 %0, %1;" : "=r"(u) : "f"(f));
    return u;
}

// pack two floats into bf16x2 hi + residual-lo (v0 in low half)
__device__ __forceinline__ void packhl(float v0, float v1, unsigned& h, unsigned& l) {
    __nv_bfloat162 h2 = __floats2bfloat162_rn(v0, v1);
    float l0 = v0 - __low2float(h2);
    float l1 = v1 - __high2float(h2);
    __nv_bfloat162 l2 = __floats2bfloat162_rn(l0, l1);
    h = *reinterpret_cast<unsigned*>(&h2);
    l = *reinterpret_cast<unsigned*>(&l2);
}

// ---- cluster / DSMEM helpers ----
__device__ __forceinline__ uint32_t smem_u32(const void* p) {
    uint32_t a;
    asm("{ .reg .u64 t; cvta.to.shared.u64 t, %1; cvt.u32.u64 %0, t; }"
        : "=r"(a) : "l"(p));
    return a;
}
__device__ __forceinline__ uint32_t mapa_rank(uint32_t saddr, uint32_t rank) {
    uint32_t r;
    asm("mapa.shared::cluster.u32 %0, %1, %2;" : "=r"(r) : "r"(saddr), "r"(rank));
    return r;
}
__device__ __forceinline__ void st_cluster_f32(uint32_t addr, float v) {
    asm volatile("st.shared::cluster.f32 [%0], %1;" :: "r"(addr), "f"(v) : "memory");
}
#define CLUSTER_SYNC() do { \
    asm volatile("barrier.cluster.arrive.aligned;" ::: "memory"); \
    asm volatile("barrier.cluster.wait.aligned;" ::: "memory"); \
} while (0)

// ----------------------------------------------------------------------------
// prep: transposes, bias sum, W_ih pad, conv weight bf16-split packs, LUTs
// ----------------------------------------------------------------------------
__global__ void prep_kernel(const float* __restrict__ W_hh,
                            const float* __restrict__ b_ih,
                            const float* __restrict__ b_hh,
                            const float* __restrict__ Wp1,
                            const float* __restrict__ Wv1,
                            const float* __restrict__ W1,
                            const float* __restrict__ W2,
                            const float* __restrict__ W3,
                            const float* __restrict__ W_ih) {
    int idx = blockIdx.x * blockDim.x + threadIdx.x;
    if (idx < 262144) {
        int j = idx >> 8, k = idx & 255;
        g_whhT[k * 1024 + j] = W_hh[idx];
    }
    if (idx < 16384) {
        int j = idx >> 8, k = idx & 255;
        g_wp1T[k * 64 + j] = Wp1[idx];
        g_wv1T[k * 64 + j] = Wv1[idx];
    }
    if (idx < 1024) g_bsum[idx] = b_ih[idx] + b_hh[idx];
    if (idx < 1024 * KPAD) {
        int row = idx / KPAD, col = idx % KPAD;
        g_wihp[idx] = (col < 517) ? W_ih[row * 517 + col] : 0.0f;
    }
    // conv1 weights: k-order (ic,ky,kx) unchanged; pairs (2pk, 2pk+1)
    if (idx < 32 * 96) {
        int oc = idx / 96, pk = idx % 96;
        float v0 = W1[oc * 192 + 2 * pk] * (1.0f / 255.0f);
        float v1 = W1[oc * 192 + 2 * pk + 1] * (1.0f / 255.0f);
        packhl(v0, v1, g_w1h[idx], g_w1l[idx]);
    }
    // conv2 weights: NEW k-order knew = pos*32 + ic (pos = ky*4+kx)
    //   kold = ic*16 + pos ; pair = (ic even, ic+1)
    if (idx < 64 * 256) {
        int oc = idx >> 8, pk = idx & 255;
        int knew0 = 2 * pk;
        int pos = knew0 >> 5, ic0 = knew0 & 31;
        int kold0 = ic0 * 16 + pos;
        int kold1 = (ic0 + 1) * 16 + pos;
        packhl(W2[oc * 512 + kold0], W2[oc * 512 + kold1],
               g_w2h[idx], g_w2l[idx]);
    }
    // conv3 weights: NEW k-order knew = pos*64 + ic (pos = ky*3+kx)
    //   kold = ic*9 + pos
    if (idx < 64 * 288) {
        int oc = idx / 288, pk = idx % 288;
        int knew0 = 2 * pk;
        int pos = knew0 >> 6, ic0 = knew0 & 63;
        int kold0 = ic0 * 9 + pos;
        int kold1 = (ic0 + 1) * 9 + pos;
        packhl(W3[oc * 576 + kold0], W3[oc * 576 + kold1],
               g_w3h[idx], g_w3l[idx]);
    }
    // conv1 LUTs
    if (idx < 192) {
        int ic = idx >> 6, ky = (idx >> 3) & 7, kx = idx & 7;
        g_lutk1[idx] = ic * 7056 + ky * 84 + kx;
    }
    if (idx < 400) g_lutn1[idx] = (idx / 20) * 336 + (idx % 20) * 4;
}

// ----------------------------------------------------------------------------
// one-hot columns of xs (cols 512..516) + zero pad (517..543)
// ----------------------------------------------------------------------------
__global__ void onehot_kernel(const int* __restrict__ la) {
    int r = blockIdx.x * blockDim.x + threadIdx.x;
    if (r < TBn) {
        int a = la[r];
        float* p = g_xs + r * KPAD + 512;
#pragma unroll
        for (int j = 0; j < 5; j++) p[j] = (j == a) ? 1.0f : 0.0f;
#pragma unroll
        for (int j = 5; j < 32; j++) p[j] = 0.0f;
    }
}

// ----------------------------------------------------------------------------
// bf16 m16n8k16 mma
// ----------------------------------------------------------------------------
__device__ __forceinline__ void mma_bf16(float* c, const unsigned* a, const unsigned* b) {
    asm volatile(
        "mma.sync.aligned.m16n8k16.row.col.f32.bf16.bf16.f32 "
        "{%0,%1,%2,%3}, {%4,%5,%6,%7}, {%8,%9}, {%0,%1,%2,%3};\n"
        : "+f"(c[0]), "+f"(c[1]), "+f"(c[2]), "+f"(c[3])
        : "r"(a[0]), "r"(a[1]), "r"(a[2]), "r"(a[3]), "r"(b[0]), "r"(b[1]));
}

// ----------------------------------------------------------------------------
// conv1: CHW raw-image gather (8-float k-runs = full sectors), NHWC output.
// BM=128, 256 threads, OC=32: 8 M-warps of 16 rows.
// ----------------------------------------------------------------------------
__global__ void __launch_bounds__(256)
conv1_bf16_kernel(const float* __restrict__ in, const float* __restrict__ bias) {
    constexpr int NPX = 400, K = 192, IMG = 21168, OC = 32;
    constexpr int NCH = K / 32, KP = K / 2, BITS = 2;

    __shared__ unsigned Ah[2][128][18], Al[2][128][18];
    __shared__ unsigned Bh[2][OC][18], Bl[2][OC][18];

    int tid = threadIdx.x, lane = tid & 31, warp = tid >> 5;
    int wm = warp * 16, wn = 0;
    int bm = blockIdx.x * 128;
    int trow = tid >> 4, tpk = tid & 15;

    int base[8];
#pragma unroll
    for (int it = 0; it < 8; it++) {
        int grow = bm + trow + 16 * it;
        int img = grow / NPX;
        int px = grow - img * NPX;
        base[it] = img * IMG + __ldg(&g_lutn1[px]);
    }

    float c[1][4][4];
#pragma unroll
    for (int nt = 0; nt < 4; nt++)
#pragma unroll
        for (int i = 0; i < 4; i++) c[0][nt][i] = 0.0f;

    {
        int koff0 = __ldg(&g_lutk1[2 * tpk]);
        int koff1 = __ldg(&g_lutk1[2 * tpk + 1]);
#pragma unroll
        for (int it = 0; it < 8; it++) {
            float v0 = __ldg(&in[base[it] + koff0]);
            float v1 = __ldg(&in[base[it] + koff1]);
            unsigned h, l;
            packhl(v0, v1, h, l);
            Ah[0][trow + 16 * it][tpk] = h;
            Al[0][trow + 16 * it][tpk] = l;
        }
#pragma unroll
        for (int it = 0; it < BITS; it++) {
            int bidx = it * 256 + tid;
            int rrow = bidx >> 4, pk = bidx & 15;
            Bh[0][rrow][pk] = __ldg(&g_w1h[rrow * KP + pk]);
            Bl[0][rrow][pk] = __ldg(&g_w1l[rrow * KP + pk]);
        }
    }
    __syncthreads();

    for (int ch = 0; ch < NCH; ch++) {
        int buf = ch & 1;
        float va0[8], va1[8];
        unsigned vbh[BITS], vbl[BITS];
        if (ch + 1 < NCH) {
            int k0 = (ch + 1) * 32, kp0 = (ch + 1) * 16;
            int koff0 = __ldg(&g_lutk1[k0 + 2 * tpk]);
            int koff1 = __ldg(&g_lutk1[k0 + 2 * tpk + 1]);
#pragma unroll
            for (int it = 0; it < 8; it++) {
                va0[it] = __ldg(&in[base[it] + koff0]);
                va1[it] = __ldg(&in[base[it] + koff1]);
            }
#pragma unroll
            for (int it = 0; it < BITS; it++) {
                int bidx = it * 256 + tid;
                int rrow = bidx >> 4, pk = bidx & 15;
                vbh[it] = __ldg(&g_w1h[rrow * KP + kp0 + pk]);
                vbl[it] = __ldg(&g_w1l[rrow * KP + kp0 + pk]);
            }
        }

        int r = lane >> 2, q = lane & 3;
#pragma unroll
        for (int ks = 0; ks < 2; ks++) {
            unsigned ah[4], al[4];
            int mr = wm + r;
            ah[0] = Ah[buf][mr][ks * 8 + q];
            ah[1] = Ah[buf][mr + 8][ks * 8 + q];
            ah[2] = Ah[buf][mr][ks * 8 + q + 4];
            ah[3] = Ah[buf][mr + 8][ks * 8 + q + 4];
            al[0] = Al[buf][mr][ks * 8 + q];
            al[1] = Al[buf][mr + 8][ks * 8 + q];
            al[2] = Al[buf][mr][ks * 8 + q + 4];
            al[3] = Al[buf][mr + 8][ks * 8 + q + 4];
#pragma unroll
            for (int nt = 0; nt < 4; nt++) {
                int nc = wn + nt * 8 + r;
                unsigned bh2[2] = {Bh[buf][nc][ks * 8 + q], Bh[buf][nc][ks * 8 + q + 4]};
                unsigned bl2[2] = {Bl[buf][nc][ks * 8 + q], Bl[buf][nc][ks * 8 + q + 4]};
                mma_bf16(c[0][nt], ah, bh2);
                mma_bf16(c[0][nt], ah, bl2);
                mma_bf16(c[0][nt], al, bh2);
            }
        }

        if (ch + 1 < NCH) {
            int nbuf = buf ^ 1;
#pragma unroll
            for (int it = 0; it < 8; it++) {
                unsigned h, l;
                packhl(va0[it], va1[it], h, l);
                Ah[nbuf][trow + 16 * it][tpk] = h;
                Al[nbuf][trow + 16 * it][tpk] = l;
            }
#pragma unroll
            for (int it = 0; it < BITS; it++) {
                int bidx = it * 256 + tid;
                int rrow = bidx >> 4, pk = bidx & 15;
                Bh[nbuf][rrow][pk] = vbh[it];
                Bl[nbuf][rrow][pk] = vbl[it];
            }
        }
        __syncthreads();
    }

    // NHWC epilogue: g_x1[img][px][32] float2 stores
#pragma unroll
    for (int nt = 0; nt < 4; nt++) {
        int row = bm + wm + (lane >> 2);
        int col = wn + nt * 8 + ((lane & 3) << 1);
        float b0 = __ldg(&bias[col]);
        float b1 = __ldg(&bias[col + 1]);
        int img0 = row / NPX, px0 = row - img0 * NPX;
        int row2 = row + 8;
        int img2 = row2 / NPX, px2 = row2 - img2 * NPX;
        float2 v01 = {fmaxf(c[0][nt][0] + b0, 0.0f), fmaxf(c[0][nt][1] + b1, 0.0f)};
        float2 v23 = {fmaxf(c[0][nt][2] + b0, 0.0f), fmaxf(c[0][nt][3] + b1, 0.0f)};
        *reinterpret_cast<float2*>(&g_x1[img0 * (NPX * 32) + px0 * 32 + col]) = v01;
        *reinterpret_cast<float2*>(&g_x1[img2 * (NPX * 32) + px2 * 32 + col]) = v23;
    }
}

// ----------------------------------------------------------------------------
// conv2/conv3: NHWC input, k-order (pos, ic) -> each 32-k chunk is one dense
// 128B run; gather = one aligned float2 per row-slot. BM=128, 256 threads,
// OC=64: 4(M)x2(N) warps. OUT_NHWC: conv2 -> g_x2 NHWC; else conv3 -> g_x3 CHW.
// ----------------------------------------------------------------------------
template<int NPX, int K, int IMG, int ICIN, int WID, int STR, int PW, int OW, bool OUT_NHWC>
__global__ void __launch_bounds__(256)
conv_nhwc_kernel(const float* __restrict__ bias) {
    constexpr int OC = 64;
    constexpr int NCH = K / 32, KP = K / 2;
    constexpr int CPP = ICIN / 32;            // chunks per kernel-position
    constexpr int BITS = 4;

    const float* in = (K == 512) ? g_x1 : g_x2;
    float* out = (K == 512) ? g_x2 : g_x3;
    const unsigned* wh = (K == 512) ? g_w2h : g_w3h;
    const unsigned* wl = (K == 512) ? g_w2l : g_w3l;

    __shared__ unsigned Ah[2][128][18], Al[2][128][18];
    __shared__ unsigned Bh[2][OC][18], Bl[2][OC][18];

    int tid = threadIdx.x, lane = tid & 31, warp = tid >> 5;
    int wm = (warp & 3) * 32, wn = (warp >> 2) * 32;
    int bm = blockIdx.x * 128;
    int trow = tid >> 4, tpk = tid & 15;

    // per-row pixel base (chunk-invariant), includes this thread's ic offset
    int base[8];
#pragma unroll
    for (int it = 0; it < 8; it++) {
        int grow = bm + trow + 16 * it;
        int img = grow / NPX;
        int px = grow - img * NPX;
        int oy = px / OW, ox = px - oy * OW;
        base[it] = img * IMG + (oy * STR * WID + ox * STR) * ICIN + 2 * tpk;
    }

    float c[2][4][4];
#pragma unroll
    for (int mt = 0; mt < 2; mt++)
#pragma unroll
        for (int nt = 0; nt < 4; nt++)
#pragma unroll
            for (int i = 0; i < 4; i++) c[mt][nt][i] = 0.0f;

    auto chunk_off = [](int ch) {
        int pos = ch / CPP;
        int ico = (ch - pos * CPP) * 32;
        int ky = pos / PW, kx = pos - ky * PW;
        return (ky * WID + kx) * ICIN + ico;
    };

    // prologue: chunk 0 (offset 0)
    {
#pragma unroll
        for (int it = 0; it < 8; it++) {
            float2 v = *reinterpret_cast<const float2*>(&in[base[it]]);
            unsigned h, l;
            packhl(v.x, v.y, h, l);
            Ah[0][trow + 16 * it][tpk] = h;
            Al[0][trow + 16 * it][tpk] = l;
        }
#pragma unroll
        for (int it = 0; it < BITS; it++) {
            int bidx = it * 256 + tid;
            int rrow = bidx >> 4, pk = bidx & 15;
            Bh[0][rrow][pk] = __ldg(&wh[rrow * KP + pk]);
            Bl[0][rrow][pk] = __ldg(&wl[rrow * KP + pk]);
        }
    }
    __syncthreads();

    for (int ch = 0; ch < NCH; ch++) {
        int buf = ch & 1;
        float va0[8], va1[8];
        unsigned vbh[BITS], vbl[BITS];
        if (ch + 1 < NCH) {
            int off = chunk_off(ch + 1);
            int kp0 = (ch + 1) * 16;
#pragma unroll
            for (int it = 0; it < 8; it++) {
                float2 v = *reinterpret_cast<const float2*>(&in[base[it] + off]);
                va0[it] = v.x;
                va1[it] = v.y;
            }
#pragma unroll
            for (int it = 0; it < BITS; it++) {
                int bidx = it * 256 + tid;
                int rrow = bidx >> 4, pk = bidx & 15;
                vbh[it] = __ldg(&wh[rrow * KP + kp0 + pk]);
                vbl[it] = __ldg(&wl[rrow * KP + kp0 + pk]);
            }
        }

        int r = lane >> 2, q = lane & 3;
#pragma unroll
        for (int ks = 0; ks < 2; ks++) {
            unsigned ah[2][4], al[2][4];
#pragma unroll
            for (int mt = 0; mt < 2; mt++) {
                int mr = wm + mt * 16 + r;
                ah[mt][0] = Ah[buf][mr][ks * 8 + q];
                ah[mt][1] = Ah[buf][mr + 8][ks * 8 + q];
                ah[mt][2] = Ah[buf][mr][ks * 8 + q + 4];
                ah[mt][3] = Ah[buf][mr + 8][ks * 8 + q + 4];
                al[mt][0] = Al[buf][mr][ks * 8 + q];
                al[mt][1] = Al[buf][mr + 8][ks * 8 + q];
                al[mt][2] = Al[buf][mr][ks * 8 + q + 4];
                al[mt][3] = Al[buf][mr + 8][ks * 8 + q + 4];
            }
#pragma unroll
            for (int nt = 0; nt < 4; nt++) {
                int nc = wn + nt * 8 + r;
                unsigned bh2[2] = {Bh[buf][nc][ks * 8 + q], Bh[buf][nc][ks * 8 + q + 4]};
                unsigned bl2[2] = {Bl[buf][nc][ks * 8 + q], Bl[buf][nc][ks * 8 + q + 4]};
#pragma unroll
                for (int mt = 0; mt < 2; mt++) {
                    mma_bf16(c[mt][nt], ah[mt], bh2);
                    mma_bf16(c[mt][nt], ah[mt], bl2);
                    mma_bf16(c[mt][nt], al[mt], bh2);
                }
            }
        }

        if (ch + 1 < NCH) {
            int nbuf = buf ^ 1;
#pragma unroll
            for (int it = 0; it < 8; it++) {
                unsigned h, l;
                packhl(va0[it], va1[it], h, l);
                Ah[nbuf][trow + 16 * it][tpk] = h;
                Al[nbuf][trow + 16 * it][tpk] = l;
            }
#pragma unroll
            for (int it = 0; it < BITS; it++) {
                int bidx = it * 256 + tid;
                int rrow = bidx >> 4, pk = bidx & 15;
                Bh[nbuf][rrow][pk] = vbh[it];
                Bl[nbuf][rrow][pk] = vbl[it];
            }
        }
        __syncthreads();
    }

    // epilogue
#pragma unroll
    for (int mt = 0; mt < 2; mt++) {
#pragma unroll
        for (int nt = 0; nt < 4; nt++) {
            int row = bm + wm + mt * 16 + (lane >> 2);
            int col = wn + nt * 8 + ((lane & 3) << 1);
            float b0 = __ldg(&bias[col]);
            float b1 = __ldg(&bias[col + 1]);
            int img0 = row / NPX, px0 = row - img0 * NPX;
            int row2 = row + 8;
            int img2 = row2 / NPX, px2 = row2 - img2 * NPX;
            if (OUT_NHWC) {
                float2 v01 = {fmaxf(c[mt][nt][0] + b0, 0.0f), fmaxf(c[mt][nt][1] + b1, 0.0f)};
                float2 v23 = {fmaxf(c[mt][nt][2] + b0, 0.0f), fmaxf(c[mt][nt][3] + b1, 0.0f)};
                *reinterpret_cast<float2*>(&out[img0 * (NPX * OC) + px0 * OC + col]) = v01;
                *reinterpret_cast<float2*>(&out[img2 * (NPX * OC) + px2 * OC + col]) = v23;
            } else {
                out[img0 * (OC * NPX) + col * NPX + px0] = fmaxf(c[mt][nt][0] + b0, 0.0f);
                out[img0 * (OC * NPX) + (col + 1) * NPX + px0] = fmaxf(c[mt][nt][1] + b1, 0.0f);
                out[img2 * (OC * NPX) + col * NPX + px2] = fmaxf(c[mt][nt][2] + b0, 0.0f);
                out[img2 * (OC * NPX) + (col + 1) * NPX + px2] = fmaxf(c[mt][nt][3] + b1, 0.0f);
            }
        }
    }
}

// ----------------------------------------------------------------------------
// tf32 tensor-core GEMM: C[M x N] = act(A[M x K] * B[N x K]^T + bias)
// ----------------------------------------------------------------------------
__device__ __forceinline__ void mma_tf32(float* c, const unsigned* a, const unsigned* b) {
    asm volatile(
        "mma.sync.aligned.m16n8k8.row.col.f32.tf32.tf32.f32 "
        "{%0,%1,%2,%3}, {%4,%5,%6,%7}, {%8,%9}, {%0,%1,%2,%3};\n"
        : "+f"(c[0]), "+f"(c[1]), "+f"(c[2]), "+f"(c[3])
        : "r"(a[0]), "r"(a[1]), "r"(a[2]), "r"(a[3]), "r"(b[0]), "r"(b[1]));
}

__device__ __forceinline__ void gemm_tf32(const float* __restrict__ A, int lda,
                                          const float* __restrict__ B, int ldb,
                                          const float* __restrict__ bias,
                                          float* __restrict__ C, int ldc,
                                          int K, bool relu) {
    __shared__ unsigned As[2][64][36];
    __shared__ unsigned Bs[2][64][36];
    int tid = threadIdx.x, lane = tid & 31, warp = tid >> 5;
    int bm = blockIdx.y * 64, bn = blockIdx.x * 64;
    int wm = (warp & 1) << 5, wn = (warp >> 1) << 5;

    float c[2][4][4];
#pragma unroll
    for (int mt = 0; mt < 2; mt++)
#pragma unroll
        for (int nt = 0; nt < 4; nt++)
#pragma unroll
            for (int i = 0; i < 4; i++) c[mt][nt][i] = 0.0f;

    int ntiles = K >> 5;
    float4 pa[4], pb[4];

#pragma unroll
    for (int i = 0; i < 4; i++) {
        int idx = tid + (i << 7);
        int row = idx >> 3, c4 = (idx & 7) << 2;
        pa[i] = *reinterpret_cast<const float4*>(A + (bm + row) * lda + c4);
        pb[i] = *reinterpret_cast<const float4*>(B + (bn + row) * ldb + c4);
    }
#pragma unroll
    for (int i = 0; i < 4; i++) {
        int idx = tid + (i << 7);
        int row = idx >> 3, c4 = (idx & 7) << 2;
        uint4 ta = {f2tf(pa[i].x), f2tf(pa[i].y), f2tf(pa[i].z), f2tf(pa[i].w)};
        uint4 tb = {f2tf(pb[i].x), f2tf(pb[i].y), f2tf(pb[i].z), f2tf(pb[i].w)};
        *reinterpret_cast<uint4*>(&As[0][row][c4]) = ta;
        *reinterpret_cast<uint4*>(&Bs[0][row][c4]) = tb;
    }
    __syncthreads();

    for (int t = 0; t < ntiles; t++) {
        int buf = t & 1;
        if (t + 1 < ntiles) {
            int k0 = (t + 1) << 5;
#pragma unroll
            for (int i = 0; i < 4; i++) {
                int idx = tid + (i << 7);
                int row = idx >> 3, c4 = (idx & 7) << 2;
                pa[i] = *reinterpret_cast<const float4*>(A + (bm + row) * lda + k0 + c4);
                pb[i] = *reinterpret_cast<const float4*>(B + (bn + row) * ldb + k0 + c4);
            }
        }
        int r = lane >> 2, q = lane & 3;
#pragma unroll
        for (int ks = 0; ks < 4; ks++) {
            unsigned a[2][4], b[4][2];
            int kc = ks << 3;
#pragma unroll
            for (int mt = 0; mt < 2; mt++) {
                int mr = wm + (mt << 4) + r;
                a[mt][0] = As[buf][mr][kc + q];
                a[mt][1] = As[buf][mr + 8][kc + q];
                a[mt][2] = As[buf][mr][kc + q + 4];
                a[mt][3] = As[buf][mr + 8][kc + q + 4];
            }
#pragma unroll
            for (int nt = 0; nt < 4; nt++) {
                int nr = wn + (nt << 3) + r;
                b[nt][0] = Bs[buf][nr][kc + q];
                b[nt][1] = Bs[buf][nr][kc + q + 4];
            }
#pragma unroll
            for (int mt = 0; mt < 2; mt++)
#pragma unroll
                for (int nt = 0; nt < 4; nt++)
                    mma_tf32(c[mt][nt], a[mt], b[nt]);
        }
        if (t + 1 < ntiles) {
            int nbuf = buf ^ 1;
#pragma unroll
            for (int i = 0; i < 4; i++) {
                int idx = tid + (i << 7);
                int row = idx >> 3, c4 = (idx & 7) << 2;
                uint4 ta = {f2tf(pa[i].x), f2tf(pa[i].y), f2tf(pa[i].z), f2tf(pa[i].w)};
                uint4 tb = {f2tf(pb[i].x), f2tf(pb[i].y), f2tf(pb[i].z), f2tf(pb[i].w)};
                *reinterpret_cast<uint4*>(&As[nbuf][row][c4]) = ta;
                *reinterpret_cast<uint4*>(&Bs[nbuf][row][c4]) = tb;
            }
            __syncthreads();
        }
    }

#pragma unroll
    for (int mt = 0; mt < 2; mt++) {
#pragma unroll
        for (int nt = 0; nt < 4; nt++) {
            int row = bm + wm + (mt << 4) + (lane >> 2);
            int col = bn + wn + (nt << 3) + ((lane & 3) << 1);
            float b0 = bias[col], b1 = bias[col + 1];
            float v0 = c[mt][nt][0] + b0;
            float v1 = c[mt][nt][1] + b1;
            float v2 = c[mt][nt][2] + b0;
            float v3 = c[mt][nt][3] + b1;
            if (relu) {
                v0 = fmaxf(v0, 0.0f); v1 = fmaxf(v1, 0.0f);
                v2 = fmaxf(v2, 0.0f); v3 = fmaxf(v3, 0.0f);
            }
            C[row * ldc + col] = v0;
            C[row * ldc + col + 1] = v1;
            C[(row + 8) * ldc + col] = v2;
            C[(row + 8) * ldc + col + 1] = v3;
        }
    }
}

__global__ void __launch_bounds__(128)
gemm_fc_kernel(const float* __restrict__ Wfc, const float* __restrict__ bfc) {
    gemm_tf32(g_x3, 3136, Wfc, 3136, bfc, g_xs, KPAD, 3136, true);
}

__global__ void __launch_bounds__(128)
gemm_pre_kernel() {
    gemm_tf32(g_xs, KPAD, g_wihp, KPAD, g_bsum, g_pre, 1024, KPAD, false);
}

// ----------------------------------------------------------------------------
// LSTM: 4 clusters x 8 CTAs, W_hh slice SMEM-resident, DSMEM gate exchange.
// Thread = (2 cols x 2 batches).
// ----------------------------------------------------------------------------
__global__ void __launch_bounds__(256, 1) __cluster_dims__(8, 1, 1)
lstm_kernel(const float* __restrict__ done,
            const float* __restrict__ h0,
            const float* __restrict__ c0,
            float* __restrict__ hT,
            float* __restrict__ cT) {
    extern __shared__ float sm[];
    float* wsl = sm;                    // 256*128 floats (weight slice)
    float* h_s = sm + 32768;            // 8*260 floats
    float* gbuf = h_s + 2080;           // 4*8*32 floats
    float* m_s = gbuf + 1024;           // 8 floats

    int tid = threadIdx.x;
    unsigned rank;
    asm("mov.u32 %0, %%cluster_ctarank;" : "=r"(rank));
    int cl = blockIdx.x >> 3;
    int bbase = cl * 8;

    {
        const float* src = g_whhT + 128 * (int)rank;
        for (int i = tid; i < 8192; i += 256) {
            int k = i >> 5, j4 = (i & 31) << 2;
            *reinterpret_cast<float4*>(&wsl[k * 128 + j4]) =
                *reinterpret_cast<const float4*>(&src[k * 1024 + j4]);
        }
    }
    for (int i = tid; i < 2048; i += 256) {
        int b = i >> 8, k = i & 255;
        h_s[b * 260 + k] = h0[(bbase + b) * 256 + k];
    }
    int ob = tid >> 5, os = tid & 31;
    int ou = 32 * (int)rank + os;
    float c_reg = c0[(bbase + ob) * 256 + ou];
    float hn = 0.0f;

    int jg2 = tid >> 2, bp = tid & 3;
    int jbase = 2 * jg2;
    int b0 = 2 * bp, b1 = b0 + 1;
    int gt = (int)rank >> 1;
    int ubase = ((128 * (int)rank) & 255) + jbase;
    uint32_t owner = (uint32_t)(ubase >> 5);
    uint32_t gbuf_a = smem_u32(gbuf);
    uint32_t h_a = smem_u32(h_s);
    uint32_t peer_gbuf = mapa_rank(gbuf_a, owner);
    uint32_t g0 = (uint32_t)(((gt * 8 + b0) * 32 + (ubase & 31)) * 4);
    uint32_t g1 = (uint32_t)(((gt * 8 + b1) * 32 + (ubase & 31)) * 4);
    uint32_t hpeer[8];
#pragma unroll
    for (int p = 0; p < 8; p++) hpeer[p] = mapa_rank(h_a, (uint32_t)p);
    uint32_t hoff = (uint32_t)((ob * 260 + ou) * 4);

    __syncthreads();
    CLUSTER_SYNC();

    for (int t = 0; t < 32; t++) {
        if (tid < 8) m_s[tid] = 1.0f - __ldg(&done[t * 32 + bbase + tid]);
        __syncthreads();
        for (int i = tid; i < 2048; i += 256) {
            int bb = i >> 8, k = i & 255;
            h_s[bb * 260 + k] *= m_s[bb];
        }
        c_reg *= m_s[ob];
        __syncthreads();

        int row0 = (t << 5) + bbase + b0;
        int row1 = row0 + 1;
        float2 a0 = *reinterpret_cast<const float2*>(
            g_pre + row0 * 1024 + 128 * (int)rank + jbase);
        float2 a1 = *reinterpret_cast<const float2*>(
            g_pre + row1 * 1024 + 128 * (int)rank + jbase);
        float acc00 = a0.x, acc01 = a0.y;
        float acc10 = a1.x, acc11 = a1.y;
        const float* hb0 = h_s + b0 * 260;
        const float* hb1 = h_s + b1 * 260;
#pragma unroll 8
        for (int k = 0; k < 256; k++) {
            float2 w = *reinterpret_cast<const float2*>(&wsl[k * 128 + jbase]);
            float h0k = hb0[k];
            float h1k = hb1[k];
            acc00 = fmaf(h0k, w.x, acc00);
            acc01 = fmaf(h0k, w.y, acc01);
            acc10 = fmaf(h1k, w.x, acc10);
            acc11 = fmaf(h1k, w.y, acc11);
        }
        st_cluster_f32(peer_gbuf + g0, acc00);
        st_cluster_f32(peer_gbuf + g0 + 4, acc01);
        st_cluster_f32(peer_gbuf + g1, acc10);
        st_cluster_f32(peer_gbuf + g1 + 4, acc11);
        CLUSTER_SYNC();

        {
            float gi = sigmoidf(gbuf[(0 * 8 + ob) * 32 + os]);
            float gf = sigmoidf(gbuf[(1 * 8 + ob) * 32 + os]);
            float gg = tanhf(gbuf[(2 * 8 + ob) * 32 + os]);
            float go = sigmoidf(gbuf[(3 * 8 + ob) * 32 + os]);
            c_reg = gf * c_reg + gi * gg;
            hn = go * tanhf(c_reg);
            g_hs[((t << 5) + bbase + ob) * 256 + ou] = hn;
#pragma unroll
            for (int p = 0; p < 8; p++) st_cluster_f32(hpeer[p] + hoff, hn);
        }
        CLUSTER_SYNC();
    }
    hT[(bbase + ob) * 256 + ou] = hn;
    cT[(bbase + ob) * 256 + ou] = c_reg;
}

// ----------------------------------------------------------------------------
// Heads: 8 rows per block; weights loaded once per k, 8 FMAs each.
// ----------------------------------------------------------------------------
__global__ void __launch_bounds__(128)
heads_kernel(const float* __restrict__ bp1,
             const float* __restrict__ Wp2,
             const float* __restrict__ bp2,
             const float* __restrict__ bv1,
             const float* __restrict__ Wv2,
             const float* __restrict__ bv2,
             float* __restrict__ logits,
             float* __restrict__ vout) {
    __shared__ float h_s[8][256];
    __shared__ float hp[8][64];
    __shared__ float hv[8][64];
    int r0 = blockIdx.x * 8, t = threadIdx.x;
    {
        const float4* g4 = reinterpret_cast<const float4*>(g_hs + r0 * 256);
        float4* s4 = reinterpret_cast<float4*>(&h_s[0][0]);
        for (int i = t; i < 512; i += 128) s4[i] = g4[i];
    }
    __syncthreads();

    if (t < 64) {
        float s[8];
#pragma unroll
        for (int r = 0; r < 8; r++) s[r] = bp1[t];
#pragma unroll 4
        for (int k = 0; k < 256; k++) {
            float w = __ldg(&g_wp1T[k * 64 + t]);
#pragma unroll
            for (int r = 0; r < 8; r++) s[r] = fmaf(h_s[r][k], w, s[r]);
        }
#pragma unroll
        for (int r = 0; r < 8; r++) hp[r][t] = tanhf(s[r]);
    } else {
        int j = t - 64;
        float s[8];
#pragma unroll
        for (int r = 0; r < 8; r++) s[r] = bv1[j];
#pragma unroll 4
        for (int k = 0; k < 256; k++) {
            float w = __ldg(&g_wv1T[k * 64 + j]);
#pragma unroll
            for (int r = 0; r < 8; r++) s[r] = fmaf(h_s[r][k], w, s[r]);
        }
#pragma unroll
        for (int r = 0; r < 8; r++) hv[r][j] = tanhf(s[r]);
    }
    __syncthreads();

    if (t < 40) {
        int r = t / 5, a = t % 5;
        float s = bp2[a];
#pragma unroll
        for (int k = 0; k < 64; k++) s = fmaf(hp[r][k], Wp2[a * 64 + k], s);
        logits[(r0 + r) * 5 + a] = s;
    }
    if (t >= 64 && t < 72) {
        int r = t - 64;
        float s = bv2[0];
#pragma unroll
        for (int k = 0; k < 64; k++) s = fmaf(hv[r][k], Wv2[k], s);
        vout[r0 + r] = s;
    }
}

// ----------------------------------------------------------------------------
// Launch
// ----------------------------------------------------------------------------
extern "C" void kernel_launch(void* const* d_in, const int* in_sizes, int n_in,
                              void* d_out, int out_size) {
    const float* image = (const float*)d_in[0];
    const int* la = (const int*)d_in[1];
    const float* done = (const float*)d_in[2];
    const float* h0 = (const float*)d_in[3];
    const float* c0 = (const float*)d_in[4];
    const float* W1 = (const float*)d_in[5];
    const float* b1 = (const float*)d_in[6];
    const float* W2 = (const float*)d_in[7];
    const float* b2 = (const float*)d_in[8];
    const float* W3 = (const float*)d_in[9];
    const float* b3 = (const float*)d_in[10];
    const float* Wfc = (const float*)d_in[11];
    const float* bfc = (const float*)d_in[12];
    const float* W_ih = (const float*)d_in[13];
    const float* W_hh = (const float*)d_in[14];
    const float* b_ih = (const float*)d_in[15];
    const float* b_hh = (const float*)d_in[16];
    const float* Wp1 = (const float*)d_in[17];
    const float* bp1 = (const float*)d_in[18];
    const float* Wp2 = (const float*)d_in[19];
    const float* bp2 = (const float*)d_in[20];
    const float* Wv1 = (const float*)d_in[21];
    const float* bv1 = (const float*)d_in[22];
    const float* Wv2 = (const float*)d_in[23];
    const float* bv2 = (const float*)d_in[24];

    float* out = (float*)d_out;
    float* o_logits = out;           // 5120
    float* o_v = out + 5120;         // 1024
    float* o_hT = out + 6144;        // 8192
    float* o_cT = out + 14336;       // 8192

    const int SMEML = (32768 + 2080 + 1024 + 8) * 4;  // 143520
    cudaFuncSetAttribute(lstm_kernel, cudaFuncAttributeMaxDynamicSharedMemorySize, SMEML);

    prep_kernel<<<2176, 256>>>(W_hh, b_ih, b_hh, Wp1, Wv1, W1, W2, W3, W_ih);
    conv1_bf16_kernel<<<3200, 256>>>(image, b1);
    conv_nhwc_kernel<81, 512, 12800, 32, 20, 2, 4, 9, true><<<648, 256>>>(b2);
    conv_nhwc_kernel<49, 576, 5184, 64, 9, 1, 3, 7, false><<<392, 256>>>(b3);
    gemm_fc_kernel<<<dim3(512 / 64, 1024 / 64), 128>>>(Wfc, bfc);
    onehot_kernel<<<4, 256>>>(la);
    gemm_pre_kernel<<<dim3(1024 / 64, 1024 / 64), 128>>>();
    lstm_kernel<<<32, 256, SMEML>>>(done, h0, c0, o_hT, o_cT);
    heads_kernel<<<128, 128>>>(bp1, Wp2, bp2, bv1, Wv2, bv2, o_logits, o_v);
}

// round 17
// speedup vs baseline: 2.6077x; 1.0935x over previous
#include <cuda_runtime.h>
#include <cuda_bf16.h>
#include <math.h>
#include <stdint.h>

// ----------------------------------------------------------------------------
// Problem constants
//   T=32, B=32, TB=1024, NA=5, HID=256, FEAT=512, IN_DIM=517 (pad 544), FLAT=3136
// Output layout (22528 floats): logits[1024*5] | v[1024] | hT[32*256] | cT[32*256]
// Intermediate layouts: g_x1, g_x2 are NHWC ([img][px][ic]); g_x3 CHW (flatten).
// ----------------------------------------------------------------------------

#define TBn 1024
#define KPAD 544    // padded IN_DIM for tf32 GEMM (multiple of 32)
#define SW 20       // conv smem row stride (unsigned) - 80B, 16B-aligned rows

// Scratch (device globals; no allocation allowed)
__device__ float g_x1[TBn * 400 * 32];       // conv1 out (NHWC)
__device__ float g_x2[TBn * 81 * 64];        // conv2 out (NHWC)
__device__ float g_x3[TBn * 3136];           // conv3 out (CHW flatten)
__device__ float g_xs[TBn * KPAD];           // feat || one-hot || zero pad
__device__ float g_pre[TBn * 1024];          // x @ W_ih^T + b_ih + b_hh
__device__ float g_whhT[256 * 1024];         // W_hh transposed: [k][4*HID]
__device__ float g_wihp[1024 * KPAD];        // W_ih zero-padded to KPAD
__device__ float g_bsum[1024];               // b_ih + b_hh
__device__ float g_wp1T[256 * 64];           // Wp1 transposed [k][64]
__device__ float g_wv1T[256 * 64];           // Wv1 transposed [k][64]
__device__ float g_hs[TBn * 256];            // all h outputs
// bf16 hi/lo split conv weights, [oc][k/2] packed bf16x2.
// conv1: k-order (ic,ky,kx). conv2/conv3: k-order (pos,ic).
__device__ unsigned g_w1h[32 * 96],  g_w1l[32 * 96];    // conv1 (scaled 1/255)
__device__ unsigned g_w2h[64 * 256], g_w2l[64 * 256];   // conv2
__device__ unsigned g_w3h[64 * 288], g_w3l[64 * 288];   // conv3
// conv1 im2col LUTs (CHW raw input)
__device__ int g_lutk1[192], g_lutn1[400];

__device__ __forceinline__ float sigmoidf(float x) { return 1.0f / (1.0f + expf(-x)); }

__device__ __forceinline__ unsigned f2tf(float f) {
    unsigned u;
    asm("cvt.rna.tf32.f32 %0, %1;" : "=r"(u) : "f"(f));
    return u;
}

// pack two floats into bf16x2 hi + residual-lo (v0 in low half)
__device__ __forceinline__ void packhl(float v0, float v1, unsigned& h, unsigned& l) {
    __nv_bfloat162 h2 = __floats2bfloat162_rn(v0, v1);
    float l0 = v0 - __low2float(h2);
    float l1 = v1 - __high2float(h2);
    __nv_bfloat162 l2 = __floats2bfloat162_rn(l0, l1);
    h = *reinterpret_cast<unsigned*>(&h2);
    l = *reinterpret_cast<unsigned*>(&l2);
}

__device__ __forceinline__ void ldsm4(unsigned* r, uint32_t addr) {
    asm volatile("ldmatrix.sync.aligned.m8n8.x4.shared.b16 {%0,%1,%2,%3}, [%4];"
        : "=r"(r[0]), "=r"(r[1]), "=r"(r[2]), "=r"(r[3]) : "r"(addr));
}

// ---- cluster / DSMEM helpers ----
__device__ __forceinline__ uint32_t smem_u32(const void* p) {
    uint32_t a;
    asm("{ .reg .u64 t; cvta.to.shared.u64 t, %1; cvt.u32.u64 %0, t; }"
        : "=r"(a) : "l"(p));
    return a;
}
__device__ __forceinline__ uint32_t mapa_rank(uint32_t saddr, uint32_t rank) {
    uint32_t r;
    asm("mapa.shared::cluster.u32 %0, %1, %2;" : "=r"(r) : "r"(saddr), "r"(rank));
    return r;
}
__device__ __forceinline__ void st_cluster_f32(uint32_t addr, float v) {
    asm volatile("st.shared::cluster.f32 [%0], %1;" :: "r"(addr), "f"(v) : "memory");
}
#define CLUSTER_SYNC() do { \
    asm volatile("barrier.cluster.arrive.aligned;" ::: "memory"); \
    asm volatile("barrier.cluster.wait.aligned;" ::: "memory"); \
} while (0)

// ----------------------------------------------------------------------------
// prep
// ----------------------------------------------------------------------------
__global__ void prep_kernel(const float* __restrict__ W_hh,
                            const float* __restrict__ b_ih,
                            const float* __restrict__ b_hh,
                            const float* __restrict__ Wp1,
                            const float* __restrict__ Wv1,
                            const float* __restrict__ W1,
                            const float* __restrict__ W2,
                            const float* __restrict__ W3,
                            const float* __restrict__ W_ih) {
    int idx = blockIdx.x * blockDim.x + threadIdx.x;
    if (idx < 262144) {
        int j = idx >> 8, k = idx & 255;
        g_whhT[k * 1024 + j] = W_hh[idx];
    }
    if (idx < 16384) {
        int j = idx >> 8, k = idx & 255;
        g_wp1T[k * 64 + j] = Wp1[idx];
        g_wv1T[k * 64 + j] = Wv1[idx];
    }
    if (idx < 1024) g_bsum[idx] = b_ih[idx] + b_hh[idx];
    if (idx < 1024 * KPAD) {
        int row = idx / KPAD, col = idx % KPAD;
        g_wihp[idx] = (col < 517) ? W_ih[row * 517 + col] : 0.0f;
    }
    if (idx < 32 * 96) {
        int oc = idx / 96, pk = idx % 96;
        float v0 = W1[oc * 192 + 2 * pk] * (1.0f / 255.0f);
        float v1 = W1[oc * 192 + 2 * pk + 1] * (1.0f / 255.0f);
        packhl(v0, v1, g_w1h[idx], g_w1l[idx]);
    }
    if (idx < 64 * 256) {
        int oc = idx >> 8, pk = idx & 255;
        int knew0 = 2 * pk;
        int pos = knew0 >> 5, ic0 = knew0 & 31;
        packhl(W2[oc * 512 + ic0 * 16 + pos], W2[oc * 512 + (ic0 + 1) * 16 + pos],
               g_w2h[idx], g_w2l[idx]);
    }
    if (idx < 64 * 288) {
        int oc = idx / 288, pk = idx % 288;
        int knew0 = 2 * pk;
        int pos = knew0 >> 6, ic0 = knew0 & 63;
        packhl(W3[oc * 576 + ic0 * 9 + pos], W3[oc * 576 + (ic0 + 1) * 9 + pos],
               g_w3h[idx], g_w3l[idx]);
    }
    if (idx < 192) {
        int ic = idx >> 6, ky = (idx >> 3) & 7, kx = idx & 7;
        g_lutk1[idx] = ic * 7056 + ky * 84 + kx;
    }
    if (idx < 400) g_lutn1[idx] = (idx / 20) * 336 + (idx % 20) * 4;
}

// ----------------------------------------------------------------------------
// one-hot columns of xs (cols 512..516) + zero pad (517..543)
// ----------------------------------------------------------------------------
__global__ void onehot_kernel(const int* __restrict__ la) {
    int r = blockIdx.x * blockDim.x + threadIdx.x;
    if (r < TBn) {
        int a = la[r];
        float* p = g_xs + r * KPAD + 512;
#pragma unroll
        for (int j = 0; j < 5; j++) p[j] = (j == a) ? 1.0f : 0.0f;
#pragma unroll
        for (int j = 5; j < 32; j++) p[j] = 0.0f;
    }
}

// ----------------------------------------------------------------------------
// bf16 m16n8k16 mma
// ----------------------------------------------------------------------------
__device__ __forceinline__ void mma_bf16(float* c, const unsigned* a, const unsigned* b) {
    asm volatile(
        "mma.sync.aligned.m16n8k16.row.col.f32.bf16.bf16.f32 "
        "{%0,%1,%2,%3}, {%4,%5,%6,%7}, {%8,%9}, {%0,%1,%2,%3};\n"
        : "+f"(c[0]), "+f"(c[1]), "+f"(c[2]), "+f"(c[3])
        : "r"(a[0]), "r"(a[1]), "r"(a[2]), "r"(a[3]), "r"(b[0]), "r"(b[1]));
}

// ----------------------------------------------------------------------------
// conv1: CHW raw-image gather, NHWC output. BM=128, 256 thr, OC=32 (MT=1).
// Fragments via ldmatrix.
// ----------------------------------------------------------------------------
__global__ void __launch_bounds__(256)
conv1_bf16_kernel(const float* __restrict__ in, const float* __restrict__ bias) {
    constexpr int NPX = 400, K = 192, IMG = 21168, OC = 32;
    constexpr int NCH = K / 32, KP = K / 2, BITS = 2;

    __shared__ unsigned Ah[2][128][SW], Al[2][128][SW];
    __shared__ unsigned Bh[2][OC][SW], Bl[2][OC][SW];

    int tid = threadIdx.x, lane = tid & 31, warp = tid >> 5;
    int wm = warp * 16;
    int bm = blockIdx.x * 128;
    int trow = tid >> 4, tpk = tid & 15;

    int base[8];
#pragma unroll
    for (int it = 0; it < 8; it++) {
        int grow = bm + trow + 16 * it;
        int img = grow / NPX;
        int px = grow - img * NPX;
        base[it] = img * IMG + __ldg(&g_lutn1[px]);
    }

    // ldmatrix lane addressing
    int lm = lane >> 3, lj = lane & 7;
    uint32_t aoff = (uint32_t)((((lm & 1) * 8 + lj) * SW + (lm >> 1) * 4) * 4);
    int bnt = lane >> 4, bkh = (lane >> 3) & 1;
    uint32_t boff = (uint32_t)(((bnt * 8 + lj) * SW + bkh * 4) * 4);
    uint32_t Ah0 = smem_u32(&Ah[0][0][0]), Al0 = smem_u32(&Al[0][0][0]);
    uint32_t Bh0 = smem_u32(&Bh[0][0][0]), Bl0 = smem_u32(&Bl[0][0][0]);
    const uint32_t ABUF = 128 * SW * 4, BBUF = OC * SW * 4;
    uint32_t aAh = Ah0 + aoff + (uint32_t)(wm * SW * 4);
    uint32_t aAl = Al0 + aoff + (uint32_t)(wm * SW * 4);

    float c[1][4][4];
#pragma unroll
    for (int nt = 0; nt < 4; nt++)
#pragma unroll
        for (int i = 0; i < 4; i++) c[0][nt][i] = 0.0f;

    {
        int koff0 = __ldg(&g_lutk1[2 * tpk]);
        int koff1 = __ldg(&g_lutk1[2 * tpk + 1]);
#pragma unroll
        for (int it = 0; it < 8; it++) {
            float v0 = __ldg(&in[base[it] + koff0]);
            float v1 = __ldg(&in[base[it] + koff1]);
            unsigned h, l;
            packhl(v0, v1, h, l);
            Ah[0][trow + 16 * it][tpk] = h;
            Al[0][trow + 16 * it][tpk] = l;
        }
#pragma unroll
        for (int it = 0; it < BITS; it++) {
            int bidx = it * 256 + tid;
            int rrow = bidx >> 4, pk = bidx & 15;
            Bh[0][rrow][pk] = __ldg(&g_w1h[rrow * KP + pk]);
            Bl[0][rrow][pk] = __ldg(&g_w1l[rrow * KP + pk]);
        }
    }
    __syncthreads();

    for (int ch = 0; ch < NCH; ch++) {
        int buf = ch & 1;
        float va0[8], va1[8];
        unsigned vbh[BITS], vbl[BITS];
        if (ch + 1 < NCH) {
            int k0 = (ch + 1) * 32, kp0 = (ch + 1) * 16;
            int koff0 = __ldg(&g_lutk1[k0 + 2 * tpk]);
            int koff1 = __ldg(&g_lutk1[k0 + 2 * tpk + 1]);
#pragma unroll
            for (int it = 0; it < 8; it++) {
                va0[it] = __ldg(&in[base[it] + koff0]);
                va1[it] = __ldg(&in[base[it] + koff1]);
            }
#pragma unroll
            for (int it = 0; it < BITS; it++) {
                int bidx = it * 256 + tid;
                int rrow = bidx >> 4, pk = bidx & 15;
                vbh[it] = __ldg(&g_w1h[rrow * KP + kp0 + pk]);
                vbl[it] = __ldg(&g_w1l[rrow * KP + kp0 + pk]);
            }
        }

        uint32_t abuf = buf ? ABUF : 0, bbuf = buf ? BBUF : 0;
#pragma unroll
        for (int ks = 0; ks < 2; ks++) {
            unsigned ah[4], al[4], bh[2][4], bl[2][4];
            ldsm4(ah, aAh + abuf + ks * 32);
            ldsm4(al, aAl + abuf + ks * 32);
            ldsm4(bh[0], Bh0 + bbuf + boff + ks * 32);
            ldsm4(bh[1], Bh0 + bbuf + boff + (uint32_t)(16 * SW * 4) + ks * 32);
            ldsm4(bl[0], Bl0 + bbuf + boff + ks * 32);
            ldsm4(bl[1], Bl0 + bbuf + boff + (uint32_t)(16 * SW * 4) + ks * 32);
#pragma unroll
            for (int nt = 0; nt < 4; nt++) {
                const unsigned* bh2 = &bh[nt >> 1][(nt & 1) * 2];
                const unsigned* bl2 = &bl[nt >> 1][(nt & 1) * 2];
                mma_bf16(c[0][nt], ah, bh2);
                mma_bf16(c[0][nt], ah, bl2);
                mma_bf16(c[0][nt], al, bh2);
            }
        }

        if (ch + 1 < NCH) {
            int nbuf = buf ^ 1;
#pragma unroll
            for (int it = 0; it < 8; it++) {
                unsigned h, l;
                packhl(va0[it], va1[it], h, l);
                Ah[nbuf][trow + 16 * it][tpk] = h;
                Al[nbuf][trow + 16 * it][tpk] = l;
            }
#pragma unroll
            for (int it = 0; it < BITS; it++) {
                int bidx = it * 256 + tid;
                int rrow = bidx >> 4, pk = bidx & 15;
                Bh[nbuf][rrow][pk] = vbh[it];
                Bl[nbuf][rrow][pk] = vbl[it];
            }
        }
        __syncthreads();
    }

    // NHWC epilogue
#pragma unroll
    for (int nt = 0; nt < 4; nt++) {
        int row = bm + wm + (lane >> 2);
        int col = nt * 8 + ((lane & 3) << 1);
        float b0 = __ldg(&bias[col]);
        float b1 = __ldg(&bias[col + 1]);
        int img0 = row / NPX, px0 = row - img0 * NPX;
        int row2 = row + 8;
        int img2 = row2 / NPX, px2 = row2 - img2 * NPX;
        float2 v01 = {fmaxf(c[0][nt][0] + b0, 0.0f), fmaxf(c[0][nt][1] + b1, 0.0f)};
        float2 v23 = {fmaxf(c[0][nt][2] + b0, 0.0f), fmaxf(c[0][nt][3] + b1, 0.0f)};
        *reinterpret_cast<float2*>(&g_x1[img0 * (NPX * 32) + px0 * 32 + col]) = v01;
        *reinterpret_cast<float2*>(&g_x1[img2 * (NPX * 32) + px2 * 32 + col]) = v23;
    }
}

// ----------------------------------------------------------------------------
// conv2/conv3: NHWC input, k-order (pos, ic), dense float2 gather.
// BM=128, 256 thr, OC=64 (MT=2). Fragments via ldmatrix.
// ----------------------------------------------------------------------------
template<int NPX, int K, int IMG, int ICIN, int WID, int STR, int PW, int OW, bool OUT_NHWC>
__global__ void __launch_bounds__(256)
conv_nhwc_kernel(const float* __restrict__ bias) {
    constexpr int OC = 64;
    constexpr int NCH = K / 32, KP = K / 2;
    constexpr int CPP = ICIN / 32;
    constexpr int BITS = 4;

    const float* in = (K == 512) ? g_x1 : g_x2;
    float* out = (K == 512) ? g_x2 : g_x3;
    const unsigned* wh = (K == 512) ? g_w2h : g_w3h;
    const unsigned* wl = (K == 512) ? g_w2l : g_w3l;

    __shared__ unsigned Ah[2][128][SW], Al[2][128][SW];
    __shared__ unsigned Bh[2][OC][SW], Bl[2][OC][SW];

    int tid = threadIdx.x, lane = tid & 31, warp = tid >> 5;
    int wm = (warp & 3) * 32, wn = (warp >> 2) * 32;
    int bm = blockIdx.x * 128;
    int trow = tid >> 4, tpk = tid & 15;

    int base[8];
#pragma unroll
    for (int it = 0; it < 8; it++) {
        int grow = bm + trow + 16 * it;
        int img = grow / NPX;
        int px = grow - img * NPX;
        int oy = px / OW, ox = px - oy * OW;
        base[it] = img * IMG + (oy * STR * WID + ox * STR) * ICIN + 2 * tpk;
    }

    int lm = lane >> 3, lj = lane & 7;
    uint32_t aoff = (uint32_t)((((lm & 1) * 8 + lj) * SW + (lm >> 1) * 4) * 4);
    int bnt = lane >> 4, bkh = (lane >> 3) & 1;
    uint32_t boff = (uint32_t)(((bnt * 8 + lj) * SW + bkh * 4) * 4);
    uint32_t Ah0 = smem_u32(&Ah[0][0][0]), Al0 = smem_u32(&Al[0][0][0]);
    uint32_t Bh0 = smem_u32(&Bh[0][0][0]), Bl0 = smem_u32(&Bl[0][0][0]);
    const uint32_t ABUF = 128 * SW * 4, BBUF = OC * SW * 4;
    uint32_t aAh = Ah0 + aoff + (uint32_t)(wm * SW * 4);
    uint32_t aAl = Al0 + aoff + (uint32_t)(wm * SW * 4);
    uint32_t bBh = Bh0 + boff + (uint32_t)(wn * SW * 4);
    uint32_t bBl = Bl0 + boff + (uint32_t)(wn * SW * 4);

    float c[2][4][4];
#pragma unroll
    for (int mt = 0; mt < 2; mt++)
#pragma unroll
        for (int nt = 0; nt < 4; nt++)
#pragma unroll
            for (int i = 0; i < 4; i++) c[mt][nt][i] = 0.0f;

    auto chunk_off = [](int ch) {
        int pos = ch / CPP;
        int ico = (ch - pos * CPP) * 32;
        int ky = pos / PW, kx = pos - ky * PW;
        return (ky * WID + kx) * ICIN + ico;
    };

    {
#pragma unroll
        for (int it = 0; it < 8; it++) {
            float2 v = *reinterpret_cast<const float2*>(&in[base[it]]);
            unsigned h, l;
            packhl(v.x, v.y, h, l);
            Ah[0][trow + 16 * it][tpk] = h;
            Al[0][trow + 16 * it][tpk] = l;
        }
#pragma unroll
        for (int it = 0; it < BITS; it++) {
            int bidx = it * 256 + tid;
            int rrow = bidx >> 4, pk = bidx & 15;
            Bh[0][rrow][pk] = __ldg(&wh[rrow * KP + pk]);
            Bl[0][rrow][pk] = __ldg(&wl[rrow * KP + pk]);
        }
    }
    __syncthreads();

    for (int ch = 0; ch < NCH; ch++) {
        int buf = ch & 1;
        float va0[8], va1[8];
        unsigned vbh[BITS], vbl[BITS];
        if (ch + 1 < NCH) {
            int off = chunk_off(ch + 1);
            int kp0 = (ch + 1) * 16;
#pragma unroll
            for (int it = 0; it < 8; it++) {
                float2 v = *reinterpret_cast<const float2*>(&in[base[it] + off]);
                va0[it] = v.x;
                va1[it] = v.y;
            }
#pragma unroll
            for (int it = 0; it < BITS; it++) {
                int bidx = it * 256 + tid;
                int rrow = bidx >> 4, pk = bidx & 15;
                vbh[it] = __ldg(&wh[rrow * KP + kp0 + pk]);
                vbl[it] = __ldg(&wl[rrow * KP + kp0 + pk]);
            }
        }

        uint32_t abuf = buf ? ABUF : 0, bbuf = buf ? BBUF : 0;
#pragma unroll
        for (int ks = 0; ks < 2; ks++) {
            unsigned ah[2][4], al[2][4], bh[2][4], bl[2][4];
            ldsm4(ah[0], aAh + abuf + ks * 32);
            ldsm4(ah[1], aAh + abuf + (uint32_t)(16 * SW * 4) + ks * 32);
            ldsm4(al[0], aAl + abuf + ks * 32);
            ldsm4(al[1], aAl + abuf + (uint32_t)(16 * SW * 4) + ks * 32);
            ldsm4(bh[0], bBh + bbuf + ks * 32);
            ldsm4(bh[1], bBh + bbuf + (uint32_t)(16 * SW * 4) + ks * 32);
            ldsm4(bl[0], bBl + bbuf + ks * 32);
            ldsm4(bl[1], bBl + bbuf + (uint32_t)(16 * SW * 4) + ks * 32);
#pragma unroll
            for (int nt = 0; nt < 4; nt++) {
                const unsigned* bh2 = &bh[nt >> 1][(nt & 1) * 2];
                const unsigned* bl2 = &bl[nt >> 1][(nt & 1) * 2];
#pragma unroll
                for (int mt = 0; mt < 2; mt++) {
                    mma_bf16(c[mt][nt], ah[mt], bh2);
                    mma_bf16(c[mt][nt], ah[mt], bl2);
                    mma_bf16(c[mt][nt], al[mt], bh2);
                }
            }
        }

        if (ch + 1 < NCH) {
            int nbuf = buf ^ 1;
#pragma unroll
            for (int it = 0; it < 8; it++) {
                unsigned h, l;
                packhl(va0[it], va1[it], h, l);
                Ah[nbuf][trow + 16 * it][tpk] = h;
                Al[nbuf][trow + 16 * it][tpk] = l;
            }
#pragma unroll
            for (int it = 0; it < BITS; it++) {
                int bidx = it * 256 + tid;
                int rrow = bidx >> 4, pk = bidx & 15;
                Bh[nbuf][rrow][pk] = vbh[it];
                Bl[nbuf][rrow][pk] = vbl[it];
            }
        }
        __syncthreads();
    }

    // epilogue
#pragma unroll
    for (int mt = 0; mt < 2; mt++) {
#pragma unroll
        for (int nt = 0; nt < 4; nt++) {
            int row = bm + wm + mt * 16 + (lane >> 2);
            int col = wn + nt * 8 + ((lane & 3) << 1);
            float b0 = __ldg(&bias[col]);
            float b1 = __ldg(&bias[col + 1]);
            int img0 = row / NPX, px0 = row - img0 * NPX;
            int row2 = row + 8;
            int img2 = row2 / NPX, px2 = row2 - img2 * NPX;
            if (OUT_NHWC) {
                float2 v01 = {fmaxf(c[mt][nt][0] + b0, 0.0f), fmaxf(c[mt][nt][1] + b1, 0.0f)};
                float2 v23 = {fmaxf(c[mt][nt][2] + b0, 0.0f), fmaxf(c[mt][nt][3] + b1, 0.0f)};
                *reinterpret_cast<float2*>(&out[img0 * (NPX * OC) + px0 * OC + col]) = v01;
                *reinterpret_cast<float2*>(&out[img2 * (NPX * OC) + px2 * OC + col]) = v23;
            } else {
                out[img0 * (OC * NPX) + col * NPX + px0] = fmaxf(c[mt][nt][0] + b0, 0.0f);
                out[img0 * (OC * NPX) + (col + 1) * NPX + px0] = fmaxf(c[mt][nt][1] + b1, 0.0f);
                out[img2 * (OC * NPX) + col * NPX + px2] = fmaxf(c[mt][nt][2] + b0, 0.0f);
                out[img2 * (OC * NPX) + (col + 1) * NPX + px2] = fmaxf(c[mt][nt][3] + b1, 0.0f);
            }
        }
    }
}

// ----------------------------------------------------------------------------
// tf32 tensor-core GEMM: C[M x N] = act(A[M x K] * B[N x K]^T + bias)
// ----------------------------------------------------------------------------
__device__ __forceinline__ void mma_tf32(float* c, const unsigned* a, const unsigned* b) {
    asm volatile(
        "mma.sync.aligned.m16n8k8.row.col.f32.tf32.tf32.f32 "
        "{%0,%1,%2,%3}, {%4,%5,%6,%7}, {%8,%9}, {%0,%1,%2,%3};\n"
        : "+f"(c[0]), "+f"(c[1]), "+f"(c[2]), "+f"(c[3])
        : "r"(a[0]), "r"(a[1]), "r"(a[2]), "r"(a[3]), "r"(b[0]), "r"(b[1]));
}

__device__ __forceinline__ void gemm_tf32(const float* __restrict__ A, int lda,
                                          const float* __restrict__ B, int ldb,
                                          const float* __restrict__ bias,
                                          float* __restrict__ C, int ldc,
                                          int K, bool relu) {
    __shared__ unsigned As[2][64][36];
    __shared__ unsigned Bs[2][64][36];
    int tid = threadIdx.x, lane = tid & 31, warp = tid >> 5;
    int bm = blockIdx.y * 64, bn = blockIdx.x * 64;
    int wm = (warp & 1) << 5, wn = (warp >> 1) << 5;

    float c[2][4][4];
#pragma unroll
    for (int mt = 0; mt < 2; mt++)
#pragma unroll
        for (int nt = 0; nt < 4; nt++)
#pragma unroll
            for (int i = 0; i < 4; i++) c[mt][nt][i] = 0.0f;

    int ntiles = K >> 5;
    float4 pa[4], pb[4];

#pragma unroll
    for (int i = 0; i < 4; i++) {
        int idx = tid + (i << 7);
        int row = idx >> 3, c4 = (idx & 7) << 2;
        pa[i] = *reinterpret_cast<const float4*>(A + (bm + row) * lda + c4);
        pb[i] = *reinterpret_cast<const float4*>(B + (bn + row) * ldb + c4);
    }
#pragma unroll
    for (int i = 0; i < 4; i++) {
        int idx = tid + (i << 7);
        int row = idx >> 3, c4 = (idx & 7) << 2;
        uint4 ta = {f2tf(pa[i].x), f2tf(pa[i].y), f2tf(pa[i].z), f2tf(pa[i].w)};
        uint4 tb = {f2tf(pb[i].x), f2tf(pb[i].y), f2tf(pb[i].z), f2tf(pb[i].w)};
        *reinterpret_cast<uint4*>(&As[0][row][c4]) = ta;
        *reinterpret_cast<uint4*>(&Bs[0][row][c4]) = tb;
    }
    __syncthreads();

    for (int t = 0; t < ntiles; t++) {
        int buf = t & 1;
        if (t + 1 < ntiles) {
            int k0 = (t + 1) << 5;
#pragma unroll
            for (int i = 0; i < 4; i++) {
                int idx = tid + (i << 7);
                int row = idx >> 3, c4 = (idx & 7) << 2;
                pa[i] = *reinterpret_cast<const float4*>(A + (bm + row) * lda + k0 + c4);
                pb[i] = *reinterpret_cast<const float4*>(B + (bn + row) * ldb + k0 + c4);
            }
        }
        int r = lane >> 2, q = lane & 3;
#pragma unroll
        for (int ks = 0; ks < 4; ks++) {
            unsigned a[2][4], b[4][2];
            int kc = ks << 3;
#pragma unroll
            for (int mt = 0; mt < 2; mt++) {
                int mr = wm + (mt << 4) + r;
                a[mt][0] = As[buf][mr][kc + q];
                a[mt][1] = As[buf][mr + 8][kc + q];
                a[mt][2] = As[buf][mr][kc + q + 4];
                a[mt][3] = As[buf][mr + 8][kc + q + 4];
            }
#pragma unroll
            for (int nt = 0; nt < 4; nt++) {
                int nr = wn + (nt << 3) + r;
                b[nt][0] = Bs[buf][nr][kc + q];
                b[nt][1] = Bs[buf][nr][kc + q + 4];
            }
#pragma unroll
            for (int mt = 0; mt < 2; mt++)
#pragma unroll
                for (int nt = 0; nt < 4; nt++)
                    mma_tf32(c[mt][nt], a[mt], b[nt]);
        }
        if (t + 1 < ntiles) {
            int nbuf = buf ^ 1;
#pragma unroll
            for (int i = 0; i < 4; i++) {
                int idx = tid + (i << 7);
                int row = idx >> 3, c4 = (idx & 7) << 2;
                uint4 ta = {f2tf(pa[i].x), f2tf(pa[i].y), f2tf(pa[i].z), f2tf(pa[i].w)};
                uint4 tb = {f2tf(pb[i].x), f2tf(pb[i].y), f2tf(pb[i].z), f2tf(pb[i].w)};
                *reinterpret_cast<uint4*>(&As[nbuf][row][c4]) = ta;
                *reinterpret_cast<uint4*>(&Bs[nbuf][row][c4]) = tb;
            }
            __syncthreads();
        }
    }

#pragma unroll
    for (int mt = 0; mt < 2; mt++) {
#pragma unroll
        for (int nt = 0; nt < 4; nt++) {
            int row = bm + wm + (mt << 4) + (lane >> 2);
            int col = bn + wn + (nt << 3) + ((lane & 3) << 1);
            float b0 = bias[col], b1 = bias[col + 1];
            float v0 = c[mt][nt][0] + b0;
            float v1 = c[mt][nt][1] + b1;
            float v2 = c[mt][nt][2] + b0;
            float v3 = c[mt][nt][3] + b1;
            if (relu) {
                v0 = fmaxf(v0, 0.0f); v1 = fmaxf(v1, 0.0f);
                v2 = fmaxf(v2, 0.0f); v3 = fmaxf(v3, 0.0f);
            }
            C[row * ldc + col] = v0;
            C[row * ldc + col + 1] = v1;
            C[(row + 8) * ldc + col] = v2;
            C[(row + 8) * ldc + col + 1] = v3;
        }
    }
}

__global__ void __launch_bounds__(128)
gemm_fc_kernel(const float* __restrict__ Wfc, const float* __restrict__ bfc) {
    gemm_tf32(g_x3, 3136, Wfc, 3136, bfc, g_xs, KPAD, 3136, true);
}

__global__ void __launch_bounds__(128)
gemm_pre_kernel() {
    gemm_tf32(g_xs, KPAD, g_wihp, KPAD, g_bsum, g_pre, 1024, KPAD, false);
}

// ----------------------------------------------------------------------------
// LSTM: 4 clusters x 8 CTAs, W_hh slice SMEM-resident, DSMEM gate exchange.
// ----------------------------------------------------------------------------
__global__ void __launch_bounds__(256, 1) __cluster_dims__(8, 1, 1)
lstm_kernel(const float* __restrict__ done,
            const float* __restrict__ h0,
            const float* __restrict__ c0,
            float* __restrict__ hT,
            float* __restrict__ cT) {
    extern __shared__ float sm[];
    float* wsl = sm;                    // 256*128 floats
    float* h_s = sm + 32768;            // 8*260 floats
    float* gbuf = h_s + 2080;           // 4*8*32 floats
    float* m_s = gbuf + 1024;           // 8 floats

    int tid = threadIdx.x;
    unsigned rank;
    asm("mov.u32 %0, %%cluster_ctarank;" : "=r"(rank));
    int cl = blockIdx.x >> 3;
    int bbase = cl * 8;

    {
        const float* src = g_whhT + 128 * (int)rank;
        for (int i = tid; i < 8192; i += 256) {
            int k = i >> 5, j4 = (i & 31) << 2;
            *reinterpret_cast<float4*>(&wsl[k * 128 + j4]) =
                *reinterpret_cast<const float4*>(&src[k * 1024 + j4]);
        }
    }
    for (int i = tid; i < 2048; i += 256) {
        int b = i >> 8, k = i & 255;
        h_s[b * 260 + k] = h0[(bbase + b) * 256 + k];
    }
    int ob = tid >> 5, os = tid & 31;
    int ou = 32 * (int)rank + os;
    float c_reg = c0[(bbase + ob) * 256 + ou];
    float hn = 0.0f;

    int jg2 = tid >> 2, bp = tid & 3;
    int jbase = 2 * jg2;
    int b0 = 2 * bp, b1 = b0 + 1;
    int gt = (int)rank >> 1;
    int ubase = ((128 * (int)rank) & 255) + jbase;
    uint32_t owner = (uint32_t)(ubase >> 5);
    uint32_t gbuf_a = smem_u32(gbuf);
    uint32_t h_a = smem_u32(h_s);
    uint32_t peer_gbuf = mapa_rank(gbuf_a, owner);
    uint32_t g0 = (uint32_t)(((gt * 8 + b0) * 32 + (ubase & 31)) * 4);
    uint32_t g1 = (uint32_t)(((gt * 8 + b1) * 32 + (ubase & 31)) * 4);
    uint32_t hpeer[8];
#pragma unroll
    for (int p = 0; p < 8; p++) hpeer[p] = mapa_rank(h_a, (uint32_t)p);
    uint32_t hoff = (uint32_t)((ob * 260 + ou) * 4);

    __syncthreads();
    CLUSTER_SYNC();

    for (int t = 0; t < 32; t++) {
        if (tid < 8) m_s[tid] = 1.0f - __ldg(&done[t * 32 + bbase + tid]);
        __syncthreads();
        for (int i = tid; i < 2048; i += 256) {
            int bb = i >> 8, k = i & 255;
            h_s[bb * 260 + k] *= m_s[bb];
        }
        c_reg *= m_s[ob];
        __syncthreads();

        int row0 = (t << 5) + bbase + b0;
        int row1 = row0 + 1;
        float2 a0 = *reinterpret_cast<const float2*>(
            g_pre + row0 * 1024 + 128 * (int)rank + jbase);
        float2 a1 = *reinterpret_cast<const float2*>(
            g_pre + row1 * 1024 + 128 * (int)rank + jbase);
        float acc00 = a0.x, acc01 = a0.y;
        float acc10 = a1.x, acc11 = a1.y;
        const float* hb0 = h_s + b0 * 260;
        const float* hb1 = h_s + b1 * 260;
#pragma unroll 8
        for (int k = 0; k < 256; k++) {
            float2 w = *reinterpret_cast<const float2*>(&wsl[k * 128 + jbase]);
            float h0k = hb0[k];
            float h1k = hb1[k];
            acc00 = fmaf(h0k, w.x, acc00);
            acc01 = fmaf(h0k, w.y, acc01);
            acc10 = fmaf(h1k, w.x, acc10);
            acc11 = fmaf(h1k, w.y, acc11);
        }
        st_cluster_f32(peer_gbuf + g0, acc00);
        st_cluster_f32(peer_gbuf + g0 + 4, acc01);
        st_cluster_f32(peer_gbuf + g1, acc10);
        st_cluster_f32(peer_gbuf + g1 + 4, acc11);
        CLUSTER_SYNC();

        {
            float gi = sigmoidf(gbuf[(0 * 8 + ob) * 32 + os]);
            float gf = sigmoidf(gbuf[(1 * 8 + ob) * 32 + os]);
            float gg = tanhf(gbuf[(2 * 8 + ob) * 32 + os]);
            float go = sigmoidf(gbuf[(3 * 8 + ob) * 32 + os]);
            c_reg = gf * c_reg + gi * gg;
            hn = go * tanhf(c_reg);
            g_hs[((t << 5) + bbase + ob) * 256 + ou] = hn;
#pragma unroll
            for (int p = 0; p < 8; p++) st_cluster_f32(hpeer[p] + hoff, hn);
        }
        CLUSTER_SYNC();
    }
    hT[(bbase + ob) * 256 + ou] = hn;
    cT[(bbase + ob) * 256 + ou] = c_reg;
}

// ----------------------------------------------------------------------------
// Heads: 8 rows per block.
// ----------------------------------------------------------------------------
__global__ void __launch_bounds__(128)
heads_kernel(const float* __restrict__ bp1,
             const float* __restrict__ Wp2,
             const float* __restrict__ bp2,
             const float* __restrict__ bv1,
             const float* __restrict__ Wv2,
             const float* __restrict__ bv2,
             float* __restrict__ logits,
             float* __restrict__ vout) {
    __shared__ float h_s[8][256];
    __shared__ float hp[8][64];
    __shared__ float hv[8][64];
    int r0 = blockIdx.x * 8, t = threadIdx.x;
    {
        const float4* g4 = reinterpret_cast<const float4*>(g_hs + r0 * 256);
        float4* s4 = reinterpret_cast<float4*>(&h_s[0][0]);
        for (int i = t; i < 512; i += 128) s4[i] = g4[i];
    }
    __syncthreads();

    if (t < 64) {
        float s[8];
#pragma unroll
        for (int r = 0; r < 8; r++) s[r] = bp1[t];
#pragma unroll 4
        for (int k = 0; k < 256; k++) {
            float w = __ldg(&g_wp1T[k * 64 + t]);
#pragma unroll
            for (int r = 0; r < 8; r++) s[r] = fmaf(h_s[r][k], w, s[r]);
        }
#pragma unroll
        for (int r = 0; r < 8; r++) hp[r][t] = tanhf(s[r]);
    } else {
        int j = t - 64;
        float s[8];
#pragma unroll
        for (int r = 0; r < 8; r++) s[r] = bv1[j];
#pragma unroll 4
        for (int k = 0; k < 256; k++) {
            float w = __ldg(&g_wv1T[k * 64 + j]);
#pragma unroll
            for (int r = 0; r < 8; r++) s[r] = fmaf(h_s[r][k], w, s[r]);
        }
#pragma unroll
        for (int r = 0; r < 8; r++) hv[r][j] = tanhf(s[r]);
    }
    __syncthreads();

    if (t < 40) {
        int r = t / 5, a = t % 5;
        float s = bp2[a];
#pragma unroll
        for (int k = 0; k < 64; k++) s = fmaf(hp[r][k], Wp2[a * 64 + k], s);
        logits[(r0 + r) * 5 + a] = s;
    }
    if (t >= 64 && t < 72) {
        int r = t - 64;
        float s = bv2[0];
#pragma unroll
        for (int k = 0; k < 64; k++) s = fmaf(hv[r][k], Wv2[k], s);
        vout[r0 + r] = s;
    }
}

// ----------------------------------------------------------------------------
// Launch
// ----------------------------------------------------------------------------
extern "C" void kernel_launch(void* const* d_in, const int* in_sizes, int n_in,
                              void* d_out, int out_size) {
    const float* image = (const float*)d_in[0];
    const int* la = (const int*)d_in[1];
    const float* done = (const float*)d_in[2];
    const float* h0 = (const float*)d_in[3];
    const float* c0 = (const float*)d_in[4];
    const float* W1 = (const float*)d_in[5];
    const float* b1 = (const float*)d_in[6];
    const float* W2 = (const float*)d_in[7];
    const float* b2 = (const float*)d_in[8];
    const float* W3 = (const float*)d_in[9];
    const float* b3 = (const float*)d_in[10];
    const float* Wfc = (const float*)d_in[11];
    const float* bfc = (const float*)d_in[12];
    const float* W_ih = (const float*)d_in[13];
    const float* W_hh = (const float*)d_in[14];
    const float* b_ih = (const float*)d_in[15];
    const float* b_hh = (const float*)d_in[16];
    const float* Wp1 = (const float*)d_in[17];
    const float* bp1 = (const float*)d_in[18];
    const float* Wp2 = (const float*)d_in[19];
    const float* bp2 = (const float*)d_in[20];
    const float* Wv1 = (const float*)d_in[21];
    const float* bv1 = (const float*)d_in[22];
    const float* Wv2 = (const float*)d_in[23];
    const float* bv2 = (const float*)d_in[24];

    float* out = (float*)d_out;
    float* o_logits = out;           // 5120
    float* o_v = out + 5120;         // 1024
    float* o_hT = out + 6144;        // 8192
    float* o_cT = out + 14336;       // 8192

    const int SMEML = (32768 + 2080 + 1024 + 8) * 4;  // 143520
    cudaFuncSetAttribute(lstm_kernel, cudaFuncAttributeMaxDynamicSharedMemorySize, SMEML);

    prep_kernel<<<2176, 256>>>(W_hh, b_ih, b_hh, Wp1, Wv1, W1, W2, W3, W_ih);
    conv1_bf16_kernel<<<3200, 256>>>(image, b1);
    conv_nhwc_kernel<81, 512, 12800, 32, 20, 2, 4, 9, true><<<648, 256>>>(b2);
    conv_nhwc_kernel<49, 576, 5184, 64, 9, 1, 3, 7, false><<<392, 256>>>(b3);
    gemm_fc_kernel<<<dim3(512 / 64, 1024 / 64), 128>>>(Wfc, bfc);
    onehot_kernel<<<4, 256>>>(la);
    gemm_pre_kernel<<<dim3(1024 / 64, 1024 / 64), 128>>>();
    lstm_kernel<<<32, 256, SMEML>>>(done, h0, c0, o_hT, o_cT);
    heads_kernel<<<128, 128>>>(bp1, Wp2, bp2, bv1, Wv2, bv2, o_logits, o_v);
}